// round 6
// baseline (speedup 1.0000x reference)
#include <cuda_runtime.h>
#include <cstdint>

#define Bn 2048
#define Tn 2048
#define TB (Tn * Bn)
#define NVOCAB 32000

typedef unsigned long long f2;

// Static device scratch (no runtime allocations allowed)
__device__ float4 g_xiR[2][TB];   // [dir][t*Bn+b]  (0.5-scaled r-gate xi, bias folded)
__device__ float4 g_xiZ[2][TB];   // (0.5-scaled z-gate xi, bias folded)
__device__ float4 g_xiN[2][TB];   // (UNscaled n-gate xi, bih folded)
__device__ float4 g_h[2][TB];     // raw hidden states per dir [t*Bn+b]
__device__ int    g_is64;

static __device__ __forceinline__ f2 pk2(float a, float b) {
    f2 r; asm("mov.b64 %0,{%1,%2};" : "=l"(r) : "f"(a), "f"(b)); return r;
}
static __device__ __forceinline__ void upk2(f2 v, float& a, float& b) {
    asm("mov.b64 {%0,%1},%2;" : "=f"(a), "=f"(b) : "l"(v));
}
static __device__ __forceinline__ f2 fma2(f2 a, f2 b, f2 c) {
    f2 r; asm("fma.rn.f32x2 %0,%1,%2,%3;" : "=l"(r) : "l"(a), "l"(b), "l"(c)); return r;
}
static __device__ __forceinline__ float tanhap(float x) {
    float r; asm("tanh.approx.f32 %0,%1;" : "=f"(r) : "f"(x)); return r;
}
static __device__ __forceinline__ uint32_t s2u(const void* p) {
    uint32_t a;
    asm("{ .reg .u64 t; cvta.to.shared.u64 t, %1; cvt.u32.u64 %0, t; }" : "=r"(a) : "l"(p));
    return a;
}
static __device__ __forceinline__ void cpa16(uint32_t s, const void* g) {
    asm volatile("cp.async.ca.shared.global [%0], [%1], 16;" :: "r"(s), "l"(g) : "memory");
}
static __device__ __forceinline__ void cpa_commit() {
    asm volatile("cp.async.commit_group;" ::: "memory");
}
template <int N> static __device__ __forceinline__ void cpa_wait() {
    asm volatile("cp.async.wait_group %0;" :: "n"(N) : "memory");
}

// ---------------------------------------------------------------------------
// Detect x dtype: int64 => every odd 32-bit word (high half) is 0 (tokens<32000)
__global__ void k_detect(const unsigned int* xw) {
    if (threadIdx.x == 0 && blockIdx.x == 0) {
        int all0 = 1;
        for (int i = 0; i < 64; i++)
            if (xw[2 * i + 1] != 0u) { all0 = 0; break; }
        g_is64 = all0;
    }
}

// ---------------------------------------------------------------------------
// xi precompute (fused transpose). One thread per (t,b), b fastest.
//   dir0 at t*Bn+b ; dir1 at (Tn-1-t)*Bn+b.
__global__ void k_xi(const void* __restrict__ xv, const float* __restrict__ emb,
                     const float* __restrict__ WihF, const float* __restrict__ bihF,
                     const float* __restrict__ bhhF,
                     const float* __restrict__ WihB, const float* __restrict__ bihB,
                     const float* __restrict__ bhhB) {
    __shared__ float sw[2][12][4];
    __shared__ float sb[2][12];
    int tid = threadIdx.x;
    if (tid < 96) {
        int d = tid / 48, g = (tid % 48) / 4, j = tid & 3;
        const float* W = d ? WihB : WihF;
        sw[d][g][j] = W[g * 4 + j] * (g < 8 ? 0.5f : 1.0f);
    }
    if (tid < 24) {
        int d = tid / 12, g = tid % 12;
        const float* bi = d ? bihB : bihF;
        const float* bh = d ? bhhB : bhhF;
        float v = bi[g] + (g < 8 ? bh[g] : 0.0f);
        sb[d][g] = (g < 8 ? 0.5f : 1.0f) * v;
    }
    __syncthreads();

    int id = blockIdx.x * blockDim.x + threadIdx.x;   // t*Bn + b
    int b = id & (Bn - 1);
    int t = id >> 11;
    int tok;
    if (g_is64) tok = (int)((const long long*)xv)[(size_t)b * Tn + t];
    else        tok = ((const int*)xv)[(size_t)b * Tn + t];
    float4 e = *(const float4*)&emb[(size_t)tok * 4];

    int idxs[2] = { id, (Tn - 1 - t) * Bn + b };
    #pragma unroll
    for (int d = 0; d < 2; d++) {
        float o[12];
        #pragma unroll
        for (int g = 0; g < 12; g++) {
            float s = sb[d][g];
            s = fmaf(sw[d][g][0], e.x, s);
            s = fmaf(sw[d][g][1], e.y, s);
            s = fmaf(sw[d][g][2], e.z, s);
            s = fmaf(sw[d][g][3], e.w, s);
            o[g] = s;
        }
        int ix = idxs[d];
        g_xiR[d][ix] = make_float4(o[0], o[1], o[2],  o[3]);
        g_xiZ[d][ix] = make_float4(o[4], o[5], o[6],  o[7]);
        g_xiN[d][ix] = make_float4(o[8], o[9], o[10], o[11]);
    }
}

// ---------------------------------------------------------------------------
// Kernel 1: fwd + bwd GRU chains, whole chain per lane, 1 warp/block.
// Register double-buffer with compile-time indices (outer loop unrolled x2).
__global__ void __launch_bounds__(32, 1)
k_dirs(const float* __restrict__ WhhF, const float* __restrict__ bhhF,
       const float* __restrict__ WhhB, const float* __restrict__ bhhB) {
    int lane  = threadIdx.x;
    int chain = blockIdx.x * 32 + lane;
    int dir   = chain >> 11;                 // warp-uniform
    int row   = chain & (Bn - 1);

    const float* Whh = dir ? WhhB : WhhF;
    const float* bhh = dir ? bhhB : bhhF;

    // All gate rows pre-scaled by 0.5 (r,z for sigmoid-as-tanh; n for the
    // r*hn fold: n_arg = xn + t_r*hn2 + hn2 with hn2 = 0.5*hn).
    f2 wp[6][4];
    #pragma unroll
    for (int p = 0; p < 6; p++)
        #pragma unroll
        for (int j = 0; j < 4; j++)
            wp[p][j] = pk2(0.5f * Whh[(2 * p) * 4 + j], 0.5f * Whh[(2 * p + 1) * 4 + j]);
    const f2 bn01 = pk2(0.5f * bhh[8], 0.5f * bhh[9]);
    const f2 bn23 = pk2(0.5f * bhh[10], 0.5f * bhh[11]);

    const ulonglong2* pR = (const ulonglong2*)g_xiR[dir];
    const ulonglong2* pZ = (const ulonglong2*)g_xiZ[dir];
    const ulonglong2* pN = (const ulonglong2*)g_xiN[dir];
    float4*           hp = g_h[dir];

    float h0 = 0.f, h1 = 0.f, h2 = 0.f, h3 = 0.f;

    auto step = [&](ulonglong2 xR, ulonglong2 xZ, ulonglong2 xN, int t) {
        f2 q0 = pk2(h0, h0), q1 = pk2(h1, h1);
        f2 q2 = pk2(h2, h2), q3 = pk2(h3, h3);
        f2 ar01 = xR.x, ar23 = xR.y;             // 0.5-scaled xi_r
        f2 az01 = xZ.x, az23 = xZ.y;             // 0.5-scaled xi_z
        f2 an01 = bn01, an23 = bn23;

        ar01 = fma2(wp[0][0], q0, ar01); ar01 = fma2(wp[0][1], q1, ar01);
        ar01 = fma2(wp[0][2], q2, ar01); ar01 = fma2(wp[0][3], q3, ar01);
        ar23 = fma2(wp[1][0], q0, ar23); ar23 = fma2(wp[1][1], q1, ar23);
        ar23 = fma2(wp[1][2], q2, ar23); ar23 = fma2(wp[1][3], q3, ar23);
        az01 = fma2(wp[2][0], q0, az01); az01 = fma2(wp[2][1], q1, az01);
        az01 = fma2(wp[2][2], q2, az01); az01 = fma2(wp[2][3], q3, az01);
        az23 = fma2(wp[3][0], q0, az23); az23 = fma2(wp[3][1], q1, az23);
        az23 = fma2(wp[3][2], q2, az23); az23 = fma2(wp[3][3], q3, az23);
        an01 = fma2(wp[4][0], q0, an01); an01 = fma2(wp[4][1], q1, an01);
        an01 = fma2(wp[4][2], q2, an01); an01 = fma2(wp[4][3], q3, an01);
        an23 = fma2(wp[5][0], q0, an23); an23 = fma2(wp[5][1], q1, an23);
        an23 = fma2(wp[5][2], q2, an23); an23 = fma2(wp[5][3], q3, an23);

        float a0, a1, a2, a3; upk2(ar01, a0, a1); upk2(ar23, a2, a3);
        float t0 = tanhap(a0), t1 = tanhap(a1), t2 = tanhap(a2), t3 = tanhap(a3);
        float c0, c1, c2, c3; upk2(az01, c0, c1); upk2(az23, c2, c3);
        float z0 = fmaf(0.5f, tanhap(c0), 0.5f);
        float z1 = fmaf(0.5f, tanhap(c1), 0.5f);
        float z2 = fmaf(0.5f, tanhap(c2), 0.5f);
        float z3 = fmaf(0.5f, tanhap(c3), 0.5f);
        float g0, g1, g2, g3; upk2(an01, g0, g1); upk2(an23, g2, g3);   // hn2 = 0.5*hn
        float x0, x1, x2, x3; upk2(xN.x, x0, x1); upk2(xN.y, x2, x3);

        float n0 = tanhap(fmaf(t0, g0, x0 + g0));
        float n1 = tanhap(fmaf(t1, g1, x1 + g1));
        float n2 = tanhap(fmaf(t2, g2, x2 + g2));
        float n3 = tanhap(fmaf(t3, g3, x3 + g3));

        h0 = fmaf(z0, h0 - n0, n0);
        h1 = fmaf(z1, h1 - n1, n1);
        h2 = fmaf(z2, h2 - n2, n2);
        h3 = fmaf(z3, h3 - n3, n3);

        int tt = dir ? (Tn - 1 - t) : t;
        hp[(size_t)tt * Bn + row] = make_float4(h0, h1, h2, h3);
    };

    ulonglong2 R0[4], Z0[4], N0[4], R1[4], Z1[4], N1[4];
    #define LOADC(c, R, Z, N)                                         \
        { _Pragma("unroll")                                           \
          for (int k = 0; k < 4; k++) {                               \
              size_t e = (size_t)(4 * (c) + k) * Bn + row;            \
              (R)[k] = pR[e]; (Z)[k] = pZ[e]; (N)[k] = pN[e];         \
          } }

    LOADC(0, R0, Z0, N0);
    const int NCP = Tn / 8;
    for (int cp = 0; cp < NCP; cp++) {
        LOADC(2 * cp + 1, R1, Z1, N1);
        #pragma unroll
        for (int k = 0; k < 4; k++) step(R0[k], Z0[k], N0[k], 8 * cp + k);
        if (cp + 1 < NCP) LOADC(2 * cp + 2, R0, Z0, N0);
        #pragma unroll
        for (int k = 0; k < 4; k++) step(R1[k], Z1[k], N1[k], 8 * cp + 4 + k);
    }
    #undef LOADC
}

// ---------------------------------------------------------------------------
// Kernel 2: output GRU (H=1) with fused 8-wide projection from raw h.
#define OSTAGES 4
#define OCK 8
__global__ void __launch_bounds__(32, 1)
k_out(const float* __restrict__ WihO, const float* __restrict__ WhhO,
      const float* __restrict__ bihO, const float* __restrict__ bhhO,
      float* __restrict__ out) {
    __shared__ char sbuf[OSTAGES * OCK * 2 * 32 * 16];   // 32 KB
    uint32_t sbase = s2u(sbuf);

    int lane = threadIdx.x;
    int row = blockIdx.x * 32 + lane;

    float wr[8], wz[8], wn[8];
    #pragma unroll
    for (int j = 0; j < 8; j++) {
        wr[j] = 0.5f * WihO[0 * 8 + j];
        wz[j] = 0.5f * WihO[1 * 8 + j];
        wn[j] = WihO[2 * 8 + j];
    }
    float cr = 0.5f * (bihO[0] + bhhO[0]);
    float cz = 0.5f * (bihO[1] + bhhO[1]);
    float cn = bihO[2];
    float wrh = 0.5f * WhhO[0], wzh = 0.5f * WhhO[1];
    float whn = 0.5f * WhhO[2], bhn = 0.5f * bhhO[2];
    float h = 0.f;

    auto slot = [&](int st, int k, int a) -> uint32_t {
        return sbase + (uint32_t)((((st * OCK + k) * 2 + a) * 32 + lane) * 16);
    };
    auto issue = [&](int c) {
        int st = c & (OSTAGES - 1);
        #pragma unroll
        for (int k = 0; k < OCK; k++) {
            int ix = (OCK * c + k) * Bn + row;
            cpa16(slot(st, k, 0), &g_h[0][ix]);
            cpa16(slot(st, k, 1), &g_h[1][ix]);
        }
    };

    issue(0); cpa_commit();
    issue(1); cpa_commit();
    issue(2); cpa_commit();

    const int NC = Tn / OCK;
    float4* outv = (float4*)out;
    for (int c = 0; c < NC; c++) {
        if (c + 3 < NC) issue(c + 3);
        cpa_commit();
        cpa_wait<3>();
        int st = c & (OSTAGES - 1);
        float o[OCK];
        #pragma unroll
        for (int k = 0; k < OCK; k++) {
            float4 f = *(const float4*)(sbuf + (slot(st, k, 0) - sbase));
            float4 b = *(const float4*)(sbuf + (slot(st, k, 1) - sbase));
            float in[8] = { f.x, f.y, f.z, f.w, b.x, b.y, b.z, b.w };
            float sr = cr, sz = cz, sx = cn;
            #pragma unroll
            for (int j = 0; j < 8; j++) {
                sr = fmaf(wr[j], in[j], sr);
                sz = fmaf(wz[j], in[j], sz);
                sx = fmaf(wn[j], in[j], sx);
            }
            float tr = tanhap(fmaf(wrh, h, sr));
            float z  = fmaf(0.5f, tanhap(fmaf(wzh, h, sz)), 0.5f);
            float g  = fmaf(whn, h, bhn);              // 0.5*hn
            float n  = tanhap(fmaf(tr, g, sx + g));
            h = fmaf(z, h - n, n);
            o[k] = fmaf(0.5f, tanhap(0.5f * h), 0.5f);
        }
        #pragma unroll
        for (int q = 0; q < OCK / 4; q++)
            outv[(size_t)row * (Tn / 4) + c * (OCK / 4) + q] =
                make_float4(o[4 * q], o[4 * q + 1], o[4 * q + 2], o[4 * q + 3]);
    }
}

// ---------------------------------------------------------------------------
extern "C" void kernel_launch(void* const* d_in, const int* in_sizes, int n_in,
                              void* d_out, int out_size) {
    const void*  x    = d_in[0];
    const float* emb  = (const float*)d_in[1];
    const float* WihF = (const float*)d_in[2];
    const float* WhhF = (const float*)d_in[3];
    const float* bihF = (const float*)d_in[4];
    const float* bhhF = (const float*)d_in[5];
    const float* WihB = (const float*)d_in[6];
    const float* WhhB = (const float*)d_in[7];
    const float* bihB = (const float*)d_in[8];
    const float* bhhB = (const float*)d_in[9];
    const float* WihO = (const float*)d_in[10];
    const float* WhhO = (const float*)d_in[11];
    const float* bihO = (const float*)d_in[12];
    const float* bhhO = (const float*)d_in[13];

    k_detect<<<1, 32>>>((const unsigned int*)x);
    k_xi<<<TB / 256, 256>>>(x, emb, WihF, bihF, bhhF, WihB, bihB, bhhB);
    k_dirs<<<(2 * Bn) / 32, 32>>>(WhhF, bhhF, WhhB, bhhB);
    k_out<<<Bn / 32, 32>>>(WihO, WhhO, bihO, bhhO, (float*)d_out);
}

// round 7
// speedup vs baseline: 1.9073x; 1.9073x over previous
#include <cuda_runtime.h>
#include <cstdint>

#define Bn 2048
#define Tn 2048
#define TB (Tn * Bn)
#define NVOCAB 32000

typedef unsigned long long f2;

// Static device scratch (no runtime allocations allowed)
__device__ float4 g_xiR[2][TB];   // [dir][t*Bn+b]  0.5-scaled r-gate xi (bias folded)
__device__ float4 g_xiZ[2][TB];   // 0.5-scaled z-gate xi (bias folded)
__device__ float4 g_xiN[2][TB];   // UNscaled n-gate xi (bih folded)
__device__ float4 g_h[2][TB];     // raw hidden states per dir
__device__ float4 g_xo[TB];       // out-GRU projections {pr,pz,pn,0}
__device__ int    g_is64;

static __device__ __forceinline__ f2 pk2(float a, float b) {
    f2 r; asm("mov.b64 %0,{%1,%2};" : "=l"(r) : "f"(a), "f"(b)); return r;
}
static __device__ __forceinline__ void upk2(f2 v, float& a, float& b) {
    asm("mov.b64 {%0,%1},%2;" : "=f"(a), "=f"(b) : "l"(v));
}
static __device__ __forceinline__ f2 fma2(f2 a, f2 b, f2 c) {
    f2 r; asm("fma.rn.f32x2 %0,%1,%2,%3;" : "=l"(r) : "l"(a), "l"(b), "l"(c)); return r;
}
static __device__ __forceinline__ float tanhap(float x) {
    float r; asm("tanh.approx.f32 %0,%1;" : "=f"(r) : "f"(x)); return r;
}
static __device__ __forceinline__ uint32_t s2u(const void* p) {
    uint32_t a;
    asm("{ .reg .u64 t; cvta.to.shared.u64 t, %1; cvt.u32.u64 %0, t; }" : "=r"(a) : "l"(p));
    return a;
}
static __device__ __forceinline__ void cpa16(uint32_t s, const void* g) {
    asm volatile("cp.async.ca.shared.global [%0], [%1], 16;" :: "r"(s), "l"(g) : "memory");
}
static __device__ __forceinline__ void cpa_commit() {
    asm volatile("cp.async.commit_group;" ::: "memory");
}
template <int N> static __device__ __forceinline__ void cpa_wait() {
    asm volatile("cp.async.wait_group %0;" :: "n"(N) : "memory");
}

// ---------------------------------------------------------------------------
__global__ void k_detect(const unsigned int* xw) {
    if (threadIdx.x == 0 && blockIdx.x == 0) {
        int all0 = 1;
        for (int i = 0; i < 64; i++)
            if (xw[2 * i + 1] != 0u) { all0 = 0; break; }
        g_is64 = all0;
    }
}

// ---------------------------------------------------------------------------
// xi precompute (fused transpose). One thread per (t,b), b fastest.
__global__ void k_xi(const void* __restrict__ xv, const float* __restrict__ emb,
                     const float* __restrict__ WihF, const float* __restrict__ bihF,
                     const float* __restrict__ bhhF,
                     const float* __restrict__ WihB, const float* __restrict__ bihB,
                     const float* __restrict__ bhhB) {
    __shared__ float sw[2][12][4];
    __shared__ float sb[2][12];
    int tid = threadIdx.x;
    if (tid < 96) {
        int d = tid / 48, g = (tid % 48) / 4, j = tid & 3;
        const float* W = d ? WihB : WihF;
        sw[d][g][j] = W[g * 4 + j] * (g < 8 ? 0.5f : 1.0f);
    }
    if (tid < 24) {
        int d = tid / 12, g = tid % 12;
        const float* bi = d ? bihB : bihF;
        const float* bh = d ? bhhB : bhhF;
        float v = bi[g] + (g < 8 ? bh[g] : 0.0f);
        sb[d][g] = (g < 8 ? 0.5f : 1.0f) * v;
    }
    __syncthreads();

    int id = blockIdx.x * blockDim.x + threadIdx.x;   // t*Bn + b
    int b = id & (Bn - 1);
    int t = id >> 11;
    int tok;
    if (g_is64) tok = (int)((const long long*)xv)[(size_t)b * Tn + t];
    else        tok = ((const int*)xv)[(size_t)b * Tn + t];
    float4 e = *(const float4*)&emb[(size_t)tok * 4];

    int idxs[2] = { id, (Tn - 1 - t) * Bn + b };
    #pragma unroll
    for (int d = 0; d < 2; d++) {
        float o[12];
        #pragma unroll
        for (int g = 0; g < 12; g++) {
            float s = sb[d][g];
            s = fmaf(sw[d][g][0], e.x, s);
            s = fmaf(sw[d][g][1], e.y, s);
            s = fmaf(sw[d][g][2], e.z, s);
            s = fmaf(sw[d][g][3], e.w, s);
            o[g] = s;
        }
        int ix = idxs[d];
        g_xiR[d][ix] = make_float4(o[0], o[1], o[2],  o[3]);
        g_xiZ[d][ix] = make_float4(o[4], o[5], o[6],  o[7]);
        g_xiN[d][ix] = make_float4(o[8], o[9], o[10], o[11]);
    }
}

// ---------------------------------------------------------------------------
// Kernel 1: fwd + bwd GRU chains, whole chain per lane, 1 warp/block,
// smem cp.async ring (proven layout), ulonglong2 slot reads, hn-prescale.
#define DSTAGES 4
__global__ void __launch_bounds__(32, 1)
k_dirs(const float* __restrict__ WhhF, const float* __restrict__ bhhF,
       const float* __restrict__ WhhB, const float* __restrict__ bhhB) {
    __shared__ char sbuf[DSTAGES * 4 * 3 * 32 * 16];   // 24 KB
    uint32_t sbase = s2u(sbuf);

    int lane  = threadIdx.x;
    int chain = blockIdx.x * 32 + lane;
    int dir   = chain >> 11;                 // warp-uniform
    int row   = chain & (Bn - 1);

    const float* Whh = dir ? WhhB : WhhF;
    const float* bhh = dir ? bhhB : bhhF;

    // ALL gate rows pre-scaled by 0.5 (r,z: sigmoid-as-tanh; n: hn-prescale).
    f2 wp[6][4];
    #pragma unroll
    for (int p = 0; p < 6; p++)
        #pragma unroll
        for (int j = 0; j < 4; j++)
            wp[p][j] = pk2(0.5f * Whh[(2 * p) * 4 + j], 0.5f * Whh[(2 * p + 1) * 4 + j]);
    const f2 bn01 = pk2(0.5f * bhh[8],  0.5f * bhh[9]);
    const f2 bn23 = pk2(0.5f * bhh[10], 0.5f * bhh[11]);

    const float4* pR = g_xiR[dir];
    const float4* pZ = g_xiZ[dir];
    const float4* pN = g_xiN[dir];
    float4*       hp = g_h[dir];

    auto slot = [&](int st, int k, int g) -> uint32_t {
        return sbase + (uint32_t)((((st * 4 + k) * 3 + g) * 32 + lane) * 16);
    };
    auto issue = [&](int c) {
        int st = c & (DSTAGES - 1);
        #pragma unroll
        for (int k = 0; k < 4; k++) {
            int ix = (4 * c + k) * Bn + row;
            cpa16(slot(st, k, 0), pR + ix);
            cpa16(slot(st, k, 1), pZ + ix);
            cpa16(slot(st, k, 2), pN + ix);
        }
    };

    issue(0); cpa_commit();
    issue(1); cpa_commit();
    issue(2); cpa_commit();

    float h0 = 0.f, h1 = 0.f, h2 = 0.f, h3 = 0.f;

    const int NC = Tn / 4;
    for (int c = 0; c < NC; c++) {
        if (c + 3 < NC) issue(c + 3);
        cpa_commit();
        cpa_wait<3>();
        int st = c & (DSTAGES - 1);
        #pragma unroll
        for (int k = 0; k < 4; k++) {
            ulonglong2 xR = *(const ulonglong2*)(sbuf + (slot(st, k, 0) - sbase));
            ulonglong2 xZ = *(const ulonglong2*)(sbuf + (slot(st, k, 1) - sbase));
            ulonglong2 xN = *(const ulonglong2*)(sbuf + (slot(st, k, 2) - sbase));

            f2 q0 = pk2(h0, h0), q1 = pk2(h1, h1);
            f2 q2 = pk2(h2, h2), q3 = pk2(h3, h3);
            f2 ar01 = xR.x, ar23 = xR.y;
            f2 az01 = xZ.x, az23 = xZ.y;
            f2 an01 = bn01, an23 = bn23;

            ar01 = fma2(wp[0][0], q0, ar01); ar01 = fma2(wp[0][1], q1, ar01);
            ar01 = fma2(wp[0][2], q2, ar01); ar01 = fma2(wp[0][3], q3, ar01);
            ar23 = fma2(wp[1][0], q0, ar23); ar23 = fma2(wp[1][1], q1, ar23);
            ar23 = fma2(wp[1][2], q2, ar23); ar23 = fma2(wp[1][3], q3, ar23);
            az01 = fma2(wp[2][0], q0, az01); az01 = fma2(wp[2][1], q1, az01);
            az01 = fma2(wp[2][2], q2, az01); az01 = fma2(wp[2][3], q3, az01);
            az23 = fma2(wp[3][0], q0, az23); az23 = fma2(wp[3][1], q1, az23);
            az23 = fma2(wp[3][2], q2, az23); az23 = fma2(wp[3][3], q3, az23);
            an01 = fma2(wp[4][0], q0, an01); an01 = fma2(wp[4][1], q1, an01);
            an01 = fma2(wp[4][2], q2, an01); an01 = fma2(wp[4][3], q3, an01);
            an23 = fma2(wp[5][0], q0, an23); an23 = fma2(wp[5][1], q1, an23);
            an23 = fma2(wp[5][2], q2, an23); an23 = fma2(wp[5][3], q3, an23);

            float a0, a1, a2, a3; upk2(ar01, a0, a1); upk2(ar23, a2, a3);
            float t0 = tanhap(a0), t1 = tanhap(a1), t2 = tanhap(a2), t3 = tanhap(a3);
            float c0, c1, c2, c3; upk2(az01, c0, c1); upk2(az23, c2, c3);
            float z0 = fmaf(0.5f, tanhap(c0), 0.5f);
            float z1 = fmaf(0.5f, tanhap(c1), 0.5f);
            float z2 = fmaf(0.5f, tanhap(c2), 0.5f);
            float z3 = fmaf(0.5f, tanhap(c3), 0.5f);
            float g0, g1, g2, g3; upk2(an01, g0, g1); upk2(an23, g2, g3);  // 0.5*hn
            float x0, x1, x2, x3; upk2(xN.x, x0, x1); upk2(xN.y, x2, x3);

            float n0 = tanhap(fmaf(t0, g0, x0 + g0));
            float n1 = tanhap(fmaf(t1, g1, x1 + g1));
            float n2 = tanhap(fmaf(t2, g2, x2 + g2));
            float n3 = tanhap(fmaf(t3, g3, x3 + g3));

            h0 = fmaf(z0, h0 - n0, n0);
            h1 = fmaf(z1, h1 - n1, n1);
            h2 = fmaf(z2, h2 - n2, n2);
            h3 = fmaf(z3, h3 - n3, n3);

            int t  = 4 * c + k;
            int tt = dir ? (Tn - 1 - t) : t;
            hp[(size_t)tt * Bn + row] = make_float4(h0, h1, h2, h3);
        }
    }
}

// ---------------------------------------------------------------------------
// Parallel projection: g_xo = {pr, pz, pn, 0} from both dirs' raw h.
// pr,pz pre-scaled 0.5; biases folded (bhh_n kept for k_out's hn-prescale).
__global__ void k_proj(const float* __restrict__ WihO,
                       const float* __restrict__ bihO,
                       const float* __restrict__ bhhO) {
    int id = blockIdx.x * blockDim.x + threadIdx.x;
    float4 f = g_h[0][id];
    float4 b = g_h[1][id];
    float in[8] = { f.x, f.y, f.z, f.w, b.x, b.y, b.z, b.w };
    float pr = 0.5f * (bihO[0] + bhhO[0]);
    float pz = 0.5f * (bihO[1] + bhhO[1]);
    float pn = bihO[2];
    #pragma unroll
    for (int j = 0; j < 8; j++) {
        pr = fmaf(0.5f * WihO[0 * 8 + j], in[j], pr);
        pz = fmaf(0.5f * WihO[1 * 8 + j], in[j], pz);
        pn = fmaf(WihO[2 * 8 + j],        in[j], pn);
    }
    g_xo[id] = make_float4(pr, pz, pn, 0.f);
}

// ---------------------------------------------------------------------------
// Kernel 2: output GRU (H=1), one float4 of projections per step.
#define OSTAGES 4
#define OCK 8
__global__ void __launch_bounds__(32, 1)
k_out(const float* __restrict__ WhhO, const float* __restrict__ bhhO,
      float* __restrict__ out) {
    __shared__ char sbuf[OSTAGES * OCK * 32 * 16];   // 16 KB
    uint32_t sbase = s2u(sbuf);

    int lane = threadIdx.x;
    int row = blockIdx.x * 32 + lane;

    float wrh = 0.5f * WhhO[0], wzh = 0.5f * WhhO[1];
    float whn = 0.5f * WhhO[2], bhn = 0.5f * bhhO[2];
    float h = 0.f;

    auto slot = [&](int st, int k) -> uint32_t {
        return sbase + (uint32_t)(((st * OCK + k) * 32 + lane) * 16);
    };
    auto issue = [&](int c) {
        int st = c & (OSTAGES - 1);
        #pragma unroll
        for (int k = 0; k < OCK; k++)
            cpa16(slot(st, k), &g_xo[(OCK * c + k) * Bn + row]);
    };

    issue(0); cpa_commit();
    issue(1); cpa_commit();
    issue(2); cpa_commit();

    const int NC = Tn / OCK;
    float4* outv = (float4*)out;
    for (int c = 0; c < NC; c++) {
        if (c + 3 < NC) issue(c + 3);
        cpa_commit();
        cpa_wait<3>();
        int st = c & (OSTAGES - 1);
        float o[OCK];
        #pragma unroll
        for (int k = 0; k < OCK; k++) {
            float4 p = *(const float4*)(sbuf + (slot(st, k) - sbase));
            float tr = tanhap(fmaf(wrh, h, p.x));
            float z  = fmaf(0.5f, tanhap(fmaf(wzh, h, p.y)), 0.5f);
            float g  = fmaf(whn, h, bhn);               // 0.5*hn
            float n  = tanhap(fmaf(tr, g, p.z + g));
            h = fmaf(z, h - n, n);
            o[k] = fmaf(0.5f, tanhap(0.5f * h), 0.5f);
        }
        #pragma unroll
        for (int q = 0; q < OCK / 4; q++)
            outv[(size_t)row * (Tn / 4) + c * (OCK / 4) + q] =
                make_float4(o[4 * q], o[4 * q + 1], o[4 * q + 2], o[4 * q + 3]);
    }
}

// ---------------------------------------------------------------------------
extern "C" void kernel_launch(void* const* d_in, const int* in_sizes, int n_in,
                              void* d_out, int out_size) {
    const void*  x    = d_in[0];
    const float* emb  = (const float*)d_in[1];
    const float* WihF = (const float*)d_in[2];
    const float* WhhF = (const float*)d_in[3];
    const float* bihF = (const float*)d_in[4];
    const float* bhhF = (const float*)d_in[5];
    const float* WihB = (const float*)d_in[6];
    const float* WhhB = (const float*)d_in[7];
    const float* bihB = (const float*)d_in[8];
    const float* bhhB = (const float*)d_in[9];
    const float* WihO = (const float*)d_in[10];
    const float* WhhO = (const float*)d_in[11];
    const float* bihO = (const float*)d_in[12];
    const float* bhhO = (const float*)d_in[13];

    k_detect<<<1, 32>>>((const unsigned int*)x);
    k_xi<<<TB / 256, 256>>>(x, emb, WihF, bihF, bhhF, WihB, bihB, bhhB);
    k_dirs<<<(2 * Bn) / 32, 32>>>(WhhF, bhhF, WhhB, bhhB);
    k_proj<<<TB / 256, 256>>>(WihO, bihO, bhhO);
    k_out<<<Bn / 32, 32>>>(WhhO, bhhO, (float*)d_out);
}

// round 8
// speedup vs baseline: 2.1642x; 1.1347x over previous
#include <cuda_runtime.h>
#include <cstdint>

#define Bn 2048
#define Tn 2048
#define TB (Tn * Bn)
#define NVOCAB 32000

typedef unsigned long long f2;

// Static device scratch (no runtime allocations allowed)
__device__ float4 g_xiR[2][TB];   // [dir][t*Bn+b]  0.5-scaled r-gate xi (bias folded)
__device__ float4 g_xiZ[2][TB];   // 0.5-scaled z-gate xi (bias folded)
__device__ float4 g_xiN[2][TB];   // UNscaled n-gate xi (bih folded)
__device__ float4 g_h[2][TB];     // raw hidden states per dir
__device__ float4 g_xo[TB];       // out-GRU projections {pr,pz,pn,0}
__device__ int    g_is64;

static __device__ __forceinline__ f2 pk2(float a, float b) {
    f2 r; asm("mov.b64 %0,{%1,%2};" : "=l"(r) : "f"(a), "f"(b)); return r;
}
static __device__ __forceinline__ void upk2(f2 v, float& a, float& b) {
    asm("mov.b64 {%0,%1},%2;" : "=f"(a), "=f"(b) : "l"(v));
}
static __device__ __forceinline__ f2 fma2(f2 a, f2 b, f2 c) {
    f2 r; asm("fma.rn.f32x2 %0,%1,%2,%3;" : "=l"(r) : "l"(a), "l"(b), "l"(c)); return r;
}
static __device__ __forceinline__ float tanhap(float x) {
    float r; asm("tanh.approx.f32 %0,%1;" : "=f"(r) : "f"(x)); return r;
}
static __device__ __forceinline__ uint32_t s2u(const void* p) {
    uint32_t a;
    asm("{ .reg .u64 t; cvta.to.shared.u64 t, %1; cvt.u32.u64 %0, t; }" : "=r"(a) : "l"(p));
    return a;
}
static __device__ __forceinline__ void cpa16(uint32_t s, const void* g) {
    asm volatile("cp.async.ca.shared.global [%0], [%1], 16;" :: "r"(s), "l"(g) : "memory");
}
static __device__ __forceinline__ void cpa8(uint32_t s, const void* g) {
    asm volatile("cp.async.ca.shared.global [%0], [%1], 8;" :: "r"(s), "l"(g) : "memory");
}
static __device__ __forceinline__ void cpa_commit() {
    asm volatile("cp.async.commit_group;" ::: "memory");
}
template <int N> static __device__ __forceinline__ void cpa_wait() {
    asm volatile("cp.async.wait_group %0;" :: "n"(N) : "memory");
}

// ---------------------------------------------------------------------------
__global__ void k_detect(const unsigned int* xw) {
    if (threadIdx.x == 0 && blockIdx.x == 0) {
        int all0 = 1;
        for (int i = 0; i < 64; i++)
            if (xw[2 * i + 1] != 0u) { all0 = 0; break; }
        g_is64 = all0;
    }
}

// ---------------------------------------------------------------------------
// xi precompute (fused transpose). One thread per (t,b), b fastest.
__global__ void k_xi(const void* __restrict__ xv, const float* __restrict__ emb,
                     const float* __restrict__ WihF, const float* __restrict__ bihF,
                     const float* __restrict__ bhhF,
                     const float* __restrict__ WihB, const float* __restrict__ bihB,
                     const float* __restrict__ bhhB) {
    __shared__ float sw[2][12][4];
    __shared__ float sb[2][12];
    int tid = threadIdx.x;
    if (tid < 96) {
        int d = tid / 48, g = (tid % 48) / 4, j = tid & 3;
        const float* W = d ? WihB : WihF;
        sw[d][g][j] = W[g * 4 + j] * (g < 8 ? 0.5f : 1.0f);
    }
    if (tid < 24) {
        int d = tid / 12, g = tid % 12;
        const float* bi = d ? bihB : bihF;
        const float* bh = d ? bhhB : bhhF;
        float v = bi[g] + (g < 8 ? bh[g] : 0.0f);
        sb[d][g] = (g < 8 ? 0.5f : 1.0f) * v;
    }
    __syncthreads();

    int id = blockIdx.x * blockDim.x + threadIdx.x;   // t*Bn + b
    int b = id & (Bn - 1);
    int t = id >> 11;
    int tok;
    if (g_is64) tok = (int)((const long long*)xv)[(size_t)b * Tn + t];
    else        tok = ((const int*)xv)[(size_t)b * Tn + t];
    float4 e = *(const float4*)&emb[(size_t)tok * 4];

    int idxs[2] = { id, (Tn - 1 - t) * Bn + b };
    #pragma unroll
    for (int d = 0; d < 2; d++) {
        float o[12];
        #pragma unroll
        for (int g = 0; g < 12; g++) {
            float s = sb[d][g];
            s = fmaf(sw[d][g][0], e.x, s);
            s = fmaf(sw[d][g][1], e.y, s);
            s = fmaf(sw[d][g][2], e.z, s);
            s = fmaf(sw[d][g][3], e.w, s);
            o[g] = s;
        }
        int ix = idxs[d];
        g_xiR[d][ix] = make_float4(o[0], o[1], o[2],  o[3]);
        g_xiZ[d][ix] = make_float4(o[4], o[5], o[6],  o[7]);
        g_xiN[d][ix] = make_float4(o[8], o[9], o[10], o[11]);
    }
}

// ---------------------------------------------------------------------------
// Kernel 1: fwd + bwd GRU chains, each chain split across lane pair (l, l+16).
// 64-thread blocks (2 warps -> 2 SMSPs/SM). smem cp.async ring, 8B slots.
#define DSTAGES 4
__global__ void __launch_bounds__(64, 1)
k_dirs(const float* __restrict__ WhhF, const float* __restrict__ bhhF,
       const float* __restrict__ WhhB, const float* __restrict__ bhhB) {
    __shared__ char sbuf[DSTAGES * 4 * 3 * 64 * 8];   // 24 KB (both warps)
    uint32_t sbase = s2u(sbuf) + (uint32_t)(threadIdx.x >> 5) * (DSTAGES * 4 * 3 * 32 * 8);

    int lane  = threadIdx.x & 31;
    int w     = threadIdx.x >> 5;
    int half  = lane >> 4;                       // 0: units 0,1 ; 1: units 2,3
    int chain = (blockIdx.x * 2 + w) * 16 + (lane & 15);
    int dir   = chain >> 11;                     // warp-uniform (16 | 2048)
    int row   = chain & (Bn - 1);
    int u0    = 2 * half;

    const float* Whh = dir ? WhhB : WhhF;
    const float* bhh = dir ? bhhB : bhhF;

    // Per-lane weights for its 2 gate rows, ALL pre-scaled 0.5
    // (r,z: sigmoid-as-tanh; n: hn-prescale). Column permuted to local q order.
    f2 wr[4], wz[4], wn[4];
    #pragma unroll
    for (int j = 0; j < 4; j++) {
        int gj = (j + u0) & 3;                   // global unit feeding local slot j
        wr[j] = pk2(0.5f * Whh[(0 + u0) * 4 + gj], 0.5f * Whh[(1 + u0) * 4 + gj]);
        wz[j] = pk2(0.5f * Whh[(4 + u0) * 4 + gj], 0.5f * Whh[(5 + u0) * 4 + gj]);
        wn[j] = pk2(0.5f * Whh[(8 + u0) * 4 + gj], 0.5f * Whh[(9 + u0) * 4 + gj]);
    }
    const f2 bn = pk2(0.5f * bhh[8 + u0], 0.5f * bhh[9 + u0]);

    const char* pR = (const char*)(g_xiR[dir]) + 8 * half;
    const char* pZ = (const char*)(g_xiZ[dir]) + 8 * half;
    const char* pN = (const char*)(g_xiN[dir]) + 8 * half;
    float2*     hp = (float2*)g_h[dir];

    auto slot = [&](int st, int k, int g) -> uint32_t {
        return sbase + (uint32_t)((((st * 4 + k) * 3 + g) * 32 + lane) * 8);
    };
    auto issue = [&](int c) {
        int st = c & (DSTAGES - 1);
        #pragma unroll
        for (int k = 0; k < 4; k++) {
            size_t off = (size_t)((4 * c + k) * Bn + row) * 16;
            cpa8(slot(st, k, 0), pR + off);
            cpa8(slot(st, k, 1), pZ + off);
            cpa8(slot(st, k, 2), pN + off);
        }
    };

    issue(0); cpa_commit();
    issue(1); cpa_commit();
    issue(2); cpa_commit();

    float ha = 0.f, hb = 0.f;                    // this lane's 2 hidden units

    const int NC = Tn / 4;
    for (int c = 0; c < NC; c++) {
        if (c + 3 < NC) issue(c + 3);
        cpa_commit();
        cpa_wait<3>();
        int st = c & (DSTAGES - 1);
        #pragma unroll
        for (int k = 0; k < 4; k++) {
            // exchange h with peer half-chain (start early; own-h FMAs overlap)
            float pa = __shfl_xor_sync(0xffffffffu, ha, 16);
            float pb = __shfl_xor_sync(0xffffffffu, hb, 16);

            f2 xR = *(const f2*)(sbuf + (slot(st, k, 0) - s2u(sbuf)));
            f2 xZ = *(const f2*)(sbuf + (slot(st, k, 1) - s2u(sbuf)));
            f2 xN = *(const f2*)(sbuf + (slot(st, k, 2) - s2u(sbuf)));

            f2 q0 = pk2(ha, ha), q1 = pk2(hb, hb);
            f2 ar = fma2(wr[0], q0, xR); ar = fma2(wr[1], q1, ar);
            f2 az = fma2(wz[0], q0, xZ); az = fma2(wz[1], q1, az);
            f2 an = fma2(wn[0], q0, bn); an = fma2(wn[1], q1, an);

            f2 q2 = pk2(pa, pa), q3 = pk2(pb, pb);
            ar = fma2(wr[2], q2, ar); ar = fma2(wr[3], q3, ar);
            az = fma2(wz[2], q2, az); az = fma2(wz[3], q3, az);
            an = fma2(wn[2], q2, an); an = fma2(wn[3], q3, an);

            float a0, a1; upk2(ar, a0, a1);
            float t0 = tanhap(a0), t1 = tanhap(a1);
            float c0, c1; upk2(az, c0, c1);
            float z0 = fmaf(0.5f, tanhap(c0), 0.5f);
            float z1 = fmaf(0.5f, tanhap(c1), 0.5f);
            float g0, g1; upk2(an, g0, g1);                 // 0.5*hn
            float x0, x1; upk2(xN, x0, x1);

            float n0 = tanhap(fmaf(t0, g0, x0 + g0));
            float n1 = tanhap(fmaf(t1, g1, x1 + g1));

            ha = fmaf(z0, ha - n0, n0);
            hb = fmaf(z1, hb - n1, n1);

            int t  = 4 * c + k;
            int tt = dir ? (Tn - 1 - t) : t;
            hp[(size_t)(tt * Bn + row) * 2 + half] = make_float2(ha, hb);
        }
    }
}

// ---------------------------------------------------------------------------
// Parallel projection: g_xo = {pr, pz, pn, 0} from both dirs' raw h.
__global__ void k_proj(const float* __restrict__ WihO,
                       const float* __restrict__ bihO,
                       const float* __restrict__ bhhO) {
    int id = blockIdx.x * blockDim.x + threadIdx.x;
    float4 f = g_h[0][id];
    float4 b = g_h[1][id];
    float in[8] = { f.x, f.y, f.z, f.w, b.x, b.y, b.z, b.w };
    float pr = 0.5f * (bihO[0] + bhhO[0]);
    float pz = 0.5f * (bihO[1] + bhhO[1]);
    float pn = bihO[2];
    #pragma unroll
    for (int j = 0; j < 8; j++) {
        pr = fmaf(0.5f * WihO[0 * 8 + j], in[j], pr);
        pz = fmaf(0.5f * WihO[1 * 8 + j], in[j], pz);
        pn = fmaf(WihO[2 * 8 + j],        in[j], pn);
    }
    g_xo[id] = make_float4(pr, pz, pn, 0.f);
}

// ---------------------------------------------------------------------------
// Kernel 2: output GRU (H=1), one float4 of projections per step.
#define OSTAGES 4
#define OCK 8
__global__ void __launch_bounds__(32, 1)
k_out(const float* __restrict__ WhhO, const float* __restrict__ bhhO,
      float* __restrict__ out) {
    __shared__ char sbuf[OSTAGES * OCK * 32 * 16];   // 16 KB
    uint32_t sbase = s2u(sbuf);

    int lane = threadIdx.x;
    int row = blockIdx.x * 32 + lane;

    float wrh = 0.5f * WhhO[0], wzh = 0.5f * WhhO[1];
    float whn = 0.5f * WhhO[2], bhn = 0.5f * bhhO[2];
    float h = 0.f;

    auto slot = [&](int st, int k) -> uint32_t {
        return sbase + (uint32_t)(((st * OCK + k) * 32 + lane) * 16);
    };
    auto issue = [&](int c) {
        int st = c & (OSTAGES - 1);
        #pragma unroll
        for (int k = 0; k < OCK; k++)
            cpa16(slot(st, k), &g_xo[(OCK * c + k) * Bn + row]);
    };

    issue(0); cpa_commit();
    issue(1); cpa_commit();
    issue(2); cpa_commit();

    const int NC = Tn / OCK;
    float4* outv = (float4*)out;
    for (int c = 0; c < NC; c++) {
        if (c + 3 < NC) issue(c + 3);
        cpa_commit();
        cpa_wait<3>();
        int st = c & (OSTAGES - 1);
        float o[OCK];
        #pragma unroll
        for (int k = 0; k < OCK; k++) {
            float4 p = *(const float4*)(sbuf + (slot(st, k) - sbase));
            float tr = tanhap(fmaf(wrh, h, p.x));
            float z  = fmaf(0.5f, tanhap(fmaf(wzh, h, p.y)), 0.5f);
            float g  = fmaf(whn, h, bhn);               // 0.5*hn
            float n  = tanhap(fmaf(tr, g, p.z + g));
            h = fmaf(z, h - n, n);
            o[k] = fmaf(0.5f, tanhap(0.5f * h), 0.5f);
        }
        #pragma unroll
        for (int q = 0; q < OCK / 4; q++)
            outv[(size_t)row * (Tn / 4) + c * (OCK / 4) + q] =
                make_float4(o[4 * q], o[4 * q + 1], o[4 * q + 2], o[4 * q + 3]);
    }
}

// ---------------------------------------------------------------------------
extern "C" void kernel_launch(void* const* d_in, const int* in_sizes, int n_in,
                              void* d_out, int out_size) {
    const void*  x    = d_in[0];
    const float* emb  = (const float*)d_in[1];
    const float* WihF = (const float*)d_in[2];
    const float* WhhF = (const float*)d_in[3];
    const float* bihF = (const float*)d_in[4];
    const float* bhhF = (const float*)d_in[5];
    const float* WihB = (const float*)d_in[6];
    const float* WhhB = (const float*)d_in[7];
    const float* bihB = (const float*)d_in[8];
    const float* bhhB = (const float*)d_in[9];
    const float* WihO = (const float*)d_in[10];
    const float* WhhO = (const float*)d_in[11];
    const float* bihO = (const float*)d_in[12];
    const float* bhhO = (const float*)d_in[13];

    k_detect<<<1, 32>>>((const unsigned int*)x);
    k_xi<<<TB / 256, 256>>>(x, emb, WihF, bihF, bhhF, WihB, bihB, bhhB);
    k_dirs<<<128, 64>>>(WhhF, bhhF, WhhB, bhhB);
    k_proj<<<TB / 256, 256>>>(WihO, bihO, bhhO);
    k_out<<<Bn / 32, 32>>>(WhhO, bhhO, (float*)d_out);
}

// round 9
// speedup vs baseline: 2.4037x; 1.1107x over previous
#include <cuda_runtime.h>
#include <cuda_fp16.h>
#include <cstdint>

#define Bn 2048
#define Tn 2048
#define TB (Tn * Bn)
#define NVOCAB 32000

typedef unsigned long long f2;

// Static device scratch (no runtime allocations allowed)
// Per (dir,t,b): uint4 = {h2(.5xr0,.5xr1), h2(.5xz0,.5xz1), h2(.5xr2,.5xr3), h2(.5xz2,.5xz3)}
//                uint2 = {h2(xn0,xn1), h2(xn2,xn3)}
__device__ uint4  g_xiRZ[2][TB];
__device__ uint2  g_xiN2[2][TB];
__device__ float4 g_h[2][TB];     // raw hidden states per dir [t*Bn+b]
__device__ int    g_is64;

static __device__ __forceinline__ f2 pk2(float a, float b) {
    f2 r; asm("mov.b64 %0,{%1,%2};" : "=l"(r) : "f"(a), "f"(b)); return r;
}
static __device__ __forceinline__ void upk2(f2 v, float& a, float& b) {
    asm("mov.b64 {%0,%1},%2;" : "=f"(a), "=f"(b) : "l"(v));
}
static __device__ __forceinline__ f2 fma2(f2 a, f2 b, f2 c) {
    f2 r; asm("fma.rn.f32x2 %0,%1,%2,%3;" : "=l"(r) : "l"(a), "l"(b), "l"(c)); return r;
}
static __device__ __forceinline__ float tanhap(float x) {
    float r; asm("tanh.approx.f32 %0,%1;" : "=f"(r) : "f"(x)); return r;
}
static __device__ __forceinline__ uint32_t pkh(float a, float b) {
    __half2 h = __floats2half2_rn(a, b);
    return *reinterpret_cast<uint32_t*>(&h);
}
static __device__ __forceinline__ f2 h2f2(uint32_t v) {
    __half2 h = *reinterpret_cast<__half2*>(&v);
    float2 f = __half22float2(h);            // .x = low = first value
    return pk2(f.x, f.y);
}
static __device__ __forceinline__ uint32_t s2u(const void* p) {
    uint32_t a;
    asm("{ .reg .u64 t; cvta.to.shared.u64 t, %1; cvt.u32.u64 %0, t; }" : "=r"(a) : "l"(p));
    return a;
}
static __device__ __forceinline__ void cpa16(uint32_t s, const void* g) {
    asm volatile("cp.async.ca.shared.global [%0], [%1], 16;" :: "r"(s), "l"(g) : "memory");
}
static __device__ __forceinline__ void cpa8(uint32_t s, const void* g) {
    asm volatile("cp.async.ca.shared.global [%0], [%1], 8;" :: "r"(s), "l"(g) : "memory");
}
static __device__ __forceinline__ void cpa4(uint32_t s, const void* g) {
    asm volatile("cp.async.ca.shared.global [%0], [%1], 4;" :: "r"(s), "l"(g) : "memory");
}
static __device__ __forceinline__ void cpa_commit() {
    asm volatile("cp.async.commit_group;" ::: "memory");
}
template <int N> static __device__ __forceinline__ void cpa_wait() {
    asm volatile("cp.async.wait_group %0;" :: "n"(N) : "memory");
}

// ---------------------------------------------------------------------------
__global__ void k_detect(const unsigned int* xw) {
    if (threadIdx.x == 0 && blockIdx.x == 0) {
        int all0 = 1;
        for (int i = 0; i < 64; i++)
            if (xw[2 * i + 1] != 0u) { all0 = 0; break; }
        g_is64 = all0;
    }
}

// ---------------------------------------------------------------------------
// xi precompute (fused transpose), fp16 outputs. One thread per (t,b), b fastest.
__global__ void k_xi(const void* __restrict__ xv, const float* __restrict__ emb,
                     const float* __restrict__ WihF, const float* __restrict__ bihF,
                     const float* __restrict__ bhhF,
                     const float* __restrict__ WihB, const float* __restrict__ bihB,
                     const float* __restrict__ bhhB) {
    __shared__ float sw[2][12][4];
    __shared__ float sb[2][12];
    int tid = threadIdx.x;
    if (tid < 96) {
        int d = tid / 48, g = (tid % 48) / 4, j = tid & 3;
        const float* W = d ? WihB : WihF;
        sw[d][g][j] = W[g * 4 + j] * (g < 8 ? 0.5f : 1.0f);
    }
    if (tid < 24) {
        int d = tid / 12, g = tid % 12;
        const float* bi = d ? bihB : bihF;
        const float* bh = d ? bhhB : bhhF;
        float v = bi[g] + (g < 8 ? bh[g] : 0.0f);
        sb[d][g] = (g < 8 ? 0.5f : 1.0f) * v;
    }
    __syncthreads();

    int id = blockIdx.x * blockDim.x + threadIdx.x;   // t*Bn + b
    int b = id & (Bn - 1);
    int t = id >> 11;
    int tok;
    if (g_is64) tok = (int)((const long long*)xv)[(size_t)b * Tn + t];
    else        tok = ((const int*)xv)[(size_t)b * Tn + t];
    float4 e = *(const float4*)&emb[(size_t)tok * 4];

    int idxs[2] = { id, (Tn - 1 - t) * Bn + b };
    #pragma unroll
    for (int d = 0; d < 2; d++) {
        float o[12];
        #pragma unroll
        for (int g = 0; g < 12; g++) {
            float s = sb[d][g];
            s = fmaf(sw[d][g][0], e.x, s);
            s = fmaf(sw[d][g][1], e.y, s);
            s = fmaf(sw[d][g][2], e.z, s);
            s = fmaf(sw[d][g][3], e.w, s);
            o[g] = s;
        }
        int ix = idxs[d];
        uint4 rz;
        rz.x = pkh(o[0], o[1]);   // 0.5*xr unit 0,1
        rz.y = pkh(o[4], o[5]);   // 0.5*xz unit 0,1
        rz.z = pkh(o[2], o[3]);   // 0.5*xr unit 2,3
        rz.w = pkh(o[6], o[7]);   // 0.5*xz unit 2,3
        g_xiRZ[d][ix] = rz;
        g_xiN2[d][ix] = make_uint2(pkh(o[8], o[9]), pkh(o[10], o[11]));
    }
}

// ---------------------------------------------------------------------------
// Kernel 1: fwd + bwd GRU chains, chain split across lane pair (l, l+16).
// 64-thread blocks (2 warps -> 2 SMSPs/SM). fp16 xi via cp.async ring.
#define DSTAGES 4
// per warp: rz region 4*4*32*8 = 4KB, n region 4*4*32*4 = 2KB
#define RZ_REGION (DSTAGES * 4 * 32 * 8)
#define N_REGION  (DSTAGES * 4 * 32 * 4)
#define WARP_SMEM (RZ_REGION + N_REGION)
__global__ void __launch_bounds__(64, 1)
k_dirs(const float* __restrict__ WhhF, const float* __restrict__ bhhF,
       const float* __restrict__ WhhB, const float* __restrict__ bhhB) {
    __shared__ char sbuf[2 * WARP_SMEM];   // 12 KB
    uint32_t sbase = s2u(sbuf) + (uint32_t)(threadIdx.x >> 5) * WARP_SMEM;

    int lane  = threadIdx.x & 31;
    int w     = threadIdx.x >> 5;
    int half  = lane >> 4;                       // 0: units 0,1 ; 1: units 2,3
    int chain = (blockIdx.x * 2 + w) * 16 + (lane & 15);
    int dir   = chain >> 11;                     // warp-uniform
    int row   = chain & (Bn - 1);
    int u0    = 2 * half;

    const float* Whh = dir ? WhhB : WhhF;
    const float* bhh = dir ? bhhB : bhhF;

    // Per-lane weights for its 2 gate rows, ALL pre-scaled 0.5
    // (r,z: sigmoid-as-tanh; n: hn-prescale). Columns permuted to local q order.
    f2 wr[4], wz[4], wn[4];
    #pragma unroll
    for (int j = 0; j < 4; j++) {
        int gj = (j + u0) & 3;                   // global unit feeding local slot j
        wr[j] = pk2(0.5f * Whh[(0 + u0) * 4 + gj], 0.5f * Whh[(1 + u0) * 4 + gj]);
        wz[j] = pk2(0.5f * Whh[(4 + u0) * 4 + gj], 0.5f * Whh[(5 + u0) * 4 + gj]);
        wn[j] = pk2(0.5f * Whh[(8 + u0) * 4 + gj], 0.5f * Whh[(9 + u0) * 4 + gj]);
    }
    const f2 bn = pk2(0.5f * bhh[8 + u0], 0.5f * bhh[9 + u0]);

    const char* pRZ = (const char*)(g_xiRZ[dir]) + 8 * half;   // 8B of 16B record
    const char* pN  = (const char*)(g_xiN2[dir]) + 4 * half;   // 4B of 8B record
    float2*     hp  = (float2*)g_h[dir];

    auto rzslot = [&](int st, int k) -> uint32_t {
        return sbase + (uint32_t)(((st * 4 + k) * 32 + lane) * 8);
    };
    auto nslot = [&](int st, int k) -> uint32_t {
        return sbase + RZ_REGION + (uint32_t)(((st * 4 + k) * 32 + lane) * 4);
    };
    auto issue = [&](int c) {
        int st = c & (DSTAGES - 1);
        #pragma unroll
        for (int k = 0; k < 4; k++) {
            int tb = (4 * c + k) * Bn + row;
            cpa8(rzslot(st, k), pRZ + (size_t)tb * 16);
            cpa4(nslot(st, k),  pN  + (size_t)tb * 8);
        }
    };

    issue(0); cpa_commit();
    issue(1); cpa_commit();
    issue(2); cpa_commit();

    float ha = 0.f, hb = 0.f;

    const int NC = Tn / 4;
    for (int c = 0; c < NC; c++) {
        if (c + 3 < NC) issue(c + 3);
        cpa_commit();
        cpa_wait<3>();
        int st = c & (DSTAGES - 1);
        #pragma unroll
        for (int k = 0; k < 4; k++) {
            // exchange h with peer half-chain (starts early; own-h FMAs overlap)
            float pa = __shfl_xor_sync(0xffffffffu, ha, 16);
            float pb = __shfl_xor_sync(0xffffffffu, hb, 16);

            uint2 hrz = *(const uint2*)(sbuf + (rzslot(st, k) - s2u(sbuf)));
            uint32_t hn = *(const uint32_t*)(sbuf + (nslot(st, k) - s2u(sbuf)));
            f2 xR = h2f2(hrz.x);                 // (0.5xr_a, 0.5xr_b)
            f2 xZ = h2f2(hrz.y);
            f2 xN = h2f2(hn);

            f2 q0 = pk2(ha, ha), q1 = pk2(hb, hb);
            f2 ar = fma2(wr[0], q0, xR); ar = fma2(wr[1], q1, ar);
            f2 az = fma2(wz[0], q0, xZ); az = fma2(wz[1], q1, az);
            f2 an = fma2(wn[0], q0, bn); an = fma2(wn[1], q1, an);

            f2 q2 = pk2(pa, pa), q3 = pk2(pb, pb);
            ar = fma2(wr[2], q2, ar); ar = fma2(wr[3], q3, ar);
            az = fma2(wz[2], q2, az); az = fma2(wz[3], q3, az);
            an = fma2(wn[2], q2, an); an = fma2(wn[3], q3, an);

            float a0, a1; upk2(ar, a0, a1);
            float t0 = tanhap(a0), t1 = tanhap(a1);
            float c0, c1; upk2(az, c0, c1);
            float z0 = fmaf(0.5f, tanhap(c0), 0.5f);
            float z1 = fmaf(0.5f, tanhap(c1), 0.5f);
            float g0, g1; upk2(an, g0, g1);                 // 0.5*hn
            float x0, x1; upk2(xN, x0, x1);

            float n0 = tanhap(fmaf(t0, g0, x0 + g0));
            float n1 = tanhap(fmaf(t1, g1, x1 + g1));

            ha = fmaf(z0, ha - n0, n0);
            hb = fmaf(z1, hb - n1, n1);

            int t  = 4 * c + k;
            int tt = dir ? (Tn - 1 - t) : t;
            hp[(size_t)(tt * Bn + row) * 2 + half] = make_float2(ha, hb);
        }
    }
}

// ---------------------------------------------------------------------------
// Kernel 2: output GRU (H=1) with fused 8-wide projection from raw h.
// (Round-6 proven form: projection rides in idle issue slots, 107us measured.)
#define OSTAGES 4
#define OCK 8
__global__ void __launch_bounds__(32, 1)
k_out(const float* __restrict__ WihO, const float* __restrict__ WhhO,
      const float* __restrict__ bihO, const float* __restrict__ bhhO,
      float* __restrict__ out) {
    __shared__ char sbuf[OSTAGES * OCK * 2 * 32 * 16];   // 32 KB
    uint32_t sbase = s2u(sbuf);

    int lane = threadIdx.x;
    int row = blockIdx.x * 32 + lane;

    float wr[8], wz[8], wn[8];
    #pragma unroll
    for (int j = 0; j < 8; j++) {
        wr[j] = 0.5f * WihO[0 * 8 + j];
        wz[j] = 0.5f * WihO[1 * 8 + j];
        wn[j] = WihO[2 * 8 + j];
    }
    float cr = 0.5f * (bihO[0] + bhhO[0]);
    float cz = 0.5f * (bihO[1] + bhhO[1]);
    float cn = bihO[2];
    float wrh = 0.5f * WhhO[0], wzh = 0.5f * WhhO[1];
    float whn = 0.5f * WhhO[2], bhn = 0.5f * bhhO[2];
    float h = 0.f;

    auto slot = [&](int st, int k, int a) -> uint32_t {
        return sbase + (uint32_t)((((st * OCK + k) * 2 + a) * 32 + lane) * 16);
    };
    auto issue = [&](int c) {
        int st = c & (OSTAGES - 1);
        #pragma unroll
        for (int k = 0; k < OCK; k++) {
            int ix = (OCK * c + k) * Bn + row;
            cpa16(slot(st, k, 0), &g_h[0][ix]);
            cpa16(slot(st, k, 1), &g_h[1][ix]);
        }
    };

    issue(0); cpa_commit();
    issue(1); cpa_commit();
    issue(2); cpa_commit();

    const int NC = Tn / OCK;
    float4* outv = (float4*)out;
    for (int c = 0; c < NC; c++) {
        if (c + 3 < NC) issue(c + 3);
        cpa_commit();
        cpa_wait<3>();
        int st = c & (OSTAGES - 1);
        float o[OCK];
        #pragma unroll
        for (int k = 0; k < OCK; k++) {
            float4 f = *(const float4*)(sbuf + (slot(st, k, 0) - sbase));
            float4 b = *(const float4*)(sbuf + (slot(st, k, 1) - sbase));
            float in[8] = { f.x, f.y, f.z, f.w, b.x, b.y, b.z, b.w };
            float sr = cr, sz = cz, sx = cn;
            #pragma unroll
            for (int j = 0; j < 8; j++) {
                sr = fmaf(wr[j], in[j], sr);
                sz = fmaf(wz[j], in[j], sz);
                sx = fmaf(wn[j], in[j], sx);
            }
            float tr = tanhap(fmaf(wrh, h, sr));
            float z  = fmaf(0.5f, tanhap(fmaf(wzh, h, sz)), 0.5f);
            float g  = fmaf(whn, h, bhn);              // 0.5*hn
            float n  = tanhap(fmaf(tr, g, sx + g));
            h = fmaf(z, h - n, n);
            o[k] = fmaf(0.5f, tanhap(0.5f * h), 0.5f);
        }
        #pragma unroll
        for (int q = 0; q < OCK / 4; q++)
            outv[(size_t)row * (Tn / 4) + c * (OCK / 4) + q] =
                make_float4(o[4 * q], o[4 * q + 1], o[4 * q + 2], o[4 * q + 3]);
    }
}

// ---------------------------------------------------------------------------
extern "C" void kernel_launch(void* const* d_in, const int* in_sizes, int n_in,
                              void* d_out, int out_size) {
    const void*  x    = d_in[0];
    const float* emb  = (const float*)d_in[1];
    const float* WihF = (const float*)d_in[2];
    const float* WhhF = (const float*)d_in[3];
    const float* bihF = (const float*)d_in[4];
    const float* bhhF = (const float*)d_in[5];
    const float* WihB = (const float*)d_in[6];
    const float* WhhB = (const float*)d_in[7];
    const float* bihB = (const float*)d_in[8];
    const float* bhhB = (const float*)d_in[9];
    const float* WihO = (const float*)d_in[10];
    const float* WhhO = (const float*)d_in[11];
    const float* bihO = (const float*)d_in[12];
    const float* bhhO = (const float*)d_in[13];

    k_detect<<<1, 32>>>((const unsigned int*)x);
    k_xi<<<TB / 256, 256>>>(x, emb, WihF, bihF, bhhF, WihB, bihB, bhhB);
    k_dirs<<<128, 64>>>(WhhF, bhhF, WhhB, bhhB);
    k_out<<<Bn / 32, 32>>>(WihO, WhhO, bihO, bhhO, (float*)d_out);
}

// round 10
// speedup vs baseline: 3.5193x; 1.4641x over previous
#include <cuda_runtime.h>
#include <cuda_fp16.h>
#include <cstdint>

#define Bn 2048
#define Tn 2048
#define TB (Tn * Bn)

typedef unsigned long long f2;

// Static device scratch (no runtime allocations allowed)
__device__ uint4  g_xiRZ[2][TB];   // fp16 {.5xr01,.5xz01,.5xr23,.5xz23}
__device__ uint2  g_xiN2[2][TB];   // fp16 {xn01, xn23}
__device__ float4 g_h[2][TB];      // raw hidden states per dir [t*Bn+b]
__device__ int    g_is64;

static __device__ __forceinline__ f2 pk2(float a, float b) {
    f2 r; asm("mov.b64 %0,{%1,%2};" : "=l"(r) : "f"(a), "f"(b)); return r;
}
static __device__ __forceinline__ void upk2(f2 v, float& a, float& b) {
    asm("mov.b64 {%0,%1},%2;" : "=f"(a), "=f"(b) : "l"(v));
}
static __device__ __forceinline__ f2 fma2(f2 a, f2 b, f2 c) {
    f2 r; asm("fma.rn.f32x2 %0,%1,%2,%3;" : "=l"(r) : "l"(a), "l"(b), "l"(c)); return r;
}
static __device__ __forceinline__ float tanhap(float x) {
    float r; asm("tanh.approx.f32 %0,%1;" : "=f"(r) : "f"(x)); return r;
}
static __device__ __forceinline__ uint32_t pkh(float a, float b) {
    __half2 h = __floats2half2_rn(a, b);
    return *reinterpret_cast<uint32_t*>(&h);
}
static __device__ __forceinline__ f2 h2f2(uint32_t v) {
    __half2 h = *reinterpret_cast<__half2*>(&v);
    float2 f = __half22float2(h);
    return pk2(f.x, f.y);
}
static __device__ __forceinline__ uint32_t s2u(const void* p) {
    uint32_t a;
    asm("{ .reg .u64 t; cvta.to.shared.u64 t, %1; cvt.u32.u64 %0, t; }" : "=r"(a) : "l"(p));
    return a;
}
static __device__ __forceinline__ void cpa16(uint32_t s, const void* g) {
    asm volatile("cp.async.ca.shared.global [%0], [%1], 16;" :: "r"(s), "l"(g) : "memory");
}
static __device__ __forceinline__ void cpa8(uint32_t s, const void* g) {
    asm volatile("cp.async.ca.shared.global [%0], [%1], 8;" :: "r"(s), "l"(g) : "memory");
}
static __device__ __forceinline__ void cpa4(uint32_t s, const void* g) {
    asm volatile("cp.async.ca.shared.global [%0], [%1], 4;" :: "r"(s), "l"(g) : "memory");
}
static __device__ __forceinline__ void cpa_commit() {
    asm volatile("cp.async.commit_group;" ::: "memory");
}
template <int N> static __device__ __forceinline__ void cpa_wait() {
    asm volatile("cp.async.wait_group %0;" :: "n"(N) : "memory");
}

// ---------------------------------------------------------------------------
__global__ void k_detect(const unsigned int* xw) {
    if (threadIdx.x == 0 && blockIdx.x == 0) {
        int all0 = 1;
        for (int i = 0; i < 64; i++)
            if (xw[2 * i + 1] != 0u) { all0 = 0; break; }
        g_is64 = all0;
    }
}

// ---------------------------------------------------------------------------
// xi precompute (fused transpose), fp16 outputs. One thread per (t,b), b fastest.
__global__ void k_xi(const void* __restrict__ xv, const float* __restrict__ emb,
                     const float* __restrict__ WihF, const float* __restrict__ bihF,
                     const float* __restrict__ bhhF,
                     const float* __restrict__ WihB, const float* __restrict__ bihB,
                     const float* __restrict__ bhhB) {
    __shared__ float sw[2][12][4];
    __shared__ float sb[2][12];
    int tid = threadIdx.x;
    if (tid < 96) {
        int d = tid / 48, g = (tid % 48) / 4, j = tid & 3;
        const float* W = d ? WihB : WihF;
        sw[d][g][j] = W[g * 4 + j] * (g < 8 ? 0.5f : 1.0f);
    }
    if (tid < 24) {
        int d = tid / 12, g = tid % 12;
        const float* bi = d ? bihB : bihF;
        const float* bh = d ? bhhB : bhhF;
        float v = bi[g] + (g < 8 ? bh[g] : 0.0f);
        sb[d][g] = (g < 8 ? 0.5f : 1.0f) * v;
    }
    __syncthreads();

    int id = blockIdx.x * blockDim.x + threadIdx.x;   // t*Bn + b
    int b = id & (Bn - 1);
    int t = id >> 11;
    int tok;
    if (g_is64) tok = (int)((const long long*)xv)[(size_t)b * Tn + t];
    else        tok = ((const int*)xv)[(size_t)b * Tn + t];
    float4 e = *(const float4*)&emb[(size_t)tok * 4];

    int idxs[2] = { id, (Tn - 1 - t) * Bn + b };
    #pragma unroll
    for (int d = 0; d < 2; d++) {
        float o[12];
        #pragma unroll
        for (int g = 0; g < 12; g++) {
            float s = sb[d][g];
            s = fmaf(sw[d][g][0], e.x, s);
            s = fmaf(sw[d][g][1], e.y, s);
            s = fmaf(sw[d][g][2], e.z, s);
            s = fmaf(sw[d][g][3], e.w, s);
            o[g] = s;
        }
        int ix = idxs[d];
        uint4 rz;
        rz.x = pkh(o[0], o[1]);
        rz.y = pkh(o[4], o[5]);
        rz.z = pkh(o[2], o[3]);
        rz.w = pkh(o[6], o[7]);
        g_xiRZ[d][ix] = rz;
        g_xiN2[d][ix] = make_uint2(pkh(o[8], o[9]), pkh(o[10], o[11]));
    }
}

// ---------------------------------------------------------------------------
// Kernel 1: segmented fwd+bwd GRU chains. Chain split across lane pair
// (l, l+16); T split into S_DIR segments with W_DIR-step warmup.
#define S_DIR 4
#define W_DIR 128
#define SEGL_DIR (Tn / S_DIR)        // 512
#define DSTAGES 4
#define RZ_REGION (DSTAGES * 4 * 32 * 8)
#define N_REGION  (DSTAGES * 4 * 32 * 4)
#define WARP_SMEM (RZ_REGION + N_REGION)
__global__ void __launch_bounds__(64, 1)
k_dirs(const float* __restrict__ WhhF, const float* __restrict__ bhhF,
       const float* __restrict__ WhhB, const float* __restrict__ bhhB) {
    __shared__ char sbuf[2 * WARP_SMEM];   // 12 KB
    uint32_t sb0 = s2u(sbuf);
    uint32_t sbase = sb0 + (uint32_t)(threadIdx.x >> 5) * WARP_SMEM;

    int lane = threadIdx.x & 31;
    int half = lane >> 4;                        // 0: units 0,1 ; 1: units 2,3
    int gw   = blockIdx.x * 2 + (threadIdx.x >> 5);
    int chainseg = gw * 16 + (lane & 15);        // seg*4096 + chain
    int seg   = chainseg >> 12;                  // warp-uniform
    int chain = chainseg & 4095;
    int dir   = chain >> 11;                     // warp-uniform
    int row   = chain & (Bn - 1);
    int u0    = 2 * half;

    const float* Whh = dir ? WhhB : WhhF;
    const float* bhh = dir ? bhhB : bhhF;

    f2 wr[4], wz[4], wn[4];
    #pragma unroll
    for (int j = 0; j < 4; j++) {
        int gj = (j + u0) & 3;
        wr[j] = pk2(0.5f * Whh[(0 + u0) * 4 + gj], 0.5f * Whh[(1 + u0) * 4 + gj]);
        wz[j] = pk2(0.5f * Whh[(4 + u0) * 4 + gj], 0.5f * Whh[(5 + u0) * 4 + gj]);
        wn[j] = pk2(0.5f * Whh[(8 + u0) * 4 + gj], 0.5f * Whh[(9 + u0) * 4 + gj]);
    }
    const f2 bn = pk2(0.5f * bhh[8 + u0], 0.5f * bhh[9 + u0]);

    const char* pRZ = (const char*)(g_xiRZ[dir]) + 8 * half;
    const char* pN  = (const char*)(g_xiN2[dir]) + 4 * half;
    float2*     hp  = (float2*)g_h[dir];

    int segstart = seg * SEGL_DIR;
    int tstart   = seg ? segstart - W_DIR : 0;
    int nsteps   = seg ? SEGL_DIR + W_DIR : SEGL_DIR;

    auto rzslot = [&](int st, int k) -> uint32_t {
        return sbase + (uint32_t)(((st * 4 + k) * 32 + lane) * 8);
    };
    auto nslot = [&](int st, int k) -> uint32_t {
        return sbase + RZ_REGION + (uint32_t)(((st * 4 + k) * 32 + lane) * 4);
    };
    auto issue = [&](int c) {
        int st = c & (DSTAGES - 1);
        #pragma unroll
        for (int k = 0; k < 4; k++) {
            int tb = (tstart + 4 * c + k) * Bn + row;
            cpa8(rzslot(st, k), pRZ + (size_t)tb * 16);
            cpa4(nslot(st, k),  pN  + (size_t)tb * 8);
        }
    };

    issue(0); cpa_commit();
    issue(1); cpa_commit();
    issue(2); cpa_commit();

    float ha = 0.f, hb = 0.f;

    const int NC = nsteps / 4;
    for (int c = 0; c < NC; c++) {
        if (c + 3 < NC) issue(c + 3);
        cpa_commit();
        cpa_wait<3>();
        int st = c & (DSTAGES - 1);
        #pragma unroll
        for (int k = 0; k < 4; k++) {
            float pa = __shfl_xor_sync(0xffffffffu, ha, 16);
            float pb = __shfl_xor_sync(0xffffffffu, hb, 16);

            uint2 hrz = *(const uint2*)(sbuf + (rzslot(st, k) - sb0));
            uint32_t hn = *(const uint32_t*)(sbuf + (nslot(st, k) - sb0));
            f2 xR = h2f2(hrz.x);
            f2 xZ = h2f2(hrz.y);
            f2 xN = h2f2(hn);

            f2 q0 = pk2(ha, ha), q1 = pk2(hb, hb);
            f2 ar = fma2(wr[0], q0, xR); ar = fma2(wr[1], q1, ar);
            f2 az = fma2(wz[0], q0, xZ); az = fma2(wz[1], q1, az);
            f2 an = fma2(wn[0], q0, bn); an = fma2(wn[1], q1, an);

            f2 q2 = pk2(pa, pa), q3 = pk2(pb, pb);
            ar = fma2(wr[2], q2, ar); ar = fma2(wr[3], q3, ar);
            az = fma2(wz[2], q2, az); az = fma2(wz[3], q3, az);
            an = fma2(wn[2], q2, an); an = fma2(wn[3], q3, an);

            float a0, a1; upk2(ar, a0, a1);
            float t0 = tanhap(a0), t1 = tanhap(a1);
            float c0, c1; upk2(az, c0, c1);
            float z0 = fmaf(0.5f, tanhap(c0), 0.5f);
            float z1 = fmaf(0.5f, tanhap(c1), 0.5f);
            float g0, g1; upk2(an, g0, g1);
            float x0, x1; upk2(xN, x0, x1);

            float n0 = tanhap(fmaf(t0, g0, x0 + g0));
            float n1 = tanhap(fmaf(t1, g1, x1 + g1));

            ha = fmaf(z0, ha - n0, n0);
            hb = fmaf(z1, hb - n1, n1);

            int t = tstart + 4 * c + k;
            if (t >= segstart) {                 // skip warmup writes
                int tt = dir ? (Tn - 1 - t) : t;
                hp[(size_t)(tt * Bn + row) * 2 + half] = make_float2(ha, hb);
            }
        }
    }
}

// ---------------------------------------------------------------------------
// Kernel 2: segmented output GRU (H=1) with fused 8-wide projection.
#define S_OUT 8
#define W_OUT 128
#define SEGL_OUT (Tn / S_OUT)        // 256
#define OSTAGES 4
#define OCK 8
__global__ void __launch_bounds__(32, 1)
k_out(const float* __restrict__ WihO, const float* __restrict__ WhhO,
      const float* __restrict__ bihO, const float* __restrict__ bhhO,
      float* __restrict__ out) {
    __shared__ char sbuf[OSTAGES * OCK * 2 * 32 * 16];   // 32 KB
    uint32_t sbase = s2u(sbuf);

    int lane = threadIdx.x;
    int rowseg = blockIdx.x * 32 + lane;         // seg*2048 + row
    int seg = rowseg >> 11;                      // warp-uniform
    int row = rowseg & (Bn - 1);

    float wr[8], wz[8], wn[8];
    #pragma unroll
    for (int j = 0; j < 8; j++) {
        wr[j] = 0.5f * WihO[0 * 8 + j];
        wz[j] = 0.5f * WihO[1 * 8 + j];
        wn[j] = WihO[2 * 8 + j];
    }
    float cr = 0.5f * (bihO[0] + bhhO[0]);
    float cz = 0.5f * (bihO[1] + bhhO[1]);
    float cn = bihO[2];
    float wrh = 0.5f * WhhO[0], wzh = 0.5f * WhhO[1];
    float whn = 0.5f * WhhO[2], bhn = 0.5f * bhhO[2];
    float h = 0.f;

    int segstart = seg * SEGL_OUT;
    int tstart   = seg ? segstart - W_OUT : 0;
    int nsteps   = seg ? SEGL_OUT + W_OUT : SEGL_OUT;

    auto slot = [&](int st, int k, int a) -> uint32_t {
        return sbase + (uint32_t)((((st * OCK + k) * 2 + a) * 32 + lane) * 16);
    };
    auto issue = [&](int c) {
        int st = c & (OSTAGES - 1);
        #pragma unroll
        for (int k = 0; k < OCK; k++) {
            int ix = (tstart + OCK * c + k) * Bn + row;
            cpa16(slot(st, k, 0), &g_h[0][ix]);
            cpa16(slot(st, k, 1), &g_h[1][ix]);
        }
    };

    issue(0); cpa_commit();
    issue(1); cpa_commit();
    issue(2); cpa_commit();

    const int NC = nsteps / OCK;
    float4* outv = (float4*)out;
    for (int c = 0; c < NC; c++) {
        if (c + 3 < NC) issue(c + 3);
        cpa_commit();
        cpa_wait<3>();
        int st = c & (OSTAGES - 1);
        int t0 = tstart + OCK * c;
        float o[OCK];
        #pragma unroll
        for (int k = 0; k < OCK; k++) {
            float4 f = *(const float4*)(sbuf + (slot(st, k, 0) - sbase));
            float4 b = *(const float4*)(sbuf + (slot(st, k, 1) - sbase));
            float in[8] = { f.x, f.y, f.z, f.w, b.x, b.y, b.z, b.w };
            float sr = cr, sz = cz, sx = cn;
            #pragma unroll
            for (int j = 0; j < 8; j++) {
                sr = fmaf(wr[j], in[j], sr);
                sz = fmaf(wz[j], in[j], sz);
                sx = fmaf(wn[j], in[j], sx);
            }
            float tr = tanhap(fmaf(wrh, h, sr));
            float z  = fmaf(0.5f, tanhap(fmaf(wzh, h, sz)), 0.5f);
            float g  = fmaf(whn, h, bhn);
            float n  = tanhap(fmaf(tr, g, sx + g));
            h = fmaf(z, h - n, n);
            o[k] = fmaf(0.5f, tanhap(0.5f * h), 0.5f);
        }
        if (t0 >= segstart) {                    // chunks are fully warmup or live
            #pragma unroll
            for (int q = 0; q < OCK / 4; q++)
                outv[(size_t)row * (Tn / 4) + (t0 >> 2) + q] =
                    make_float4(o[4 * q], o[4 * q + 1], o[4 * q + 2], o[4 * q + 3]);
        }
    }
}

// ---------------------------------------------------------------------------
extern "C" void kernel_launch(void* const* d_in, const int* in_sizes, int n_in,
                              void* d_out, int out_size) {
    const void*  x    = d_in[0];
    const float* emb  = (const float*)d_in[1];
    const float* WihF = (const float*)d_in[2];
    const float* WhhF = (const float*)d_in[3];
    const float* bihF = (const float*)d_in[4];
    const float* bhhF = (const float*)d_in[5];
    const float* WihB = (const float*)d_in[6];
    const float* WhhB = (const float*)d_in[7];
    const float* bihB = (const float*)d_in[8];
    const float* bhhB = (const float*)d_in[9];
    const float* WihO = (const float*)d_in[10];
    const float* WhhO = (const float*)d_in[11];
    const float* bihO = (const float*)d_in[12];
    const float* bhhO = (const float*)d_in[13];

    k_detect<<<1, 32>>>((const unsigned int*)x);
    k_xi<<<TB / 256, 256>>>(x, emb, WihF, bihF, bhhF, WihB, bihB, bhhB);
    k_dirs<<<(2 * Bn * S_DIR) / 32, 64>>>(WhhF, bhhF, WhhB, bhhB);   // 512 blocks
    k_out<<<(Bn * S_OUT) / 32, 32>>>(WihO, WhhO, bihO, bhhO, (float*)d_out);
}

// round 11
// speedup vs baseline: 4.9590x; 1.4091x over previous
#include <cuda_runtime.h>
#include <cuda_fp16.h>
#include <cstdint>

#define Bn 2048
#define Tn 2048
#define TB (Tn * Bn)

typedef unsigned long long f2;

// Static device scratch (no runtime allocations allowed)
__device__ float4 g_e[TB];        // transposed fp32 embedding [t*Bn+b] (67MB, L2-resident)
__device__ uint2  g_h16[2][TB];   // fp16 hidden {h2(h0,h1), h2(h2,h3)} per dir (67MB)
__device__ int    g_is64;

static __device__ __forceinline__ f2 pk2(float a, float b) {
    f2 r; asm("mov.b64 %0,{%1,%2};" : "=l"(r) : "f"(a), "f"(b)); return r;
}
static __device__ __forceinline__ void upk2(f2 v, float& a, float& b) {
    asm("mov.b64 {%0,%1},%2;" : "=f"(a), "=f"(b) : "l"(v));
}
static __device__ __forceinline__ f2 fma2(f2 a, f2 b, f2 c) {
    f2 r; asm("fma.rn.f32x2 %0,%1,%2,%3;" : "=l"(r) : "l"(a), "l"(b), "l"(c)); return r;
}
static __device__ __forceinline__ float tanhap(float x) {
    float r; asm("tanh.approx.f32 %0,%1;" : "=f"(r) : "f"(x)); return r;
}
static __device__ __forceinline__ uint32_t pkh(float a, float b) {
    __half2 h = __floats2half2_rn(a, b);
    return *reinterpret_cast<uint32_t*>(&h);
}
static __device__ __forceinline__ f2 h2f2(uint32_t v) {
    __half2 h = *reinterpret_cast<__half2*>(&v);
    float2 f = __half22float2(h);
    return pk2(f.x, f.y);
}
static __device__ __forceinline__ uint32_t s2u(const void* p) {
    uint32_t a;
    asm("{ .reg .u64 t; cvta.to.shared.u64 t, %1; cvt.u32.u64 %0, t; }" : "=r"(a) : "l"(p));
    return a;
}
static __device__ __forceinline__ void cpa16(uint32_t s, const void* g) {
    asm volatile("cp.async.ca.shared.global [%0], [%1], 16;" :: "r"(s), "l"(g) : "memory");
}
static __device__ __forceinline__ void cpa8(uint32_t s, const void* g) {
    asm volatile("cp.async.ca.shared.global [%0], [%1], 8;" :: "r"(s), "l"(g) : "memory");
}
static __device__ __forceinline__ void cpa_commit() {
    asm volatile("cp.async.commit_group;" ::: "memory");
}
template <int N> static __device__ __forceinline__ void cpa_wait() {
    asm volatile("cp.async.wait_group %0;" :: "n"(N) : "memory");
}

// ---------------------------------------------------------------------------
__global__ void k_detect(const unsigned int* xw) {
    if (threadIdx.x == 0 && blockIdx.x == 0) {
        int all0 = 1;
        for (int i = 0; i < 64; i++)
            if (xw[2 * i + 1] != 0u) { all0 = 0; break; }
        g_is64 = all0;
    }
}

// ---------------------------------------------------------------------------
// Transposed embedding: e[t*Bn+b] = emb[x[b][t]] (fp32 float4).
// Each thread: one b-row, 8 consecutive t (vectorized token loads).
__global__ void k_xi(const void* __restrict__ xv, const float* __restrict__ emb) {
    int bt  = blockIdx.x;                 // 2048 blocks
    int b0  = (bt & 7) * 256;             // Bn/256 = 8 tiles in b
    int t0  = (bt >> 3) * 8;              // 256 tiles in t
    int b   = b0 + threadIdx.x;

    int tok[8];
    if (g_is64) {
        const int4* p = (const int4*)((const long long*)xv + (size_t)b * Tn + t0);
        int4 a = p[0], c = p[1], d = p[2], e = p[3];
        tok[0] = a.x; tok[1] = a.z; tok[2] = c.x; tok[3] = c.z;
        tok[4] = d.x; tok[5] = d.z; tok[6] = e.x; tok[7] = e.z;
    } else {
        const int4* p = (const int4*)((const int*)xv + (size_t)b * Tn + t0);
        int4 a = p[0], c = p[1];
        tok[0] = a.x; tok[1] = a.y; tok[2] = a.z; tok[3] = a.w;
        tok[4] = c.x; tok[5] = c.y; tok[6] = c.z; tok[7] = c.w;
    }
    #pragma unroll
    for (int k = 0; k < 8; k++) {
        float4 e = *(const float4*)&emb[(size_t)tok[k] * 4];
        g_e[(size_t)(t0 + k) * Bn + b] = e;
    }
}

// ---------------------------------------------------------------------------
// Kernel 1: segmented fwd+bwd GRU chains; chain split across lane pair
// (l, l+16). Computes xi = Wih*e + bias in-register from streamed e.
#define S_DIR 4
#define W_DIR 128
#define SEGL_DIR (Tn / S_DIR)        // 512
#define DSTAGES 4
#define WARP_SMEM (DSTAGES * 4 * 16 * 16)   // 4KB per warp
__global__ void __launch_bounds__(64, 1)
k_dirs(const float* __restrict__ WhhF, const float* __restrict__ bhhF,
       const float* __restrict__ WhhB, const float* __restrict__ bhhB,
       const float* __restrict__ WihF, const float* __restrict__ bihF,
       const float* __restrict__ WihB, const float* __restrict__ bihB) {
    __shared__ char sbuf[2 * WARP_SMEM];   // 8 KB
    uint32_t sb0 = s2u(sbuf);
    uint32_t sbase = sb0 + (uint32_t)(threadIdx.x >> 5) * WARP_SMEM;

    int lane = threadIdx.x & 31;
    int half = lane >> 4;                        // 0: units 0,1 ; 1: units 2,3
    int ch   = lane & 15;
    int gw   = blockIdx.x * 2 + (threadIdx.x >> 5);
    int chainseg = gw * 16 + ch;                 // seg*4096 + chain
    int seg   = chainseg >> 12;                  // warp-uniform
    int chain = chainseg & 4095;
    int dir   = chain >> 11;                     // warp-uniform
    int row   = chain & (Bn - 1);
    int u0    = 2 * half;

    const float* Whh = dir ? WhhB : WhhF;
    const float* bhh = dir ? bhhB : bhhF;
    const float* Wih = dir ? WihB : WihF;
    const float* bih = dir ? bihB : bihF;

    // Recurrent weights (local q order), all pre-scaled 0.5.
    f2 wr[4], wz[4], wn[4];
    #pragma unroll
    for (int j = 0; j < 4; j++) {
        int gj = (j + u0) & 3;
        wr[j] = pk2(0.5f * Whh[(0 + u0) * 4 + gj], 0.5f * Whh[(1 + u0) * 4 + gj]);
        wz[j] = pk2(0.5f * Whh[(4 + u0) * 4 + gj], 0.5f * Whh[(5 + u0) * 4 + gj]);
        wn[j] = pk2(0.5f * Whh[(8 + u0) * 4 + gj], 0.5f * Whh[(9 + u0) * 4 + gj]);
    }
    // Input weights (e order, no permutation), r/z pre-scaled 0.5.
    f2 ur[4], uz[4], un[4];
    #pragma unroll
    for (int j = 0; j < 4; j++) {
        ur[j] = pk2(0.5f * Wih[(0 + u0) * 4 + j], 0.5f * Wih[(1 + u0) * 4 + j]);
        uz[j] = pk2(0.5f * Wih[(4 + u0) * 4 + j], 0.5f * Wih[(5 + u0) * 4 + j]);
        un[j] = pk2(Wih[(8 + u0) * 4 + j],        Wih[(9 + u0) * 4 + j]);
    }
    const f2 br  = pk2(0.5f * (bih[0 + u0] + bhh[0 + u0]),
                       0.5f * (bih[1 + u0] + bhh[1 + u0]));
    const f2 bz  = pk2(0.5f * (bih[4 + u0] + bhh[4 + u0]),
                       0.5f * (bih[5 + u0] + bhh[5 + u0]));
    const f2 bxn = pk2(bih[8 + u0], bih[9 + u0]);
    const f2 bhn = pk2(0.5f * bhh[8 + u0], 0.5f * bhh[9 + u0]);

    const char* pe = (const char*)g_e;
    uint32_t*   hp = (uint32_t*)g_h16[dir];

    int segstart = seg * SEGL_DIR;
    int tstart   = seg ? segstart - W_DIR : 0;
    int nsteps   = seg ? SEGL_DIR + W_DIR : SEGL_DIR;

    auto slot = [&](int st, int k, int c) -> uint32_t {
        return sbase + (uint32_t)(((st * 4 + k) * 16 + c) * 16);
    };
    int k0 = lane >> 4;                          // this lane loads steps k0, k0+2
    auto issue = [&](int c) {
        int st = c & (DSTAGES - 1);
        #pragma unroll
        for (int kk = 0; kk < 2; kk++) {
            int k = k0 + 2 * kk;
            int t = tstart + 4 * c + k;
            int tq = dir ? (Tn - 1 - t) : t;
            cpa16(slot(st, k, ch), pe + ((size_t)tq * Bn + row) * 16);
        }
    };

    issue(0); cpa_commit();
    issue(1); cpa_commit();
    issue(2); cpa_commit();

    float ha = 0.f, hb = 0.f;

    const int NC = nsteps / 4;
    for (int c = 0; c < NC; c++) {
        if (c + 3 < NC) issue(c + 3);
        cpa_commit();
        cpa_wait<3>();
        int st = c & (DSTAGES - 1);
        #pragma unroll
        for (int k = 0; k < 4; k++) {
            float pa = __shfl_xor_sync(0xffffffffu, ha, 16);
            float pb = __shfl_xor_sync(0xffffffffu, hb, 16);

            float4 ev = *(const float4*)(sbuf + (slot(st, k, ch) - sb0));
            f2 e0 = pk2(ev.x, ev.x), e1 = pk2(ev.y, ev.y);
            f2 e2 = pk2(ev.z, ev.z), e3 = pk2(ev.w, ev.w);

            // xi parts (independent of h; overlaps shfl latency)
            f2 ar = fma2(ur[0], e0, br);  ar = fma2(ur[1], e1, ar);
            ar = fma2(ur[2], e2, ar);     ar = fma2(ur[3], e3, ar);
            f2 az = fma2(uz[0], e0, bz);  az = fma2(uz[1], e1, az);
            az = fma2(uz[2], e2, az);     az = fma2(uz[3], e3, az);
            f2 xn = fma2(un[0], e0, bxn); xn = fma2(un[1], e1, xn);
            xn = fma2(un[2], e2, xn);     xn = fma2(un[3], e3, xn);

            f2 q0 = pk2(ha, ha), q1 = pk2(hb, hb);
            ar = fma2(wr[0], q0, ar); ar = fma2(wr[1], q1, ar);
            az = fma2(wz[0], q0, az); az = fma2(wz[1], q1, az);
            f2 an = fma2(wn[0], q0, bhn); an = fma2(wn[1], q1, an);

            f2 q2 = pk2(pa, pa), q3 = pk2(pb, pb);
            ar = fma2(wr[2], q2, ar); ar = fma2(wr[3], q3, ar);
            az = fma2(wz[2], q2, az); az = fma2(wz[3], q3, az);
            an = fma2(wn[2], q2, an); an = fma2(wn[3], q3, an);

            float a0, a1; upk2(ar, a0, a1);
            float tr0 = tanhap(a0), tr1 = tanhap(a1);
            float c0, c1; upk2(az, c0, c1);
            float z0 = fmaf(0.5f, tanhap(c0), 0.5f);
            float z1 = fmaf(0.5f, tanhap(c1), 0.5f);
            float g0, g1; upk2(an, g0, g1);              // 0.5*hn
            float x0, x1; upk2(xn, x0, x1);

            float n0 = tanhap(fmaf(tr0, g0, x0 + g0));
            float n1 = tanhap(fmaf(tr1, g1, x1 + g1));

            ha = fmaf(z0, ha - n0, n0);
            hb = fmaf(z1, hb - n1, n1);

            int t = tstart + 4 * c + k;
            if (t >= segstart) {
                int tt = dir ? (Tn - 1 - t) : t;
                hp[(size_t)(tt * Bn + row) * 2 + half] = pkh(ha, hb);
            }
        }
    }
}

// ---------------------------------------------------------------------------
// Kernel 2: segmented output GRU (H=1), fused 8-wide projection from fp16 h.
#define S_OUT 16
#define W_OUT 128
#define SEGL_OUT (Tn / S_OUT)        // 128
#define OSTAGES 4
#define OCK 8
__global__ void __launch_bounds__(32, 1)
k_out(const float* __restrict__ WihO, const float* __restrict__ WhhO,
      const float* __restrict__ bihO, const float* __restrict__ bhhO,
      float* __restrict__ out) {
    __shared__ char sbuf[OSTAGES * OCK * 2 * 32 * 8];   // 16 KB
    uint32_t sbase = s2u(sbuf);

    int lane = threadIdx.x;
    int rowseg = blockIdx.x * 32 + lane;         // seg*2048 + row
    int seg = rowseg >> 11;                      // warp-uniform
    int row = rowseg & (Bn - 1);

    float wr[8], wz[8], wn[8];
    #pragma unroll
    for (int j = 0; j < 8; j++) {
        wr[j] = 0.5f * WihO[0 * 8 + j];
        wz[j] = 0.5f * WihO[1 * 8 + j];
        wn[j] = WihO[2 * 8 + j];
    }
    float cr = 0.5f * (bihO[0] + bhhO[0]);
    float cz = 0.5f * (bihO[1] + bhhO[1]);
    float cn = bihO[2];
    float wrh = 0.5f * WhhO[0], wzh = 0.5f * WhhO[1];
    float whn = 0.5f * WhhO[2], bhn = 0.5f * bhhO[2];
    float h = 0.f;

    int segstart = seg * SEGL_OUT;
    int tstart   = seg ? segstart - W_OUT : 0;
    int nsteps   = seg ? SEGL_OUT + W_OUT : SEGL_OUT;

    auto slot = [&](int st, int k, int a) -> uint32_t {
        return sbase + (uint32_t)((((st * OCK + k) * 2 + a) * 32 + lane) * 8);
    };
    auto issue = [&](int c) {
        int st = c & (OSTAGES - 1);
        #pragma unroll
        for (int k = 0; k < OCK; k++) {
            int ix = (tstart + OCK * c + k) * Bn + row;
            cpa8(slot(st, k, 0), &g_h16[0][ix]);
            cpa8(slot(st, k, 1), &g_h16[1][ix]);
        }
    };

    issue(0); cpa_commit();
    issue(1); cpa_commit();
    issue(2); cpa_commit();

    const int NC = nsteps / OCK;
    float4* outv = (float4*)out;
    for (int c = 0; c < NC; c++) {
        if (c + 3 < NC) issue(c + 3);
        cpa_commit();
        cpa_wait<3>();
        int st = c & (OSTAGES - 1);
        int t0 = tstart + OCK * c;
        float o[OCK];
        #pragma unroll
        for (int k = 0; k < OCK; k++) {
            uint2 hf = *(const uint2*)(sbuf + (slot(st, k, 0) - sbase));
            uint2 hg = *(const uint2*)(sbuf + (slot(st, k, 1) - sbase));
            float in[8];
            upk2(h2f2(hf.x), in[0], in[1]);
            upk2(h2f2(hf.y), in[2], in[3]);
            upk2(h2f2(hg.x), in[4], in[5]);
            upk2(h2f2(hg.y), in[6], in[7]);
            float sr = cr, sz = cz, sx = cn;
            #pragma unroll
            for (int j = 0; j < 8; j++) {
                sr = fmaf(wr[j], in[j], sr);
                sz = fmaf(wz[j], in[j], sz);
                sx = fmaf(wn[j], in[j], sx);
            }
            float tr = tanhap(fmaf(wrh, h, sr));
            float z  = fmaf(0.5f, tanhap(fmaf(wzh, h, sz)), 0.5f);
            float g  = fmaf(whn, h, bhn);
            float n  = tanhap(fmaf(tr, g, sx + g));
            h = fmaf(z, h - n, n);
            o[k] = fmaf(0.5f, tanhap(0.5f * h), 0.5f);
        }
        if (t0 >= segstart) {
            #pragma unroll
            for (int q = 0; q < OCK / 4; q++)
                outv[(size_t)row * (Tn / 4) + (t0 >> 2) + q] =
                    make_float4(o[4 * q], o[4 * q + 1], o[4 * q + 2], o[4 * q + 3]);
        }
    }
}

// ---------------------------------------------------------------------------
extern "C" void kernel_launch(void* const* d_in, const int* in_sizes, int n_in,
                              void* d_out, int out_size) {
    const void*  x    = d_in[0];
    const float* emb  = (const float*)d_in[1];
    const float* WihF = (const float*)d_in[2];
    const float* WhhF = (const float*)d_in[3];
    const float* bihF = (const float*)d_in[4];
    const float* bhhF = (const float*)d_in[5];
    const float* WihB = (const float*)d_in[6];
    const float* WhhB = (const float*)d_in[7];
    const float* bihB = (const float*)d_in[8];
    const float* bhhB = (const float*)d_in[9];
    const float* WihO = (const float*)d_in[10];
    const float* WhhO = (const float*)d_in[11];
    const float* bihO = (const float*)d_in[12];
    const float* bhhO = (const float*)d_in[13];

    k_detect<<<1, 32>>>((const unsigned int*)x);
    k_xi<<<2048, 256>>>(x, emb);
    k_dirs<<<(2 * Bn * S_DIR) / 32, 64>>>(WhhF, bhhF, WhhB, bhhB,
                                          WihF, bihF, WihB, bihB);
    k_out<<<(Bn * S_OUT) / 32, 32>>>(WihO, WhhO, bihO, bhhO, (float*)d_out);
}

// round 12
// speedup vs baseline: 5.5216x; 1.1134x over previous
#include <cuda_runtime.h>
#include <cuda_fp16.h>
#include <cstdint>

#define Bn 2048
#define Tn 2048
#define TB (Tn * Bn)

typedef unsigned long long f2;

// Static device scratch (no runtime allocations allowed)
__device__ float4 g_e[TB];        // transposed fp32 embedding [t*Bn+b] (67MB)
__device__ uint2  g_h16[2][TB];   // fp16 hidden {h2(h0,h1), h2(h2,h3)} per dir
__device__ int    g_is64;

static __device__ __forceinline__ f2 pk2(float a, float b) {
    f2 r; asm("mov.b64 %0,{%1,%2};" : "=l"(r) : "f"(a), "f"(b)); return r;
}
static __device__ __forceinline__ void upk2(f2 v, float& a, float& b) {
    asm("mov.b64 {%0,%1},%2;" : "=f"(a), "=f"(b) : "l"(v));
}
static __device__ __forceinline__ f2 fma2(f2 a, f2 b, f2 c) {
    f2 r; asm("fma.rn.f32x2 %0,%1,%2,%3;" : "=l"(r) : "l"(a), "l"(b), "l"(c)); return r;
}
static __device__ __forceinline__ float tanhap(float x) {
    float r; asm("tanh.approx.f32 %0,%1;" : "=f"(r) : "f"(x)); return r;
}
static __device__ __forceinline__ uint32_t pkh(float a, float b) {
    __half2 h = __floats2half2_rn(a, b);
    return *reinterpret_cast<uint32_t*>(&h);
}
static __device__ __forceinline__ f2 h2f2(uint32_t v) {
    __half2 h = *reinterpret_cast<__half2*>(&v);
    float2 f = __half22float2(h);
    return pk2(f.x, f.y);
}
static __device__ __forceinline__ uint32_t s2u(const void* p) {
    uint32_t a;
    asm("{ .reg .u64 t; cvta.to.shared.u64 t, %1; cvt.u32.u64 %0, t; }" : "=r"(a) : "l"(p));
    return a;
}
static __device__ __forceinline__ void cpa16(uint32_t s, const void* g) {
    asm volatile("cp.async.ca.shared.global [%0], [%1], 16;" :: "r"(s), "l"(g) : "memory");
}
static __device__ __forceinline__ void cpa8(uint32_t s, const void* g) {
    asm volatile("cp.async.ca.shared.global [%0], [%1], 8;" :: "r"(s), "l"(g) : "memory");
}
static __device__ __forceinline__ void cpa_commit() {
    asm volatile("cp.async.commit_group;" ::: "memory");
}
template <int N> static __device__ __forceinline__ void cpa_wait() {
    asm volatile("cp.async.wait_group %0;" :: "n"(N) : "memory");
}

// ---------------------------------------------------------------------------
__global__ void k_detect(const unsigned int* xw) {
    if (threadIdx.x == 0 && blockIdx.x == 0) {
        int all0 = 1;
        for (int i = 0; i < 64; i++)
            if (xw[2 * i + 1] != 0u) { all0 = 0; break; }
        g_is64 = all0;
    }
}

// ---------------------------------------------------------------------------
// Transposed embedding: e[t*Bn+b] = emb[x[b][t]] (fp32 float4).
__global__ void k_xi(const void* __restrict__ xv, const float* __restrict__ emb) {
    int bt  = blockIdx.x;                 // 2048 blocks
    int b0  = (bt & 7) * 256;
    int t0  = (bt >> 3) * 8;
    int b   = b0 + threadIdx.x;

    int tok[8];
    if (g_is64) {
        const int4* p = (const int4*)((const long long*)xv + (size_t)b * Tn + t0);
        int4 a = p[0], c = p[1], d = p[2], e = p[3];
        tok[0] = a.x; tok[1] = a.z; tok[2] = c.x; tok[3] = c.z;
        tok[4] = d.x; tok[5] = d.z; tok[6] = e.x; tok[7] = e.z;
    } else {
        const int4* p = (const int4*)((const int*)xv + (size_t)b * Tn + t0);
        int4 a = p[0], c = p[1];
        tok[0] = a.x; tok[1] = a.y; tok[2] = a.z; tok[3] = a.w;
        tok[4] = c.x; tok[5] = c.y; tok[6] = c.z; tok[7] = c.w;
    }
    #pragma unroll
    for (int k = 0; k < 8; k++) {
        float4 e = *(const float4*)&emb[(size_t)tok[k] * 4];
        g_e[(size_t)(t0 + k) * Bn + b] = e;
    }
}

// ---------------------------------------------------------------------------
// Kernel 1: segmented fwd+bwd GRU chains; chain split across lane pair
// (l, l+16). xi = Wih*e + bias recomputed in-register from streamed e.
#define S_DIR 8
#define W_DIR 64
#define SEGL_DIR (Tn / S_DIR)        // 256
#define DSTAGES 4
#define WARP_SMEM (DSTAGES * 4 * 16 * 16)   // 4KB per warp
__global__ void __launch_bounds__(64, 1)
k_dirs(const float* __restrict__ WhhF, const float* __restrict__ bhhF,
       const float* __restrict__ WhhB, const float* __restrict__ bhhB,
       const float* __restrict__ WihF, const float* __restrict__ bihF,
       const float* __restrict__ WihB, const float* __restrict__ bihB) {
    __shared__ char sbuf[2 * WARP_SMEM];   // 8 KB
    uint32_t sb0 = s2u(sbuf);
    uint32_t sbase = sb0 + (uint32_t)(threadIdx.x >> 5) * WARP_SMEM;

    int lane = threadIdx.x & 31;
    int half = lane >> 4;                        // 0: units 0,1 ; 1: units 2,3
    int ch   = lane & 15;
    int gw   = blockIdx.x * 2 + (threadIdx.x >> 5);
    int chainseg = gw * 16 + ch;                 // seg*4096 + chain
    int seg   = chainseg >> 12;                  // warp-uniform
    int chain = chainseg & 4095;
    int dir   = chain >> 11;                     // warp-uniform
    int row   = chain & (Bn - 1);
    int u0    = 2 * half;

    const float* Whh = dir ? WhhB : WhhF;
    const float* bhh = dir ? bhhB : bhhF;
    const float* Wih = dir ? WihB : WihF;
    const float* bih = dir ? bihB : bihF;

    f2 wr[4], wz[4], wn[4];
    #pragma unroll
    for (int j = 0; j < 4; j++) {
        int gj = (j + u0) & 3;
        wr[j] = pk2(0.5f * Whh[(0 + u0) * 4 + gj], 0.5f * Whh[(1 + u0) * 4 + gj]);
        wz[j] = pk2(0.5f * Whh[(4 + u0) * 4 + gj], 0.5f * Whh[(5 + u0) * 4 + gj]);
        wn[j] = pk2(0.5f * Whh[(8 + u0) * 4 + gj], 0.5f * Whh[(9 + u0) * 4 + gj]);
    }
    f2 ur[4], uz[4], un[4];
    #pragma unroll
    for (int j = 0; j < 4; j++) {
        ur[j] = pk2(0.5f * Wih[(0 + u0) * 4 + j], 0.5f * Wih[(1 + u0) * 4 + j]);
        uz[j] = pk2(0.5f * Wih[(4 + u0) * 4 + j], 0.5f * Wih[(5 + u0) * 4 + j]);
        un[j] = pk2(Wih[(8 + u0) * 4 + j],        Wih[(9 + u0) * 4 + j]);
    }
    const f2 br  = pk2(0.5f * (bih[0 + u0] + bhh[0 + u0]),
                       0.5f * (bih[1 + u0] + bhh[1 + u0]));
    const f2 bz  = pk2(0.5f * (bih[4 + u0] + bhh[4 + u0]),
                       0.5f * (bih[5 + u0] + bhh[5 + u0]));
    const f2 bxn = pk2(bih[8 + u0], bih[9 + u0]);
    const f2 bhn = pk2(0.5f * bhh[8 + u0], 0.5f * bhh[9 + u0]);

    const char* pe = (const char*)g_e;
    uint32_t*   hp = (uint32_t*)g_h16[dir];

    int segstart = seg * SEGL_DIR;
    int tstart   = seg ? segstart - W_DIR : 0;
    int nsteps   = seg ? SEGL_DIR + W_DIR : SEGL_DIR;

    auto slot = [&](int st, int k, int c) -> uint32_t {
        return sbase + (uint32_t)(((st * 4 + k) * 16 + c) * 16);
    };
    int k0 = lane >> 4;
    auto issue = [&](int c) {
        int st = c & (DSTAGES - 1);
        #pragma unroll
        for (int kk = 0; kk < 2; kk++) {
            int k = k0 + 2 * kk;
            int t = tstart + 4 * c + k;
            int tq = dir ? (Tn - 1 - t) : t;
            cpa16(slot(st, k, ch), pe + ((size_t)tq * Bn + row) * 16);
        }
    };

    issue(0); cpa_commit();
    issue(1); cpa_commit();
    issue(2); cpa_commit();

    float ha = 0.f, hb = 0.f;

    const int NC = nsteps / 4;
    for (int c = 0; c < NC; c++) {
        if (c + 3 < NC) issue(c + 3);
        cpa_commit();
        cpa_wait<3>();
        int st = c & (DSTAGES - 1);
        #pragma unroll
        for (int k = 0; k < 4; k++) {
            float pa = __shfl_xor_sync(0xffffffffu, ha, 16);
            float pb = __shfl_xor_sync(0xffffffffu, hb, 16);

            float4 ev = *(const float4*)(sbuf + (slot(st, k, ch) - sb0));
            f2 e0 = pk2(ev.x, ev.x), e1 = pk2(ev.y, ev.y);
            f2 e2 = pk2(ev.z, ev.z), e3 = pk2(ev.w, ev.w);

            f2 ar = fma2(ur[0], e0, br);  ar = fma2(ur[1], e1, ar);
            ar = fma2(ur[2], e2, ar);     ar = fma2(ur[3], e3, ar);
            f2 az = fma2(uz[0], e0, bz);  az = fma2(uz[1], e1, az);
            az = fma2(uz[2], e2, az);     az = fma2(uz[3], e3, az);
            f2 xn = fma2(un[0], e0, bxn); xn = fma2(un[1], e1, xn);
            xn = fma2(un[2], e2, xn);     xn = fma2(un[3], e3, xn);

            f2 q0 = pk2(ha, ha), q1 = pk2(hb, hb);
            ar = fma2(wr[0], q0, ar); ar = fma2(wr[1], q1, ar);
            az = fma2(wz[0], q0, az); az = fma2(wz[1], q1, az);
            f2 an = fma2(wn[0], q0, bhn); an = fma2(wn[1], q1, an);

            f2 q2 = pk2(pa, pa), q3 = pk2(pb, pb);
            ar = fma2(wr[2], q2, ar); ar = fma2(wr[3], q3, ar);
            az = fma2(wz[2], q2, az); az = fma2(wz[3], q3, az);
            an = fma2(wn[2], q2, an); an = fma2(wn[3], q3, an);

            float a0, a1; upk2(ar, a0, a1);
            float tr0 = tanhap(a0), tr1 = tanhap(a1);
            float c0, c1; upk2(az, c0, c1);
            float z0 = fmaf(0.5f, tanhap(c0), 0.5f);
            float z1 = fmaf(0.5f, tanhap(c1), 0.5f);
            float g0, g1; upk2(an, g0, g1);              // 0.5*hn
            float x0, x1; upk2(xn, x0, x1);

            float n0 = tanhap(fmaf(tr0, g0, x0 + g0));
            float n1 = tanhap(fmaf(tr1, g1, x1 + g1));

            ha = fmaf(z0, ha - n0, n0);
            hb = fmaf(z1, hb - n1, n1);

            int t = tstart + 4 * c + k;
            if (t >= segstart) {
                int tt = dir ? (Tn - 1 - t) : t;
                hp[(size_t)(tt * Bn + row) * 2 + half] = pkh(ha, hb);
            }
        }
    }
}

// ---------------------------------------------------------------------------
// Kernel 2: segmented output GRU (H=1), fused 8-wide projection from fp16 h.
#define S_OUT 32
#define W_OUT 64
#define SEGL_OUT (Tn / S_OUT)        // 64
#define OSTAGES 4
#define OCK 8
__global__ void __launch_bounds__(32, 1)
k_out(const float* __restrict__ WihO, const float* __restrict__ WhhO,
      const float* __restrict__ bihO, const float* __restrict__ bhhO,
      float* __restrict__ out) {
    __shared__ char sbuf[OSTAGES * OCK * 2 * 32 * 8];   // 16 KB
    uint32_t sbase = s2u(sbuf);

    int lane = threadIdx.x;
    int rowseg = blockIdx.x * 32 + lane;         // seg*2048 + row
    int seg = rowseg >> 11;                      // warp-uniform
    int row = rowseg & (Bn - 1);

    float wr[8], wz[8], wn[8];
    #pragma unroll
    for (int j = 0; j < 8; j++) {
        wr[j] = 0.5f * WihO[0 * 8 + j];
        wz[j] = 0.5f * WihO[1 * 8 + j];
        wn[j] = WihO[2 * 8 + j];
    }
    float cr = 0.5f * (bihO[0] + bhhO[0]);
    float cz = 0.5f * (bihO[1] + bhhO[1]);
    float cn = bihO[2];
    float wrh = 0.5f * WhhO[0], wzh = 0.5f * WhhO[1];
    float whn = 0.5f * WhhO[2], bhn = 0.5f * bhhO[2];
    float h = 0.f;

    int segstart = seg * SEGL_OUT;
    int tstart   = seg ? segstart - W_OUT : 0;
    int nsteps   = seg ? SEGL_OUT + W_OUT : SEGL_OUT;

    auto slot = [&](int st, int k, int a) -> uint32_t {
        return sbase + (uint32_t)((((st * OCK + k) * 2 + a) * 32 + lane) * 8);
    };
    auto issue = [&](int c) {
        int st = c & (OSTAGES - 1);
        #pragma unroll
        for (int k = 0; k < OCK; k++) {
            int ix = (tstart + OCK * c + k) * Bn + row;
            cpa8(slot(st, k, 0), &g_h16[0][ix]);
            cpa8(slot(st, k, 1), &g_h16[1][ix]);
        }
    };

    issue(0); cpa_commit();
    issue(1); cpa_commit();
    issue(2); cpa_commit();

    const int NC = nsteps / OCK;
    float4* outv = (float4*)out;
    for (int c = 0; c < NC; c++) {
        if (c + 3 < NC) issue(c + 3);
        cpa_commit();
        cpa_wait<3>();
        int st = c & (OSTAGES - 1);
        int t0 = tstart + OCK * c;
        float o[OCK];
        #pragma unroll
        for (int k = 0; k < OCK; k++) {
            uint2 hf = *(const uint2*)(sbuf + (slot(st, k, 0) - sbase));
            uint2 hg = *(const uint2*)(sbuf + (slot(st, k, 1) - sbase));
            float in[8];
            upk2(h2f2(hf.x), in[0], in[1]);
            upk2(h2f2(hf.y), in[2], in[3]);
            upk2(h2f2(hg.x), in[4], in[5]);
            upk2(h2f2(hg.y), in[6], in[7]);
            float sr = cr, sz = cz, sx = cn;
            #pragma unroll
            for (int j = 0; j < 8; j++) {
                sr = fmaf(wr[j], in[j], sr);
                sz = fmaf(wz[j], in[j], sz);
                sx = fmaf(wn[j], in[j], sx);
            }
            float tr = tanhap(fmaf(wrh, h, sr));
            float z  = fmaf(0.5f, tanhap(fmaf(wzh, h, sz)), 0.5f);
            float g  = fmaf(whn, h, bhn);
            float n  = tanhap(fmaf(tr, g, sx + g));
            h = fmaf(z, h - n, n);
            o[k] = fmaf(0.5f, tanhap(0.5f * h), 0.5f);
        }
        if (t0 >= segstart) {
            #pragma unroll
            for (int q = 0; q < OCK / 4; q++)
                outv[(size_t)row * (Tn / 4) + (t0 >> 2) + q] =
                    make_float4(o[4 * q], o[4 * q + 1], o[4 * q + 2], o[4 * q + 3]);
        }
    }
}

// ---------------------------------------------------------------------------
extern "C" void kernel_launch(void* const* d_in, const int* in_sizes, int n_in,
                              void* d_out, int out_size) {
    const void*  x    = d_in[0];
    const float* emb  = (const float*)d_in[1];
    const float* WihF = (const float*)d_in[2];
    const float* WhhF = (const float*)d_in[3];
    const float* bihF = (const float*)d_in[4];
    const float* bhhF = (const float*)d_in[5];
    const float* WihB = (const float*)d_in[6];
    const float* WhhB = (const float*)d_in[7];
    const float* bihB = (const float*)d_in[8];
    const float* bhhB = (const float*)d_in[9];
    const float* WihO = (const float*)d_in[10];
    const float* WhhO = (const float*)d_in[11];
    const float* bihO = (const float*)d_in[12];
    const float* bhhO = (const float*)d_in[13];

    k_detect<<<1, 32>>>((const unsigned int*)x);
    k_xi<<<2048, 256>>>(x, emb);
    k_dirs<<<(2 * Bn * S_DIR) / 32, 64>>>(WhhF, bhhF, WhhB, bhhB,
                                          WihF, bihF, WihB, bihB);
    k_out<<<(Bn * S_OUT) / 32, 32>>>(WihO, WhhO, bihO, bhhO, (float*)d_out);
}

// round 13
// speedup vs baseline: 5.6013x; 1.0144x over previous
#include <cuda_runtime.h>
#include <cuda_fp16.h>
#include <cstdint>

#define Bn 2048
#define Tn 2048
#define TB (Tn * Bn)

typedef unsigned long long f2;

// Static device scratch (no runtime allocations allowed)
__device__ uint2  g_e16[TB];      // fp16 embedding {h2(e0,e1),h2(e2,e3)} [t*Bn+b] (33MB)
__device__ uint2  g_h16[2][TB];   // fp16 hidden {h2(h0,h1), h2(h2,h3)} per dir
__device__ int    g_is64;

static __device__ __forceinline__ f2 pk2(float a, float b) {
    f2 r; asm("mov.b64 %0,{%1,%2};" : "=l"(r) : "f"(a), "f"(b)); return r;
}
static __device__ __forceinline__ void upk2(f2 v, float& a, float& b) {
    asm("mov.b64 {%0,%1},%2;" : "=f"(a), "=f"(b) : "l"(v));
}
static __device__ __forceinline__ f2 fma2(f2 a, f2 b, f2 c) {
    f2 r; asm("fma.rn.f32x2 %0,%1,%2,%3;" : "=l"(r) : "l"(a), "l"(b), "l"(c)); return r;
}
static __device__ __forceinline__ float tanhap(float x) {
    float r; asm("tanh.approx.f32 %0,%1;" : "=f"(r) : "f"(x)); return r;
}
static __device__ __forceinline__ uint32_t pkh(float a, float b) {
    __half2 h = __floats2half2_rn(a, b);
    return *reinterpret_cast<uint32_t*>(&h);
}
static __device__ __forceinline__ f2 h2f2(uint32_t v) {
    __half2 h = *reinterpret_cast<__half2*>(&v);
    float2 f = __half22float2(h);
    return pk2(f.x, f.y);
}
static __device__ __forceinline__ uint32_t s2u(const void* p) {
    uint32_t a;
    asm("{ .reg .u64 t; cvta.to.shared.u64 t, %1; cvt.u32.u64 %0, t; }" : "=r"(a) : "l"(p));
    return a;
}
static __device__ __forceinline__ void cpa8(uint32_t s, const void* g) {
    asm volatile("cp.async.ca.shared.global [%0], [%1], 8;" :: "r"(s), "l"(g) : "memory");
}
static __device__ __forceinline__ void cpa_commit() {
    asm volatile("cp.async.commit_group;" ::: "memory");
}
template <int N> static __device__ __forceinline__ void cpa_wait() {
    asm volatile("cp.async.wait_group %0;" :: "n"(N) : "memory");
}

// ---------------------------------------------------------------------------
__global__ void k_detect(const unsigned int* xw) {
    if (threadIdx.x == 0 && blockIdx.x == 0) {
        int all0 = 1;
        for (int i = 0; i < 64; i++)
            if (xw[2 * i + 1] != 0u) { all0 = 0; break; }
        g_is64 = all0;
    }
}

// ---------------------------------------------------------------------------
// Transposed fp16 embedding: e16[t*Bn+b] = fp16(emb[x[b][t]]).
__global__ void k_xi(const void* __restrict__ xv, const float* __restrict__ emb) {
    int bt  = blockIdx.x;                 // 2048 blocks
    int b0  = (bt & 7) * 256;
    int t0  = (bt >> 3) * 8;
    int b   = b0 + threadIdx.x;

    int tok[8];
    if (g_is64) {
        const int4* p = (const int4*)((const long long*)xv + (size_t)b * Tn + t0);
        int4 a = p[0], c = p[1], d = p[2], e = p[3];
        tok[0] = a.x; tok[1] = a.z; tok[2] = c.x; tok[3] = c.z;
        tok[4] = d.x; tok[5] = d.z; tok[6] = e.x; tok[7] = e.z;
    } else {
        const int4* p = (const int4*)((const int*)xv + (size_t)b * Tn + t0);
        int4 a = p[0], c = p[1];
        tok[0] = a.x; tok[1] = a.y; tok[2] = a.z; tok[3] = a.w;
        tok[4] = c.x; tok[5] = c.y; tok[6] = c.z; tok[7] = c.w;
    }
    #pragma unroll
    for (int k = 0; k < 8; k++) {
        float4 e = *(const float4*)&emb[(size_t)tok[k] * 4];
        g_e16[(size_t)(t0 + k) * Bn + b] = make_uint2(pkh(e.x, e.y), pkh(e.z, e.w));
    }
}

// ---------------------------------------------------------------------------
// Kernel 1: segmented fwd+bwd GRU chains; chain split across lane pair
// (l, l+16). xi = Wih*e + bias recomputed in-register from streamed fp16 e.
#define S_DIR 8
#define W_DIR 64
#define SEGL_DIR (Tn / S_DIR)        // 256
#define DSTAGES 4
#define WARP_SMEM (DSTAGES * 4 * 16 * 8)   // 2KB per warp
__global__ void __launch_bounds__(64, 1)
k_dirs(const float* __restrict__ WhhF, const float* __restrict__ bhhF,
       const float* __restrict__ WhhB, const float* __restrict__ bhhB,
       const float* __restrict__ WihF, const float* __restrict__ bihF,
       const float* __restrict__ WihB, const float* __restrict__ bihB) {
    __shared__ char sbuf[2 * WARP_SMEM];   // 4 KB
    uint32_t sb0 = s2u(sbuf);
    uint32_t sbase = sb0 + (uint32_t)(threadIdx.x >> 5) * WARP_SMEM;

    int lane = threadIdx.x & 31;
    int half = lane >> 4;                        // 0: units 0,1 ; 1: units 2,3
    int ch   = lane & 15;
    int gw   = blockIdx.x * 2 + (threadIdx.x >> 5);
    int chainseg = gw * 16 + ch;                 // seg*4096 + chain
    int seg   = chainseg >> 12;                  // warp-uniform
    int chain = chainseg & 4095;
    int dir   = chain >> 11;                     // warp-uniform
    int row   = chain & (Bn - 1);
    int u0    = 2 * half;

    const float* Whh = dir ? WhhB : WhhF;
    const float* bhh = dir ? bhhB : bhhF;
    const float* Wih = dir ? WihB : WihF;
    const float* bih = dir ? bihB : bihF;

    f2 wr[4], wz[4], wn[4];
    #pragma unroll
    for (int j = 0; j < 4; j++) {
        int gj = (j + u0) & 3;
        wr[j] = pk2(0.5f * Whh[(0 + u0) * 4 + gj], 0.5f * Whh[(1 + u0) * 4 + gj]);
        wz[j] = pk2(0.5f * Whh[(4 + u0) * 4 + gj], 0.5f * Whh[(5 + u0) * 4 + gj]);
        wn[j] = pk2(0.5f * Whh[(8 + u0) * 4 + gj], 0.5f * Whh[(9 + u0) * 4 + gj]);
    }
    f2 ur[4], uz[4], un[4];
    #pragma unroll
    for (int j = 0; j < 4; j++) {
        ur[j] = pk2(0.5f * Wih[(0 + u0) * 4 + j], 0.5f * Wih[(1 + u0) * 4 + j]);
        uz[j] = pk2(0.5f * Wih[(4 + u0) * 4 + j], 0.5f * Wih[(5 + u0) * 4 + j]);
        un[j] = pk2(Wih[(8 + u0) * 4 + j],        Wih[(9 + u0) * 4 + j]);
    }
    const f2 br  = pk2(0.5f * (bih[0 + u0] + bhh[0 + u0]),
                       0.5f * (bih[1 + u0] + bhh[1 + u0]));
    const f2 bz  = pk2(0.5f * (bih[4 + u0] + bhh[4 + u0]),
                       0.5f * (bih[5 + u0] + bhh[5 + u0]));
    const f2 bxn = pk2(bih[8 + u0], bih[9 + u0]);
    const f2 bhn = pk2(0.5f * bhh[8 + u0], 0.5f * bhh[9 + u0]);

    const char* pe = (const char*)g_e16;
    uint32_t*   hp = (uint32_t*)g_h16[dir];

    int segstart = seg * SEGL_DIR;
    int tstart   = seg ? segstart - W_DIR : 0;
    int nsteps   = seg ? SEGL_DIR + W_DIR : SEGL_DIR;

    auto slot = [&](int st, int k, int c) -> uint32_t {
        return sbase + (uint32_t)(((st * 4 + k) * 16 + c) * 8);
    };
    int k0 = lane >> 4;
    auto issue = [&](int c) {
        int st = c & (DSTAGES - 1);
        #pragma unroll
        for (int kk = 0; kk < 2; kk++) {
            int k = k0 + 2 * kk;
            int t = tstart + 4 * c + k;
            int tq = dir ? (Tn - 1 - t) : t;
            cpa8(slot(st, k, ch), pe + ((size_t)tq * Bn + row) * 8);
        }
    };

    issue(0); cpa_commit();
    issue(1); cpa_commit();
    issue(2); cpa_commit();

    float ha = 0.f, hb = 0.f;

    const int NC = nsteps / 4;
    for (int c = 0; c < NC; c++) {
        if (c + 3 < NC) issue(c + 3);
        cpa_commit();
        cpa_wait<3>();
        int st = c & (DSTAGES - 1);
        #pragma unroll
        for (int k = 0; k < 4; k++) {
            float pa = __shfl_xor_sync(0xffffffffu, ha, 16);
            float pb = __shfl_xor_sync(0xffffffffu, hb, 16);

            uint2 eh = *(const uint2*)(sbuf + (slot(st, k, ch) - sb0));
            float ex, ey, ez, ew;
            upk2(h2f2(eh.x), ex, ey);
            upk2(h2f2(eh.y), ez, ew);
            f2 e0 = pk2(ex, ex), e1 = pk2(ey, ey);
            f2 e2 = pk2(ez, ez), e3 = pk2(ew, ew);

            f2 ar = fma2(ur[0], e0, br);  ar = fma2(ur[1], e1, ar);
            ar = fma2(ur[2], e2, ar);     ar = fma2(ur[3], e3, ar);
            f2 az = fma2(uz[0], e0, bz);  az = fma2(uz[1], e1, az);
            az = fma2(uz[2], e2, az);     az = fma2(uz[3], e3, az);
            f2 xn = fma2(un[0], e0, bxn); xn = fma2(un[1], e1, xn);
            xn = fma2(un[2], e2, xn);     xn = fma2(un[3], e3, xn);

            f2 q0 = pk2(ha, ha), q1 = pk2(hb, hb);
            ar = fma2(wr[0], q0, ar); ar = fma2(wr[1], q1, ar);
            az = fma2(wz[0], q0, az); az = fma2(wz[1], q1, az);
            f2 an = fma2(wn[0], q0, bhn); an = fma2(wn[1], q1, an);

            f2 q2 = pk2(pa, pa), q3 = pk2(pb, pb);
            ar = fma2(wr[2], q2, ar); ar = fma2(wr[3], q3, ar);
            az = fma2(wz[2], q2, az); az = fma2(wz[3], q3, az);
            an = fma2(wn[2], q2, an); an = fma2(wn[3], q3, an);

            float a0, a1; upk2(ar, a0, a1);
            float tr0 = tanhap(a0), tr1 = tanhap(a1);
            float c0, c1; upk2(az, c0, c1);
            float z0 = fmaf(0.5f, tanhap(c0), 0.5f);
            float z1 = fmaf(0.5f, tanhap(c1), 0.5f);
            float g0, g1; upk2(an, g0, g1);              // 0.5*hn
            float x0, x1; upk2(xn, x0, x1);

            float n0 = tanhap(fmaf(tr0, g0, x0 + g0));
            float n1 = tanhap(fmaf(tr1, g1, x1 + g1));

            ha = fmaf(z0, ha - n0, n0);
            hb = fmaf(z1, hb - n1, n1);

            int t = tstart + 4 * c + k;
            if (t >= segstart) {
                int tt = dir ? (Tn - 1 - t) : t;
                hp[(size_t)(tt * Bn + row) * 2 + half] = pkh(ha, hb);
            }
        }
    }
}

// ---------------------------------------------------------------------------
// Kernel 2: segmented output GRU (H=1), fused 8-wide projection from fp16 h.
#define S_OUT 32
#define W_OUT 64
#define SEGL_OUT (Tn / S_OUT)        // 64
#define OSTAGES 4
#define OCK 8
__global__ void __launch_bounds__(32, 1)
k_out(const float* __restrict__ WihO, const float* __restrict__ WhhO,
      const float* __restrict__ bihO, const float* __restrict__ bhhO,
      float* __restrict__ out) {
    __shared__ char sbuf[OSTAGES * OCK * 2 * 32 * 8];   // 16 KB
    uint32_t sbase = s2u(sbuf);

    int lane = threadIdx.x;
    int rowseg = blockIdx.x * 32 + lane;         // seg*2048 + row
    int seg = rowseg >> 11;                      // warp-uniform
    int row = rowseg & (Bn - 1);

    float wr[8], wz[8], wn[8];
    #pragma unroll
    for (int j = 0; j < 8; j++) {
        wr[j] = 0.5f * WihO[0 * 8 + j];
        wz[j] = 0.5f * WihO[1 * 8 + j];
        wn[j] = WihO[2 * 8 + j];
    }
    float cr = 0.5f * (bihO[0] + bhhO[0]);
    float cz = 0.5f * (bihO[1] + bhhO[1]);
    float cn = bihO[2];
    float wrh = 0.5f * WhhO[0], wzh = 0.5f * WhhO[1];
    float whn = 0.5f * WhhO[2], bhn = 0.5f * bhhO[2];
    float h = 0.f;

    int segstart = seg * SEGL_OUT;
    int tstart   = seg ? segstart - W_OUT : 0;
    int nsteps   = seg ? SEGL_OUT + W_OUT : SEGL_OUT;

    auto slot = [&](int st, int k, int a) -> uint32_t {
        return sbase + (uint32_t)((((st * OCK + k) * 2 + a) * 32 + lane) * 8);
    };
    auto issue = [&](int c) {
        int st = c & (OSTAGES - 1);
        #pragma unroll
        for (int k = 0; k < OCK; k++) {
            int ix = (tstart + OCK * c + k) * Bn + row;
            cpa8(slot(st, k, 0), &g_h16[0][ix]);
            cpa8(slot(st, k, 1), &g_h16[1][ix]);
        }
    };

    issue(0); cpa_commit();
    issue(1); cpa_commit();
    issue(2); cpa_commit();

    const int NC = nsteps / OCK;
    float4* outv = (float4*)out;
    for (int c = 0; c < NC; c++) {
        if (c + 3 < NC) issue(c + 3);
        cpa_commit();
        cpa_wait<3>();
        int st = c & (OSTAGES - 1);
        int t0 = tstart + OCK * c;
        float o[OCK];
        #pragma unroll
        for (int k = 0; k < OCK; k++) {
            uint2 hf = *(const uint2*)(sbuf + (slot(st, k, 0) - sbase));
            uint2 hg = *(const uint2*)(sbuf + (slot(st, k, 1) - sbase));
            float in[8];
            upk2(h2f2(hf.x), in[0], in[1]);
            upk2(h2f2(hf.y), in[2], in[3]);
            upk2(h2f2(hg.x), in[4], in[5]);
            upk2(h2f2(hg.y), in[6], in[7]);
            float sr = cr, sz = cz, sx = cn;
            #pragma unroll
            for (int j = 0; j < 8; j++) {
                sr = fmaf(wr[j], in[j], sr);
                sz = fmaf(wz[j], in[j], sz);
                sx = fmaf(wn[j], in[j], sx);
            }
            float tr = tanhap(fmaf(wrh, h, sr));
            float z  = fmaf(0.5f, tanhap(fmaf(wzh, h, sz)), 0.5f);
            float g  = fmaf(whn, h, bhn);
            float n  = tanhap(fmaf(tr, g, sx + g));
            h = fmaf(z, h - n, n);
            o[k] = fmaf(0.5f, tanhap(0.5f * h), 0.5f);
        }
        if (t0 >= segstart) {
            #pragma unroll
            for (int q = 0; q < OCK / 4; q++)
                outv[(size_t)row * (Tn / 4) + (t0 >> 2) + q] =
                    make_float4(o[4 * q], o[4 * q + 1], o[4 * q + 2], o[4 * q + 3]);
        }
    }
}

// ---------------------------------------------------------------------------
extern "C" void kernel_launch(void* const* d_in, const int* in_sizes, int n_in,
                              void* d_out, int out_size) {
    const void*  x    = d_in[0];
    const float* emb  = (const float*)d_in[1];
    const float* WihF = (const float*)d_in[2];
    const float* WhhF = (const float*)d_in[3];
    const float* bihF = (const float*)d_in[4];
    const float* bhhF = (const float*)d_in[5];
    const float* WihB = (const float*)d_in[6];
    const float* WhhB = (const float*)d_in[7];
    const float* bihB = (const float*)d_in[8];
    const float* bhhB = (const float*)d_in[9];
    const float* WihO = (const float*)d_in[10];
    const float* WhhO = (const float*)d_in[11];
    const float* bihO = (const float*)d_in[12];
    const float* bhhO = (const float*)d_in[13];

    k_detect<<<1, 32>>>((const unsigned int*)x);
    k_xi<<<2048, 256>>>(x, emb);
    k_dirs<<<(2 * Bn * S_DIR) / 32, 64>>>(WhhF, bhhF, WhhB, bhhB,
                                          WihF, bihF, WihB, bihB);
    k_out<<<(Bn * S_OUT) / 32, 32>>>(WihO, WhhO, bihO, bhhO, (float*)d_out);
}

// round 14
// speedup vs baseline: 5.9461x; 1.0616x over previous
#include <cuda_runtime.h>
#include <cuda_fp16.h>
#include <cstdint>

#define Bn 2048
#define Tn 2048
#define TB (Tn * Bn)

typedef unsigned long long f2;

// Static device scratch (no runtime allocations allowed)
__device__ uint2  g_e16[TB];      // fp16 embedding {h2(e0,e1),h2(e2,e3)} [t*Bn+b] (33MB)
__device__ uint2  g_h16[2][TB];   // fp16 hidden {h2(h0,h1), h2(h2,h3)} per dir
__device__ int    g_is64;

static __device__ __forceinline__ f2 pk2(float a, float b) {
    f2 r; asm("mov.b64 %0,{%1,%2};" : "=l"(r) : "f"(a), "f"(b)); return r;
}
static __device__ __forceinline__ void upk2(f2 v, float& a, float& b) {
    asm("mov.b64 {%0,%1},%2;" : "=f"(a), "=f"(b) : "l"(v));
}
static __device__ __forceinline__ f2 fma2(f2 a, f2 b, f2 c) {
    f2 r; asm("fma.rn.f32x2 %0,%1,%2,%3;" : "=l"(r) : "l"(a), "l"(b), "l"(c)); return r;
}
static __device__ __forceinline__ float tanhap(float x) {
    float r; asm("tanh.approx.f32 %0,%1;" : "=f"(r) : "f"(x)); return r;
}
static __device__ __forceinline__ uint32_t pkh(float a, float b) {
    __half2 h = __floats2half2_rn(a, b);
    return *reinterpret_cast<uint32_t*>(&h);
}
static __device__ __forceinline__ f2 h2f2(uint32_t v) {
    __half2 h = *reinterpret_cast<__half2*>(&v);
    float2 f = __half22float2(h);
    return pk2(f.x, f.y);
}
static __device__ __forceinline__ uint32_t s2u(const void* p) {
    uint32_t a;
    asm("{ .reg .u64 t; cvta.to.shared.u64 t, %1; cvt.u32.u64 %0, t; }" : "=r"(a) : "l"(p));
    return a;
}
static __device__ __forceinline__ void cpa8(uint32_t s, const void* g) {
    asm volatile("cp.async.ca.shared.global [%0], [%1], 8;" :: "r"(s), "l"(g) : "memory");
}
static __device__ __forceinline__ void cpa_commit() {
    asm volatile("cp.async.commit_group;" ::: "memory");
}
template <int N> static __device__ __forceinline__ void cpa_wait() {
    asm volatile("cp.async.wait_group %0;" :: "n"(N) : "memory");
}

// ---------------------------------------------------------------------------
__global__ void k_detect(const unsigned int* xw) {
    if (threadIdx.x == 0 && blockIdx.x == 0) {
        int all0 = 1;
        for (int i = 0; i < 64; i++)
            if (xw[2 * i + 1] != 0u) { all0 = 0; break; }
        g_is64 = all0;
    }
}

// ---------------------------------------------------------------------------
// Transposed fp16 embedding: e16[t*Bn+b] = fp16(emb[x[b][t]]).
__global__ void k_xi(const void* __restrict__ xv, const float* __restrict__ emb) {
    int bt  = blockIdx.x;                 // 2048 blocks
    int b0  = (bt & 7) * 256;
    int t0  = (bt >> 3) * 8;
    int b   = b0 + threadIdx.x;

    int tok[8];
    if (g_is64) {
        const int4* p = (const int4*)((const long long*)xv + (size_t)b * Tn + t0);
        int4 a = p[0], c = p[1], d = p[2], e = p[3];
        tok[0] = a.x; tok[1] = a.z; tok[2] = c.x; tok[3] = c.z;
        tok[4] = d.x; tok[5] = d.z; tok[6] = e.x; tok[7] = e.z;
    } else {
        const int4* p = (const int4*)((const int*)xv + (size_t)b * Tn + t0);
        int4 a = p[0], c = p[1];
        tok[0] = a.x; tok[1] = a.y; tok[2] = a.z; tok[3] = a.w;
        tok[4] = c.x; tok[5] = c.y; tok[6] = c.z; tok[7] = c.w;
    }
    #pragma unroll
    for (int k = 0; k < 8; k++) {
        float4 e = *(const float4*)&emb[(size_t)tok[k] * 4];
        g_e16[(size_t)(t0 + k) * Bn + b] = make_uint2(pkh(e.x, e.y), pkh(e.z, e.w));
    }
}

// ---------------------------------------------------------------------------
// Kernel 1: segmented fwd+bwd GRU chains; chain split across lane pair
// (l, l+16). xi = Wih*e + bias recomputed in-register from streamed fp16 e.
#define S_DIR 16
#define W_DIR 48
#define SEGL_DIR (Tn / S_DIR)        // 128
#define DSTAGES 4
#define WARP_SMEM (DSTAGES * 4 * 16 * 8)   // 2KB per warp
__global__ void __launch_bounds__(64, 1)
k_dirs(const float* __restrict__ WhhF, const float* __restrict__ bhhF,
       const float* __restrict__ WhhB, const float* __restrict__ bhhB,
       const float* __restrict__ WihF, const float* __restrict__ bihF,
       const float* __restrict__ WihB, const float* __restrict__ bihB) {
    __shared__ char sbuf[2 * WARP_SMEM];   // 4 KB
    uint32_t sb0 = s2u(sbuf);
    uint32_t sbase = sb0 + (uint32_t)(threadIdx.x >> 5) * WARP_SMEM;

    int lane = threadIdx.x & 31;
    int half = lane >> 4;                        // 0: units 0,1 ; 1: units 2,3
    int ch   = lane & 15;
    int gw   = blockIdx.x * 2 + (threadIdx.x >> 5);
    int chainseg = gw * 16 + ch;                 // seg*4096 + chain
    int seg   = chainseg >> 12;                  // warp-uniform
    int chain = chainseg & 4095;
    int dir   = chain >> 11;                     // warp-uniform
    int row   = chain & (Bn - 1);
    int u0    = 2 * half;

    const float* Whh = dir ? WhhB : WhhF;
    const float* bhh = dir ? bhhB : bhhF;
    const float* Wih = dir ? WihB : WihF;
    const float* bih = dir ? bihB : bihF;

    f2 wr[4], wz[4], wn[4];
    #pragma unroll
    for (int j = 0; j < 4; j++) {
        int gj = (j + u0) & 3;
        wr[j] = pk2(0.5f * Whh[(0 + u0) * 4 + gj], 0.5f * Whh[(1 + u0) * 4 + gj]);
        wz[j] = pk2(0.5f * Whh[(4 + u0) * 4 + gj], 0.5f * Whh[(5 + u0) * 4 + gj]);
        wn[j] = pk2(0.5f * Whh[(8 + u0) * 4 + gj], 0.5f * Whh[(9 + u0) * 4 + gj]);
    }
    f2 ur[4], uz[4], un[4];
    #pragma unroll
    for (int j = 0; j < 4; j++) {
        ur[j] = pk2(0.5f * Wih[(0 + u0) * 4 + j], 0.5f * Wih[(1 + u0) * 4 + j]);
        uz[j] = pk2(0.5f * Wih[(4 + u0) * 4 + j], 0.5f * Wih[(5 + u0) * 4 + j]);
        un[j] = pk2(Wih[(8 + u0) * 4 + j],        Wih[(9 + u0) * 4 + j]);
    }
    const f2 br  = pk2(0.5f * (bih[0 + u0] + bhh[0 + u0]),
                       0.5f * (bih[1 + u0] + bhh[1 + u0]));
    const f2 bz  = pk2(0.5f * (bih[4 + u0] + bhh[4 + u0]),
                       0.5f * (bih[5 + u0] + bhh[5 + u0]));
    const f2 bxn = pk2(bih[8 + u0], bih[9 + u0]);
    const f2 bhn = pk2(0.5f * bhh[8 + u0], 0.5f * bhh[9 + u0]);

    const char* pe = (const char*)g_e16;
    uint32_t*   hp = (uint32_t*)g_h16[dir];

    int segstart = seg * SEGL_DIR;
    int tstart   = seg ? segstart - W_DIR : 0;
    int nsteps   = seg ? SEGL_DIR + W_DIR : SEGL_DIR;

    auto slot = [&](int st, int k, int c) -> uint32_t {
        return sbase + (uint32_t)(((st * 4 + k) * 16 + c) * 8);
    };
    int k0 = lane >> 4;
    auto issue = [&](int c) {
        int st = c & (DSTAGES - 1);
        #pragma unroll
        for (int kk = 0; kk < 2; kk++) {
            int k = k0 + 2 * kk;
            int t = tstart + 4 * c + k;
            int tq = dir ? (Tn - 1 - t) : t;
            cpa8(slot(st, k, ch), pe + ((size_t)tq * Bn + row) * 8);
        }
    };

    issue(0); cpa_commit();
    issue(1); cpa_commit();
    issue(2); cpa_commit();

    float ha = 0.f, hb = 0.f;

    const int NC = nsteps / 4;
    for (int c = 0; c < NC; c++) {
        if (c + 3 < NC) issue(c + 3);
        cpa_commit();
        cpa_wait<3>();
        int st = c & (DSTAGES - 1);
        #pragma unroll
        for (int k = 0; k < 4; k++) {
            float pa = __shfl_xor_sync(0xffffffffu, ha, 16);
            float pb = __shfl_xor_sync(0xffffffffu, hb, 16);

            uint2 eh = *(const uint2*)(sbuf + (slot(st, k, ch) - sb0));
            float ex, ey, ez, ew;
            upk2(h2f2(eh.x), ex, ey);
            upk2(h2f2(eh.y), ez, ew);
            f2 e0 = pk2(ex, ex), e1 = pk2(ey, ey);
            f2 e2 = pk2(ez, ez), e3 = pk2(ew, ew);

            f2 ar = fma2(ur[0], e0, br);  ar = fma2(ur[1], e1, ar);
            ar = fma2(ur[2], e2, ar);     ar = fma2(ur[3], e3, ar);
            f2 az = fma2(uz[0], e0, bz);  az = fma2(uz[1], e1, az);
            az = fma2(uz[2], e2, az);     az = fma2(uz[3], e3, az);
            f2 xn = fma2(un[0], e0, bxn); xn = fma2(un[1], e1, xn);
            xn = fma2(un[2], e2, xn);     xn = fma2(un[3], e3, xn);

            f2 q0 = pk2(ha, ha), q1 = pk2(hb, hb);
            ar = fma2(wr[0], q0, ar); ar = fma2(wr[1], q1, ar);
            az = fma2(wz[0], q0, az); az = fma2(wz[1], q1, az);
            f2 an = fma2(wn[0], q0, bhn); an = fma2(wn[1], q1, an);

            f2 q2 = pk2(pa, pa), q3 = pk2(pb, pb);
            ar = fma2(wr[2], q2, ar); ar = fma2(wr[3], q3, ar);
            az = fma2(wz[2], q2, az); az = fma2(wz[3], q3, az);
            an = fma2(wn[2], q2, an); an = fma2(wn[3], q3, an);

            float a0, a1; upk2(ar, a0, a1);
            float tr0 = tanhap(a0), tr1 = tanhap(a1);
            float c0, c1; upk2(az, c0, c1);
            float z0 = fmaf(0.5f, tanhap(c0), 0.5f);
            float z1 = fmaf(0.5f, tanhap(c1), 0.5f);
            float g0, g1; upk2(an, g0, g1);              // 0.5*hn
            float x0, x1; upk2(xn, x0, x1);

            float n0 = tanhap(fmaf(tr0, g0, x0 + g0));
            float n1 = tanhap(fmaf(tr1, g1, x1 + g1));

            ha = fmaf(z0, ha - n0, n0);
            hb = fmaf(z1, hb - n1, n1);

            int t = tstart + 4 * c + k;
            if (t >= segstart) {
                int tt = dir ? (Tn - 1 - t) : t;
                hp[(size_t)(tt * Bn + row) * 2 + half] = pkh(ha, hb);
            }
        }
    }
}

// ---------------------------------------------------------------------------
// Kernel 2: segmented output GRU (H=1), fused 8-wide projection from fp16 h.
#define S_OUT 32
#define W_OUT 48
#define SEGL_OUT (Tn / S_OUT)        // 64
#define OSTAGES 4
#define OCK 8
__global__ void __launch_bounds__(32, 1)
k_out(const float* __restrict__ WihO, const float* __restrict__ WhhO,
      const float* __restrict__ bihO, const float* __restrict__ bhhO,
      float* __restrict__ out) {
    __shared__ char sbuf[OSTAGES * OCK * 2 * 32 * 8];   // 16 KB
    uint32_t sbase = s2u(sbuf);

    int lane = threadIdx.x;
    int rowseg = blockIdx.x * 32 + lane;         // seg*2048 + row
    int seg = rowseg >> 11;                      // warp-uniform
    int row = rowseg & (Bn - 1);

    float wr[8], wz[8], wn[8];
    #pragma unroll
    for (int j = 0; j < 8; j++) {
        wr[j] = 0.5f * WihO[0 * 8 + j];
        wz[j] = 0.5f * WihO[1 * 8 + j];
        wn[j] = WihO[2 * 8 + j];
    }
    float cr = 0.5f * (bihO[0] + bhhO[0]);
    float cz = 0.5f * (bihO[1] + bhhO[1]);
    float cn = bihO[2];
    float wrh = 0.5f * WhhO[0], wzh = 0.5f * WhhO[1];
    float whn = 0.5f * WhhO[2], bhn = 0.5f * bhhO[2];
    float h = 0.f;

    int segstart = seg * SEGL_OUT;
    int tstart   = seg ? segstart - W_OUT : 0;
    int nsteps   = seg ? SEGL_OUT + W_OUT : SEGL_OUT;

    auto slot = [&](int st, int k, int a) -> uint32_t {
        return sbase + (uint32_t)((((st * OCK + k) * 2 + a) * 32 + lane) * 8);
    };
    auto issue = [&](int c) {
        int st = c & (OSTAGES - 1);
        #pragma unroll
        for (int k = 0; k < OCK; k++) {
            int ix = (tstart + OCK * c + k) * Bn + row;
            cpa8(slot(st, k, 0), &g_h16[0][ix]);
            cpa8(slot(st, k, 1), &g_h16[1][ix]);
        }
    };

    issue(0); cpa_commit();
    issue(1); cpa_commit();
    issue(2); cpa_commit();

    const int NC = nsteps / OCK;
    float4* outv = (float4*)out;
    for (int c = 0; c < NC; c++) {
        if (c + 3 < NC) issue(c + 3);
        cpa_commit();
        cpa_wait<3>();
        int st = c & (OSTAGES - 1);
        int t0 = tstart + OCK * c;
        float o[OCK];
        #pragma unroll
        for (int k = 0; k < OCK; k++) {
            uint2 hf = *(const uint2*)(sbuf + (slot(st, k, 0) - sbase));
            uint2 hg = *(const uint2*)(sbuf + (slot(st, k, 1) - sbase));
            float in[8];
            upk2(h2f2(hf.x), in[0], in[1]);
            upk2(h2f2(hf.y), in[2], in[3]);
            upk2(h2f2(hg.x), in[4], in[5]);
            upk2(h2f2(hg.y), in[6], in[7]);
            float sr = cr, sz = cz, sx = cn;
            #pragma unroll
            for (int j = 0; j < 8; j++) {
                sr = fmaf(wr[j], in[j], sr);
                sz = fmaf(wz[j], in[j], sz);
                sx = fmaf(wn[j], in[j], sx);
            }
            float tr = tanhap(fmaf(wrh, h, sr));
            float z  = fmaf(0.5f, tanhap(fmaf(wzh, h, sz)), 0.5f);
            float g  = fmaf(whn, h, bhn);
            float n  = tanhap(fmaf(tr, g, sx + g));
            h = fmaf(z, h - n, n);
            o[k] = fmaf(0.5f, tanhap(0.5f * h), 0.5f);
        }
        if (t0 >= segstart) {
            #pragma unroll
            for (int q = 0; q < OCK / 4; q++)
                outv[(size_t)row * (Tn / 4) + (t0 >> 2) + q] =
                    make_float4(o[4 * q], o[4 * q + 1], o[4 * q + 2], o[4 * q + 3]);
        }
    }
}

// ---------------------------------------------------------------------------
extern "C" void kernel_launch(void* const* d_in, const int* in_sizes, int n_in,
                              void* d_out, int out_size) {
    const void*  x    = d_in[0];
    const float* emb  = (const float*)d_in[1];
    const float* WihF = (const float*)d_in[2];
    const float* WhhF = (const float*)d_in[3];
    const float* bihF = (const float*)d_in[4];
    const float* bhhF = (const float*)d_in[5];
    const float* WihB = (const float*)d_in[6];
    const float* WhhB = (const float*)d_in[7];
    const float* bihB = (const float*)d_in[8];
    const float* bhhB = (const float*)d_in[9];
    const float* WihO = (const float*)d_in[10];
    const float* WhhO = (const float*)d_in[11];
    const float* bihO = (const float*)d_in[12];
    const float* bhhO = (const float*)d_in[13];

    k_detect<<<1, 32>>>((const unsigned int*)x);
    k_xi<<<2048, 256>>>(x, emb);
    k_dirs<<<(2 * Bn * S_DIR) / 32, 64>>>(WhhF, bhhF, WhhB, bhhB,
                                          WihF, bihF, WihB, bihB);
    k_out<<<(Bn * S_OUT) / 32, 32>>>(WihO, WhhO, bihO, bhhO, (float*)d_out);
}

// round 15
// speedup vs baseline: 6.2187x; 1.0458x over previous
#include <cuda_runtime.h>
#include <cuda_fp16.h>
#include <cstdint>

#define Bn 2048
#define Tn 2048
#define TB (Tn * Bn)

typedef unsigned long long f2;

// Static device scratch (no runtime allocations allowed)
__device__ float4 g_e[TB];        // fp32 embedding [t*Bn+b] (67MB, L2-resident)
__device__ uint2  g_h16[2][TB];   // fp16 hidden {h2(h0,h1), h2(h2,h3)} per dir
__device__ int    g_is64;

static __device__ __forceinline__ f2 pk2(float a, float b) {
    f2 r; asm("mov.b64 %0,{%1,%2};" : "=l"(r) : "f"(a), "f"(b)); return r;
}
static __device__ __forceinline__ void upk2(f2 v, float& a, float& b) {
    asm("mov.b64 {%0,%1},%2;" : "=f"(a), "=f"(b) : "l"(v));
}
static __device__ __forceinline__ f2 fma2(f2 a, f2 b, f2 c) {
    f2 r; asm("fma.rn.f32x2 %0,%1,%2,%3;" : "=l"(r) : "l"(a), "l"(b), "l"(c)); return r;
}
static __device__ __forceinline__ float tanhap(float x) {
    float r; asm("tanh.approx.f32 %0,%1;" : "=f"(r) : "f"(x)); return r;
}
static __device__ __forceinline__ uint32_t pkh(float a, float b) {
    __half2 h = __floats2half2_rn(a, b);
    return *reinterpret_cast<uint32_t*>(&h);
}
static __device__ __forceinline__ f2 h2f2(uint32_t v) {
    __half2 h = *reinterpret_cast<__half2*>(&v);
    float2 f = __half22float2(h);
    return pk2(f.x, f.y);
}
static __device__ __forceinline__ uint32_t s2u(const void* p) {
    uint32_t a;
    asm("{ .reg .u64 t; cvta.to.shared.u64 t, %1; cvt.u32.u64 %0, t; }" : "=r"(a) : "l"(p));
    return a;
}
static __device__ __forceinline__ void cpa16(uint32_t s, const void* g) {
    asm volatile("cp.async.ca.shared.global [%0], [%1], 16;" :: "r"(s), "l"(g) : "memory");
}
static __device__ __forceinline__ void cpa8(uint32_t s, const void* g) {
    asm volatile("cp.async.ca.shared.global [%0], [%1], 8;" :: "r"(s), "l"(g) : "memory");
}
static __device__ __forceinline__ void cpa_commit() {
    asm volatile("cp.async.commit_group;" ::: "memory");
}
template <int N> static __device__ __forceinline__ void cpa_wait() {
    asm volatile("cp.async.wait_group %0;" :: "n"(N) : "memory");
}

// ---------------------------------------------------------------------------
__global__ void k_detect(const unsigned int* xw) {
    if (threadIdx.x == 0 && blockIdx.x == 0) {
        int all0 = 1;
        for (int i = 0; i < 64; i++)
            if (xw[2 * i + 1] != 0u) { all0 = 0; break; }
        g_is64 = all0;
    }
}

// ---------------------------------------------------------------------------
// Transposed fp32 embedding: e[t*Bn+b] = emb[x[b][t]].
__global__ void k_xi(const void* __restrict__ xv, const float* __restrict__ emb) {
    int bt  = blockIdx.x;                 // 2048 blocks
    int b0  = (bt & 7) * 256;
    int t0  = (bt >> 3) * 8;
    int b   = b0 + threadIdx.x;

    int tok[8];
    if (g_is64) {
        const int4* p = (const int4*)((const long long*)xv + (size_t)b * Tn + t0);
        int4 a = p[0], c = p[1], d = p[2], e = p[3];
        tok[0] = a.x; tok[1] = a.z; tok[2] = c.x; tok[3] = c.z;
        tok[4] = d.x; tok[5] = d.z; tok[6] = e.x; tok[7] = e.z;
    } else {
        const int4* p = (const int4*)((const int*)xv + (size_t)b * Tn + t0);
        int4 a = p[0], c = p[1];
        tok[0] = a.x; tok[1] = a.y; tok[2] = a.z; tok[3] = a.w;
        tok[4] = c.x; tok[5] = c.y; tok[6] = c.z; tok[7] = c.w;
    }
    #pragma unroll
    for (int k = 0; k < 8; k++) {
        float4 e = *(const float4*)&emb[(size_t)tok[k] * 4];
        g_e[(size_t)(t0 + k) * Bn + b] = e;
    }
}

// ---------------------------------------------------------------------------
// Kernel 1: segmented fwd+bwd GRU chains; chain split across lane pair
// (l, l+16). xi = Wih*e + bias recomputed in-register from fp32 e stream.
#define S_DIR 16
#define W_DIR 32
#define SEGL_DIR (Tn / S_DIR)        // 128
#define DSTAGES 4
#define WARP_SMEM (DSTAGES * 4 * 16 * 16)   // 4KB per warp
__global__ void __launch_bounds__(64, 1)
k_dirs(const float* __restrict__ WhhF, const float* __restrict__ bhhF,
       const float* __restrict__ WhhB, const float* __restrict__ bhhB,
       const float* __restrict__ WihF, const float* __restrict__ bihF,
       const float* __restrict__ WihB, const float* __restrict__ bihB) {
    __shared__ char sbuf[2 * WARP_SMEM];   // 8 KB
    uint32_t sb0 = s2u(sbuf);
    uint32_t sbase = sb0 + (uint32_t)(threadIdx.x >> 5) * WARP_SMEM;

    int lane = threadIdx.x & 31;
    int half = lane >> 4;                        // 0: units 0,1 ; 1: units 2,3
    int ch   = lane & 15;
    int gw   = blockIdx.x * 2 + (threadIdx.x >> 5);
    int chainseg = gw * 16 + ch;                 // seg*4096 + chain
    int seg   = chainseg >> 12;                  // warp-uniform
    int chain = chainseg & 4095;
    int dir   = chain >> 11;                     // warp-uniform
    int row   = chain & (Bn - 1);
    int u0    = 2 * half;

    const float* Whh = dir ? WhhB : WhhF;
    const float* bhh = dir ? bhhB : bhhF;
    const float* Wih = dir ? WihB : WihF;
    const float* bih = dir ? bihB : bihF;

    f2 wr[4], wz[4], wn[4];
    #pragma unroll
    for (int j = 0; j < 4; j++) {
        int gj = (j + u0) & 3;
        wr[j] = pk2(0.5f * Whh[(0 + u0) * 4 + gj], 0.5f * Whh[(1 + u0) * 4 + gj]);
        wz[j] = pk2(0.5f * Whh[(4 + u0) * 4 + gj], 0.5f * Whh[(5 + u0) * 4 + gj]);
        wn[j] = pk2(0.5f * Whh[(8 + u0) * 4 + gj], 0.5f * Whh[(9 + u0) * 4 + gj]);
    }
    f2 ur[4], uz[4], un[4];
    #pragma unroll
    for (int j = 0; j < 4; j++) {
        ur[j] = pk2(0.5f * Wih[(0 + u0) * 4 + j], 0.5f * Wih[(1 + u0) * 4 + j]);
        uz[j] = pk2(0.5f * Wih[(4 + u0) * 4 + j], 0.5f * Wih[(5 + u0) * 4 + j]);
        un[j] = pk2(Wih[(8 + u0) * 4 + j],        Wih[(9 + u0) * 4 + j]);
    }
    const f2 br  = pk2(0.5f * (bih[0 + u0] + bhh[0 + u0]),
                       0.5f * (bih[1 + u0] + bhh[1 + u0]));
    const f2 bz  = pk2(0.5f * (bih[4 + u0] + bhh[4 + u0]),
                       0.5f * (bih[5 + u0] + bhh[5 + u0]));
    const f2 bxn = pk2(bih[8 + u0], bih[9 + u0]);
    const f2 bhn = pk2(0.5f * bhh[8 + u0], 0.5f * bhh[9 + u0]);

    const char* pe = (const char*)g_e;
    uint32_t*   hp = (uint32_t*)g_h16[dir];

    int segstart = seg * SEGL_DIR;
    int tstart   = seg ? segstart - W_DIR : 0;
    int nsteps   = seg ? SEGL_DIR + W_DIR : SEGL_DIR;

    auto slot = [&](int st, int k, int c) -> uint32_t {
        return sbase + (uint32_t)(((st * 4 + k) * 16 + c) * 16);
    };
    int k0 = lane >> 4;
    auto issue = [&](int c) {
        int st = c & (DSTAGES - 1);
        #pragma unroll
        for (int kk = 0; kk < 2; kk++) {
            int k = k0 + 2 * kk;
            int t = tstart + 4 * c + k;
            int tq = dir ? (Tn - 1 - t) : t;
            cpa16(slot(st, k, ch), pe + ((size_t)tq * Bn + row) * 16);
        }
    };

    issue(0); cpa_commit();
    issue(1); cpa_commit();
    issue(2); cpa_commit();

    float ha = 0.f, hb = 0.f;

    const int NC = nsteps / 4;
    for (int c = 0; c < NC; c++) {
        if (c + 3 < NC) issue(c + 3);
        cpa_commit();
        cpa_wait<3>();
        int st = c & (DSTAGES - 1);
        #pragma unroll
        for (int k = 0; k < 4; k++) {
            float pa = __shfl_xor_sync(0xffffffffu, ha, 16);
            float pb = __shfl_xor_sync(0xffffffffu, hb, 16);

            float4 ev = *(const float4*)(sbuf + (slot(st, k, ch) - sb0));
            f2 e0 = pk2(ev.x, ev.x), e1 = pk2(ev.y, ev.y);
            f2 e2 = pk2(ev.z, ev.z), e3 = pk2(ev.w, ev.w);

            f2 ar = fma2(ur[0], e0, br);  ar = fma2(ur[1], e1, ar);
            ar = fma2(ur[2], e2, ar);     ar = fma2(ur[3], e3, ar);
            f2 az = fma2(uz[0], e0, bz);  az = fma2(uz[1], e1, az);
            az = fma2(uz[2], e2, az);     az = fma2(uz[3], e3, az);
            f2 xn = fma2(un[0], e0, bxn); xn = fma2(un[1], e1, xn);
            xn = fma2(un[2], e2, xn);     xn = fma2(un[3], e3, xn);

            f2 q0 = pk2(ha, ha), q1 = pk2(hb, hb);
            ar = fma2(wr[0], q0, ar); ar = fma2(wr[1], q1, ar);
            az = fma2(wz[0], q0, az); az = fma2(wz[1], q1, az);
            f2 an = fma2(wn[0], q0, bhn); an = fma2(wn[1], q1, an);

            f2 q2 = pk2(pa, pa), q3 = pk2(pb, pb);
            ar = fma2(wr[2], q2, ar); ar = fma2(wr[3], q3, ar);
            az = fma2(wz[2], q2, az); az = fma2(wz[3], q3, az);
            an = fma2(wn[2], q2, an); an = fma2(wn[3], q3, an);

            float a0, a1; upk2(ar, a0, a1);
            float tr0 = tanhap(a0), tr1 = tanhap(a1);
            float c0, c1; upk2(az, c0, c1);
            float z0 = fmaf(0.5f, tanhap(c0), 0.5f);
            float z1 = fmaf(0.5f, tanhap(c1), 0.5f);
            float g0, g1; upk2(an, g0, g1);              // 0.5*hn
            float x0, x1; upk2(xn, x0, x1);

            float n0 = tanhap(fmaf(tr0, g0, x0 + g0));
            float n1 = tanhap(fmaf(tr1, g1, x1 + g1));

            ha = fmaf(z0, ha - n0, n0);
            hb = fmaf(z1, hb - n1, n1);

            int t = tstart + 4 * c + k;
            if (t >= segstart) {
                int tt = dir ? (Tn - 1 - t) : t;
                hp[(size_t)(tt * Bn + row) * 2 + half] = pkh(ha, hb);
            }
        }
    }
}

// ---------------------------------------------------------------------------
// Kernel 2: segmented output GRU (H=1), fused 8-wide projection from fp16 h.
#define S_OUT 32
#define W_OUT 32
#define SEGL_OUT (Tn / S_OUT)        // 64
#define OSTAGES 4
#define OCK 8
__global__ void __launch_bounds__(32, 1)
k_out(const float* __restrict__ WihO, const float* __restrict__ WhhO,
      const float* __restrict__ bihO, const float* __restrict__ bhhO,
      float* __restrict__ out) {
    __shared__ char sbuf[OSTAGES * OCK * 2 * 32 * 8];   // 16 KB
    uint32_t sbase = s2u(sbuf);

    int lane = threadIdx.x;
    int rowseg = blockIdx.x * 32 + lane;         // seg*2048 + row
    int seg = rowseg >> 11;                      // warp-uniform
    int row = rowseg & (Bn - 1);

    float wr[8], wz[8], wn[8];
    #pragma unroll
    for (int j = 0; j < 8; j++) {
        wr[j] = 0.5f * WihO[0 * 8 + j];
        wz[j] = 0.5f * WihO[1 * 8 + j];
        wn[j] = WihO[2 * 8 + j];
    }
    float cr = 0.5f * (bihO[0] + bhhO[0]);
    float cz = 0.5f * (bihO[1] + bhhO[1]);
    float cn = bihO[2];
    float wrh = 0.5f * WhhO[0], wzh = 0.5f * WhhO[1];
    float whn = 0.5f * WhhO[2], bhn = 0.5f * bhhO[2];
    float h = 0.f;

    int segstart = seg * SEGL_OUT;
    int tstart   = seg ? segstart - W_OUT : 0;
    int nsteps   = seg ? SEGL_OUT + W_OUT : SEGL_OUT;

    auto slot = [&](int st, int k, int a) -> uint32_t {
        return sbase + (uint32_t)((((st * OCK + k) * 2 + a) * 32 + lane) * 8);
    };
    auto issue = [&](int c) {
        int st = c & (OSTAGES - 1);
        #pragma unroll
        for (int k = 0; k < OCK; k++) {
            int ix = (tstart + OCK * c + k) * Bn + row;
            cpa8(slot(st, k, 0), &g_h16[0][ix]);
            cpa8(slot(st, k, 1), &g_h16[1][ix]);
        }
    };

    issue(0); cpa_commit();
    issue(1); cpa_commit();
    issue(2); cpa_commit();

    const int NC = nsteps / OCK;
    float4* outv = (float4*)out;
    for (int c = 0; c < NC; c++) {
        if (c + 3 < NC) issue(c + 3);
        cpa_commit();
        cpa_wait<3>();
        int st = c & (OSTAGES - 1);
        int t0 = tstart + OCK * c;
        float o[OCK];
        #pragma unroll
        for (int k = 0; k < OCK; k++) {
            uint2 hf = *(const uint2*)(sbuf + (slot(st, k, 0) - sbase));
            uint2 hg = *(const uint2*)(sbuf + (slot(st, k, 1) - sbase));
            float in[8];
            upk2(h2f2(hf.x), in[0], in[1]);
            upk2(h2f2(hf.y), in[2], in[3]);
            upk2(h2f2(hg.x), in[4], in[5]);
            upk2(h2f2(hg.y), in[6], in[7]);
            float sr = cr, sz = cz, sx = cn;
            #pragma unroll
            for (int j = 0; j < 8; j++) {
                sr = fmaf(wr[j], in[j], sr);
                sz = fmaf(wz[j], in[j], sz);
                sx = fmaf(wn[j], in[j], sx);
            }
            float tr = tanhap(fmaf(wrh, h, sr));
            float z  = fmaf(0.5f, tanhap(fmaf(wzh, h, sz)), 0.5f);
            float g  = fmaf(whn, h, bhn);
            float n  = tanhap(fmaf(tr, g, sx + g));
            h = fmaf(z, h - n, n);
            o[k] = fmaf(0.5f, tanhap(0.5f * h), 0.5f);
        }
        if (t0 >= segstart) {
            #pragma unroll
            for (int q = 0; q < OCK / 4; q++)
                outv[(size_t)row * (Tn / 4) + (t0 >> 2) + q] =
                    make_float4(o[4 * q], o[4 * q + 1], o[4 * q + 2], o[4 * q + 3]);
        }
    }
}

// ---------------------------------------------------------------------------
extern "C" void kernel_launch(void* const* d_in, const int* in_sizes, int n_in,
                              void* d_out, int out_size) {
    const void*  x    = d_in[0];
    const float* emb  = (const float*)d_in[1];
    const float* WihF = (const float*)d_in[2];
    const float* WhhF = (const float*)d_in[3];
    const float* bihF = (const float*)d_in[4];
    const float* bhhF = (const float*)d_in[5];
    const float* WihB = (const float*)d_in[6];
    const float* WhhB = (const float*)d_in[7];
    const float* bihB = (const float*)d_in[8];
    const float* bhhB = (const float*)d_in[9];
    const float* WihO = (const float*)d_in[10];
    const float* WhhO = (const float*)d_in[11];
    const float* bihO = (const float*)d_in[12];
    const float* bhhO = (const float*)d_in[13];

    k_detect<<<1, 32>>>((const unsigned int*)x);
    k_xi<<<2048, 256>>>(x, emb);
    k_dirs<<<(2 * Bn * S_DIR) / 32, 64>>>(WhhF, bhhF, WhhB, bhhB,
                                          WihF, bihF, WihB, bihB);
    k_out<<<(Bn * S_OUT) / 32, 32>>>(WihO, WhhO, bihO, bhhO, (float*)d_out);
}

// round 16
// speedup vs baseline: 6.2500x; 1.0050x over previous
#include <cuda_runtime.h>
#include <cuda_fp16.h>
#include <cstdint>

#define Bn 2048
#define Tn 2048
#define TB (Tn * Bn)

typedef unsigned long long f2;

// Static device scratch (no runtime allocations allowed)
__device__ float4 g_e[TB];        // fp32 embedding [t*Bn+b] (67MB, L2-resident)
__device__ uint2  g_h16[2][TB];   // fp16 hidden {h2(h0,h1), h2(h2,h3)} per dir
__device__ int    g_is64;

static __device__ __forceinline__ f2 pk2(float a, float b) {
    f2 r; asm("mov.b64 %0,{%1,%2};" : "=l"(r) : "f"(a), "f"(b)); return r;
}
static __device__ __forceinline__ void upk2(f2 v, float& a, float& b) {
    asm("mov.b64 {%0,%1},%2;" : "=f"(a), "=f"(b) : "l"(v));
}
static __device__ __forceinline__ f2 fma2(f2 a, f2 b, f2 c) {
    f2 r; asm("fma.rn.f32x2 %0,%1,%2,%3;" : "=l"(r) : "l"(a), "l"(b), "l"(c)); return r;
}
static __device__ __forceinline__ float tanhap(float x) {
    float r; asm("tanh.approx.f32 %0,%1;" : "=f"(r) : "f"(x)); return r;
}
static __device__ __forceinline__ uint32_t pkh(float a, float b) {
    __half2 h = __floats2half2_rn(a, b);
    return *reinterpret_cast<uint32_t*>(&h);
}
static __device__ __forceinline__ __half2 u2h2(uint32_t v) {
    return *reinterpret_cast<__half2*>(&v);
}
static __device__ __forceinline__ uint32_t s2u(const void* p) {
    uint32_t a;
    asm("{ .reg .u64 t; cvta.to.shared.u64 t, %1; cvt.u32.u64 %0, t; }" : "=r"(a) : "l"(p));
    return a;
}
static __device__ __forceinline__ void cpa16(uint32_t s, const void* g) {
    asm volatile("cp.async.ca.shared.global [%0], [%1], 16;" :: "r"(s), "l"(g) : "memory");
}
static __device__ __forceinline__ void cpa8(uint32_t s, const void* g) {
    asm volatile("cp.async.ca.shared.global [%0], [%1], 8;" :: "r"(s), "l"(g) : "memory");
}
static __device__ __forceinline__ void cpa_commit() {
    asm volatile("cp.async.commit_group;" ::: "memory");
}
template <int N> static __device__ __forceinline__ void cpa_wait() {
    asm volatile("cp.async.wait_group %0;" :: "n"(N) : "memory");
}

// ---------------------------------------------------------------------------
__global__ void k_detect(const unsigned int* xw) {
    if (threadIdx.x == 0 && blockIdx.x == 0) {
        int all0 = 1;
        for (int i = 0; i < 64; i++)
            if (xw[2 * i + 1] != 0u) { all0 = 0; break; }
        g_is64 = all0;
    }
}

// ---------------------------------------------------------------------------
// Transposed fp32 embedding: e[t*Bn+b] = emb[x[b][t]].
__global__ void k_xi(const void* __restrict__ xv, const float* __restrict__ emb) {
    int bt  = blockIdx.x;                 // 2048 blocks
    int b0  = (bt & 7) * 256;
    int t0  = (bt >> 3) * 8;
    int b   = b0 + threadIdx.x;

    int tok[8];
    if (g_is64) {
        const int4* p = (const int4*)((const long long*)xv + (size_t)b * Tn + t0);
        int4 a = p[0], c = p[1], d = p[2], e = p[3];
        tok[0] = a.x; tok[1] = a.z; tok[2] = c.x; tok[3] = c.z;
        tok[4] = d.x; tok[5] = d.z; tok[6] = e.x; tok[7] = e.z;
    } else {
        const int4* p = (const int4*)((const int*)xv + (size_t)b * Tn + t0);
        int4 a = p[0], c = p[1];
        tok[0] = a.x; tok[1] = a.y; tok[2] = a.z; tok[3] = a.w;
        tok[4] = c.x; tok[5] = c.y; tok[6] = c.z; tok[7] = c.w;
    }
    #pragma unroll
    for (int k = 0; k < 8; k++) {
        float4 e = *(const float4*)&emb[(size_t)tok[k] * 4];
        g_e[(size_t)(t0 + k) * Bn + b] = e;
    }
}

// ---------------------------------------------------------------------------
// Kernel 1: segmented fwd+bwd GRU chains; chain split across lane pair
// (l, l+16). xi = Wih*e + bias recomputed in-register from fp32 e stream.
#define S_DIR 16
#define W_DIR 32
#define SEGL_DIR (Tn / S_DIR)        // 128
#define DSTAGES 4
#define WARP_SMEM (DSTAGES * 4 * 16 * 16)   // 4KB per warp
__global__ void __launch_bounds__(64, 1)
k_dirs(const float* __restrict__ WhhF, const float* __restrict__ bhhF,
       const float* __restrict__ WhhB, const float* __restrict__ bhhB,
       const float* __restrict__ WihF, const float* __restrict__ bihF,
       const float* __restrict__ WihB, const float* __restrict__ bihB) {
    __shared__ char sbuf[2 * WARP_SMEM];   // 8 KB
    uint32_t sb0 = s2u(sbuf);
    uint32_t sbase = sb0 + (uint32_t)(threadIdx.x >> 5) * WARP_SMEM;

    int lane = threadIdx.x & 31;
    int half = lane >> 4;                        // 0: units 0,1 ; 1: units 2,3
    int ch   = lane & 15;
    int gw   = blockIdx.x * 2 + (threadIdx.x >> 5);
    int chainseg = gw * 16 + ch;                 // seg*4096 + chain
    int seg   = chainseg >> 12;                  // warp-uniform
    int chain = chainseg & 4095;
    int dir   = chain >> 11;                     // warp-uniform
    int row   = chain & (Bn - 1);
    int u0    = 2 * half;

    const float* Whh = dir ? WhhB : WhhF;
    const float* bhh = dir ? bhhB : bhhF;
    const float* Wih = dir ? WihB : WihF;
    const float* bih = dir ? bihB : bihF;

    f2 wr[4], wz[4], wn[4];
    #pragma unroll
    for (int j = 0; j < 4; j++) {
        int gj = (j + u0) & 3;
        wr[j] = pk2(0.5f * Whh[(0 + u0) * 4 + gj], 0.5f * Whh[(1 + u0) * 4 + gj]);
        wz[j] = pk2(0.5f * Whh[(4 + u0) * 4 + gj], 0.5f * Whh[(5 + u0) * 4 + gj]);
        wn[j] = pk2(0.5f * Whh[(8 + u0) * 4 + gj], 0.5f * Whh[(9 + u0) * 4 + gj]);
    }
    f2 ur[4], uz[4], un[4];
    #pragma unroll
    for (int j = 0; j < 4; j++) {
        ur[j] = pk2(0.5f * Wih[(0 + u0) * 4 + j], 0.5f * Wih[(1 + u0) * 4 + j]);
        uz[j] = pk2(0.5f * Wih[(4 + u0) * 4 + j], 0.5f * Wih[(5 + u0) * 4 + j]);
        un[j] = pk2(Wih[(8 + u0) * 4 + j],        Wih[(9 + u0) * 4 + j]);
    }
    const f2 br  = pk2(0.5f * (bih[0 + u0] + bhh[0 + u0]),
                       0.5f * (bih[1 + u0] + bhh[1 + u0]));
    const f2 bz  = pk2(0.5f * (bih[4 + u0] + bhh[4 + u0]),
                       0.5f * (bih[5 + u0] + bhh[5 + u0]));
    const f2 bxn = pk2(bih[8 + u0], bih[9 + u0]);
    const f2 bhn = pk2(0.5f * bhh[8 + u0], 0.5f * bhh[9 + u0]);

    const char* pe = (const char*)g_e;
    uint32_t*   hp = (uint32_t*)g_h16[dir];

    int segstart = seg * SEGL_DIR;
    int tstart   = seg ? segstart - W_DIR : 0;
    int nsteps   = seg ? SEGL_DIR + W_DIR : SEGL_DIR;

    auto slot = [&](int st, int k, int c) -> uint32_t {
        return sbase + (uint32_t)(((st * 4 + k) * 16 + c) * 16);
    };
    int k0 = lane >> 4;
    auto issue = [&](int c) {
        int st = c & (DSTAGES - 1);
        #pragma unroll
        for (int kk = 0; kk < 2; kk++) {
            int k = k0 + 2 * kk;
            int t = tstart + 4 * c + k;
            int tq = dir ? (Tn - 1 - t) : t;
            cpa16(slot(st, k, ch), pe + ((size_t)tq * Bn + row) * 16);
        }
    };

    issue(0); cpa_commit();
    issue(1); cpa_commit();
    issue(2); cpa_commit();

    float ha = 0.f, hb = 0.f;

    const int NC = nsteps / 4;
    for (int c = 0; c < NC; c++) {
        if (c + 3 < NC) issue(c + 3);
        cpa_commit();
        cpa_wait<3>();
        int st = c & (DSTAGES - 1);
        #pragma unroll
        for (int k = 0; k < 4; k++) {
            float pa = __shfl_xor_sync(0xffffffffu, ha, 16);
            float pb = __shfl_xor_sync(0xffffffffu, hb, 16);

            float4 ev = *(const float4*)(sbuf + (slot(st, k, ch) - sb0));
            f2 e0 = pk2(ev.x, ev.x), e1 = pk2(ev.y, ev.y);
            f2 e2 = pk2(ev.z, ev.z), e3 = pk2(ev.w, ev.w);

            f2 ar = fma2(ur[0], e0, br);  ar = fma2(ur[1], e1, ar);
            ar = fma2(ur[2], e2, ar);     ar = fma2(ur[3], e3, ar);
            f2 az = fma2(uz[0], e0, bz);  az = fma2(uz[1], e1, az);
            az = fma2(uz[2], e2, az);     az = fma2(uz[3], e3, az);
            f2 xn = fma2(un[0], e0, bxn); xn = fma2(un[1], e1, xn);
            xn = fma2(un[2], e2, xn);     xn = fma2(un[3], e3, xn);

            f2 q0 = pk2(ha, ha), q1 = pk2(hb, hb);
            ar = fma2(wr[0], q0, ar); ar = fma2(wr[1], q1, ar);
            az = fma2(wz[0], q0, az); az = fma2(wz[1], q1, az);
            f2 an = fma2(wn[0], q0, bhn); an = fma2(wn[1], q1, an);

            f2 q2 = pk2(pa, pa), q3 = pk2(pb, pb);
            ar = fma2(wr[2], q2, ar); ar = fma2(wr[3], q3, ar);
            az = fma2(wz[2], q2, az); az = fma2(wz[3], q3, az);
            an = fma2(wn[2], q2, an); an = fma2(wn[3], q3, an);

            float a0, a1; upk2(ar, a0, a1);
            float tr0 = tanhap(a0), tr1 = tanhap(a1);
            float c0, c1; upk2(az, c0, c1);
            float z0 = fmaf(0.5f, tanhap(c0), 0.5f);
            float z1 = fmaf(0.5f, tanhap(c1), 0.5f);
            float g0, g1; upk2(an, g0, g1);              // 0.5*hn
            float x0, x1; upk2(xn, x0, x1);

            float n0 = tanhap(fmaf(tr0, g0, x0 + g0));
            float n1 = tanhap(fmaf(tr1, g1, x1 + g1));

            ha = fmaf(z0, ha - n0, n0);
            hb = fmaf(z1, hb - n1, n1);

            int t = tstart + 4 * c + k;
            if (t >= segstart) {
                int tt = dir ? (Tn - 1 - t) : t;
                hp[(size_t)(tt * Bn + row) * 2 + half] = pkh(ha, hb);
            }
        }
    }
}

// ---------------------------------------------------------------------------
// Kernel 2: segmented output GRU (H=1). Projection done in half2 (HFMA2) —
// no F2F on the 8 h inputs; only 3 F2F (one per gate sum).
#define S_OUT 32
#define W_OUT 32
#define SEGL_OUT (Tn / S_OUT)        // 64
#define OSTAGES 4
#define OCK 8
__global__ void __launch_bounds__(32, 1)
k_out(const float* __restrict__ WihO, const float* __restrict__ WhhO,
      const float* __restrict__ bihO, const float* __restrict__ bhhO,
      float* __restrict__ out) {
    __shared__ char sbuf[OSTAGES * OCK * 2 * 32 * 8];   // 16 KB
    uint32_t sbase = s2u(sbuf);

    int lane = threadIdx.x;
    int rowseg = blockIdx.x * 32 + lane;         // seg*2048 + row
    int seg = rowseg >> 11;                      // warp-uniform
    int row = rowseg & (Bn - 1);

    // half2 projection weights: pair j covers concat dims (2j, 2j+1)
    // order: [f0 f1][f2 f3][b0 b1][b2 b3] — matches h16 load layout.
    __half2 hwr[4], hwz[4], hwn[4];
    #pragma unroll
    for (int j = 0; j < 4; j++) {
        hwr[j] = __floats2half2_rn(0.5f * WihO[0 * 8 + 2 * j], 0.5f * WihO[0 * 8 + 2 * j + 1]);
        hwz[j] = __floats2half2_rn(0.5f * WihO[1 * 8 + 2 * j], 0.5f * WihO[1 * 8 + 2 * j + 1]);
        hwn[j] = __floats2half2_rn(WihO[2 * 8 + 2 * j],        WihO[2 * 8 + 2 * j + 1]);
    }
    // biases seeded into the half2 accumulators (low half only)
    __half2 hbr = __floats2half2_rn(0.5f * (bihO[0] + bhhO[0]), 0.f);
    __half2 hbz = __floats2half2_rn(0.5f * (bihO[1] + bhhO[1]), 0.f);
    __half2 hbn = __floats2half2_rn(bihO[2], 0.f);
    float wrh = 0.5f * WhhO[0], wzh = 0.5f * WhhO[1];
    float whn = 0.5f * WhhO[2], bhn = 0.5f * bhhO[2];
    float h = 0.f;

    int segstart = seg * SEGL_OUT;
    int tstart   = seg ? segstart - W_OUT : 0;
    int nsteps   = seg ? SEGL_OUT + W_OUT : SEGL_OUT;

    auto slot = [&](int st, int k, int a) -> uint32_t {
        return sbase + (uint32_t)((((st * OCK + k) * 2 + a) * 32 + lane) * 8);
    };
    auto issue = [&](int c) {
        int st = c & (OSTAGES - 1);
        #pragma unroll
        for (int k = 0; k < OCK; k++) {
            int ix = (tstart + OCK * c + k) * Bn + row;
            cpa8(slot(st, k, 0), &g_h16[0][ix]);
            cpa8(slot(st, k, 1), &g_h16[1][ix]);
        }
    };

    issue(0); cpa_commit();
    issue(1); cpa_commit();
    issue(2); cpa_commit();

    const int NC = nsteps / OCK;
    float4* outv = (float4*)out;
    for (int c = 0; c < NC; c++) {
        if (c + 3 < NC) issue(c + 3);
        cpa_commit();
        cpa_wait<3>();
        int st = c & (OSTAGES - 1);
        int t0 = tstart + OCK * c;
        float o[OCK];
        #pragma unroll
        for (int k = 0; k < OCK; k++) {
            uint2 hf = *(const uint2*)(sbuf + (slot(st, k, 0) - sbase));
            uint2 hg = *(const uint2*)(sbuf + (slot(st, k, 1) - sbase));
            __half2 i0 = u2h2(hf.x), i1 = u2h2(hf.y);
            __half2 i2 = u2h2(hg.x), i3 = u2h2(hg.y);

            __half2 acr = __hfma2(i0, hwr[0], hbr);
            acr = __hfma2(i1, hwr[1], acr);
            acr = __hfma2(i2, hwr[2], acr);
            acr = __hfma2(i3, hwr[3], acr);
            __half2 acz = __hfma2(i0, hwz[0], hbz);
            acz = __hfma2(i1, hwz[1], acz);
            acz = __hfma2(i2, hwz[2], acz);
            acz = __hfma2(i3, hwz[3], acz);
            __half2 acn = __hfma2(i0, hwn[0], hbn);
            acn = __hfma2(i1, hwn[1], acn);
            acn = __hfma2(i2, hwn[2], acn);
            acn = __hfma2(i3, hwn[3], acn);

            float sr = __half2float(__hadd(__low2half(acr), __high2half(acr)));
            float sz = __half2float(__hadd(__low2half(acz), __high2half(acz)));
            float sx = __half2float(__hadd(__low2half(acn), __high2half(acn)));

            float tr = tanhap(fmaf(wrh, h, sr));
            float z  = fmaf(0.5f, tanhap(fmaf(wzh, h, sz)), 0.5f);
            float g  = fmaf(whn, h, bhn);
            float n  = tanhap(fmaf(tr, g, sx + g));
            h = fmaf(z, h - n, n);
            o[k] = fmaf(0.5f, tanhap(0.5f * h), 0.5f);
        }
        if (t0 >= segstart) {
            #pragma unroll
            for (int q = 0; q < OCK / 4; q++)
                outv[(size_t)row * (Tn / 4) + (t0 >> 2) + q] =
                    make_float4(o[4 * q], o[4 * q + 1], o[4 * q + 2], o[4 * q + 3]);
        }
    }
}

// ---------------------------------------------------------------------------
extern "C" void kernel_launch(void* const* d_in, const int* in_sizes, int n_in,
                              void* d_out, int out_size) {
    const void*  x    = d_in[0];
    const float* emb  = (const float*)d_in[1];
    const float* WihF = (const float*)d_in[2];
    const float* WhhF = (const float*)d_in[3];
    const float* bihF = (const float*)d_in[4];
    const float* bhhF = (const float*)d_in[5];
    const float* WihB = (const float*)d_in[6];
    const float* WhhB = (const float*)d_in[7];
    const float* bihB = (const float*)d_in[8];
    const float* bhhB = (const float*)d_in[9];
    const float* WihO = (const float*)d_in[10];
    const float* WhhO = (const float*)d_in[11];
    const float* bihO = (const float*)d_in[12];
    const float* bhhO = (const float*)d_in[13];

    k_detect<<<1, 32>>>((const unsigned int*)x);
    k_xi<<<2048, 256>>>(x, emb);
    k_dirs<<<(2 * Bn * S_DIR) / 32, 64>>>(WhhF, bhhF, WhhB, bhhB,
                                          WihF, bihF, WihB, bihB);
    k_out<<<(Bn * S_OUT) / 32, 32>>>(WihO, WhhO, bihO, bhhO, (float*)d_out);
}

// round 17
// speedup vs baseline: 6.2547x; 1.0008x over previous
#include <cuda_runtime.h>
#include <cuda_fp16.h>
#include <cstdint>

#define Bn 2048
#define Tn 2048
#define TB (Tn * Bn)

typedef unsigned long long f2;

// Static device scratch (no runtime allocations allowed)
__device__ float4 g_e[TB];        // fp32 embedding [t*Bn+b] (67MB, L2-resident)
__device__ uint2  g_h16[2][TB];   // fp16 hidden {h2(h0,h1), h2(h2,h3)} per dir

static __device__ __forceinline__ f2 pk2(float a, float b) {
    f2 r; asm("mov.b64 %0,{%1,%2};" : "=l"(r) : "f"(a), "f"(b)); return r;
}
static __device__ __forceinline__ void upk2(f2 v, float& a, float& b) {
    asm("mov.b64 {%0,%1},%2;" : "=f"(a), "=f"(b) : "l"(v));
}
static __device__ __forceinline__ f2 fma2(f2 a, f2 b, f2 c) {
    f2 r; asm("fma.rn.f32x2 %0,%1,%2,%3;" : "=l"(r) : "l"(a), "l"(b), "l"(c)); return r;
}
static __device__ __forceinline__ float tanhap(float x) {
    float r; asm("tanh.approx.f32 %0,%1;" : "=f"(r) : "f"(x)); return r;
}
static __device__ __forceinline__ uint32_t pkh(float a, float b) {
    __half2 h = __floats2half2_rn(a, b);
    return *reinterpret_cast<uint32_t*>(&h);
}
static __device__ __forceinline__ __half2 u2h2(uint32_t v) {
    return *reinterpret_cast<__half2*>(&v);
}
static __device__ __forceinline__ uint32_t s2u(const void* p) {
    uint32_t a;
    asm("{ .reg .u64 t; cvta.to.shared.u64 t, %1; cvt.u32.u64 %0, t; }" : "=r"(a) : "l"(p));
    return a;
}
static __device__ __forceinline__ void cpa16(uint32_t s, const void* g) {
    asm volatile("cp.async.ca.shared.global [%0], [%1], 16;" :: "r"(s), "l"(g) : "memory");
}
static __device__ __forceinline__ void cpa8(uint32_t s, const void* g) {
    asm volatile("cp.async.ca.shared.global [%0], [%1], 8;" :: "r"(s), "l"(g) : "memory");
}
static __device__ __forceinline__ void cpa_commit() {
    asm volatile("cp.async.commit_group;" ::: "memory");
}
template <int N> static __device__ __forceinline__ void cpa_wait() {
    asm volatile("cp.async.wait_group %0;" :: "n"(N) : "memory");
}

// ---------------------------------------------------------------------------
// Transposed fp32 embedding: e[t*Bn+b] = emb[x[b][t]].
// Dtype detection (int64 vs int32) folded in: every block scans the first
// 512B of x (L2-hot broadcast) — deterministic, identical across blocks.
__global__ void k_xi(const void* __restrict__ xv, const float* __restrict__ emb) {
    __shared__ int s_is64;
    if (threadIdx.x == 0) {
        const unsigned int* xw = (const unsigned int*)xv;
        int all0 = 1;
        #pragma unroll 8
        for (int i = 0; i < 64; i++)
            if (xw[2 * i + 1] != 0u) { all0 = 0; }
        s_is64 = all0;
    }
    __syncthreads();
    int is64 = s_is64;

    int bt  = blockIdx.x;                 // 2048 blocks
    int b0  = (bt & 7) * 256;
    int t0  = (bt >> 3) * 8;
    int b   = b0 + threadIdx.x;

    int tok[8];
    if (is64) {
        const int4* p = (const int4*)((const long long*)xv + (size_t)b * Tn + t0);
        int4 a = p[0], c = p[1], d = p[2], e = p[3];
        tok[0] = a.x; tok[1] = a.z; tok[2] = c.x; tok[3] = c.z;
        tok[4] = d.x; tok[5] = d.z; tok[6] = e.x; tok[7] = e.z;
    } else {
        const int4* p = (const int4*)((const int*)xv + (size_t)b * Tn + t0);
        int4 a = p[0], c = p[1];
        tok[0] = a.x; tok[1] = a.y; tok[2] = a.z; tok[3] = a.w;
        tok[4] = c.x; tok[5] = c.y; tok[6] = c.z; tok[7] = c.w;
    }
    #pragma unroll
    for (int k = 0; k < 8; k++) {
        float4 e = *(const float4*)&emb[(size_t)tok[k] * 4];
        g_e[(size_t)(t0 + k) * Bn + b] = e;
    }
}

// ---------------------------------------------------------------------------
// Kernel 1: segmented fwd+bwd GRU chains; chain split across lane pair
// (l, l+16). xi = Wih*e + bias recomputed in-register from fp32 e stream.
#define S_DIR 16
#define W_DIR 24
#define SEGL_DIR (Tn / S_DIR)        // 128
#define DSTAGES 4
#define WARP_SMEM (DSTAGES * 4 * 16 * 16)   // 4KB per warp
__global__ void __launch_bounds__(64, 1)
k_dirs(const float* __restrict__ WhhF, const float* __restrict__ bhhF,
       const float* __restrict__ WhhB, const float* __restrict__ bhhB,
       const float* __restrict__ WihF, const float* __restrict__ bihF,
       const float* __restrict__ WihB, const float* __restrict__ bihB) {
    __shared__ char sbuf[2 * WARP_SMEM];   // 8 KB
    uint32_t sb0 = s2u(sbuf);
    uint32_t sbase = sb0 + (uint32_t)(threadIdx.x >> 5) * WARP_SMEM;

    int lane = threadIdx.x & 31;
    int half = lane >> 4;                        // 0: units 0,1 ; 1: units 2,3
    int ch   = lane & 15;
    int gw   = blockIdx.x * 2 + (threadIdx.x >> 5);
    int chainseg = gw * 16 + ch;                 // seg*4096 + chain
    int seg   = chainseg >> 12;                  // warp-uniform
    int chain = chainseg & 4095;
    int dir   = chain >> 11;                     // warp-uniform
    int row   = chain & (Bn - 1);
    int u0    = 2 * half;

    const float* Whh = dir ? WhhB : WhhF;
    const float* bhh = dir ? bhhB : bhhF;
    const float* Wih = dir ? WihB : WihF;
    const float* bih = dir ? bihB : bihF;

    f2 wr[4], wz[4], wn[4];
    #pragma unroll
    for (int j = 0; j < 4; j++) {
        int gj = (j + u0) & 3;
        wr[j] = pk2(0.5f * Whh[(0 + u0) * 4 + gj], 0.5f * Whh[(1 + u0) * 4 + gj]);
        wz[j] = pk2(0.5f * Whh[(4 + u0) * 4 + gj], 0.5f * Whh[(5 + u0) * 4 + gj]);
        wn[j] = pk2(0.5f * Whh[(8 + u0) * 4 + gj], 0.5f * Whh[(9 + u0) * 4 + gj]);
    }
    f2 ur[4], uz[4], un[4];
    #pragma unroll
    for (int j = 0; j < 4; j++) {
        ur[j] = pk2(0.5f * Wih[(0 + u0) * 4 + j], 0.5f * Wih[(1 + u0) * 4 + j]);
        uz[j] = pk2(0.5f * Wih[(4 + u0) * 4 + j], 0.5f * Wih[(5 + u0) * 4 + j]);
        un[j] = pk2(Wih[(8 + u0) * 4 + j],        Wih[(9 + u0) * 4 + j]);
    }
    const f2 br  = pk2(0.5f * (bih[0 + u0] + bhh[0 + u0]),
                       0.5f * (bih[1 + u0] + bhh[1 + u0]));
    const f2 bz  = pk2(0.5f * (bih[4 + u0] + bhh[4 + u0]),
                       0.5f * (bih[5 + u0] + bhh[5 + u0]));
    const f2 bxn = pk2(bih[8 + u0], bih[9 + u0]);
    const f2 bhn = pk2(0.5f * bhh[8 + u0], 0.5f * bhh[9 + u0]);

    const char* pe = (const char*)g_e;
    uint32_t*   hp = (uint32_t*)g_h16[dir];

    int segstart = seg * SEGL_DIR;
    int tstart   = seg ? segstart - W_DIR : 0;
    int nsteps   = seg ? SEGL_DIR + W_DIR : SEGL_DIR;

    auto slot = [&](int st, int k, int c) -> uint32_t {
        return sbase + (uint32_t)(((st * 4 + k) * 16 + c) * 16);
    };
    int k0 = lane >> 4;
    auto issue = [&](int c) {
        int st = c & (DSTAGES - 1);
        #pragma unroll
        for (int kk = 0; kk < 2; kk++) {
            int k = k0 + 2 * kk;
            int t = tstart + 4 * c + k;
            int tq = dir ? (Tn - 1 - t) : t;
            cpa16(slot(st, k, ch), pe + ((size_t)tq * Bn + row) * 16);
        }
    };

    issue(0); cpa_commit();
    issue(1); cpa_commit();
    issue(2); cpa_commit();

    float ha = 0.f, hb = 0.f;

    const int NC = nsteps / 4;
    for (int c = 0; c < NC; c++) {
        if (c + 3 < NC) issue(c + 3);
        cpa_commit();
        cpa_wait<3>();
        int st = c & (DSTAGES - 1);
        #pragma unroll
        for (int k = 0; k < 4; k++) {
            float pa = __shfl_xor_sync(0xffffffffu, ha, 16);
            float pb = __shfl_xor_sync(0xffffffffu, hb, 16);

            float4 ev = *(const float4*)(sbuf + (slot(st, k, ch) - sb0));
            f2 e0 = pk2(ev.x, ev.x), e1 = pk2(ev.y, ev.y);
            f2 e2 = pk2(ev.z, ev.z), e3 = pk2(ev.w, ev.w);

            f2 ar = fma2(ur[0], e0, br);  ar = fma2(ur[1], e1, ar);
            ar = fma2(ur[2], e2, ar);     ar = fma2(ur[3], e3, ar);
            f2 az = fma2(uz[0], e0, bz);  az = fma2(uz[1], e1, az);
            az = fma2(uz[2], e2, az);     az = fma2(uz[3], e3, az);
            f2 xn = fma2(un[0], e0, bxn); xn = fma2(un[1], e1, xn);
            xn = fma2(un[2], e2, xn);     xn = fma2(un[3], e3, xn);

            f2 q0 = pk2(ha, ha), q1 = pk2(hb, hb);
            ar = fma2(wr[0], q0, ar); ar = fma2(wr[1], q1, ar);
            az = fma2(wz[0], q0, az); az = fma2(wz[1], q1, az);
            f2 an = fma2(wn[0], q0, bhn); an = fma2(wn[1], q1, an);

            f2 q2 = pk2(pa, pa), q3 = pk2(pb, pb);
            ar = fma2(wr[2], q2, ar); ar = fma2(wr[3], q3, ar);
            az = fma2(wz[2], q2, az); az = fma2(wz[3], q3, az);
            an = fma2(wn[2], q2, an); an = fma2(wn[3], q3, an);

            float a0, a1; upk2(ar, a0, a1);
            float tr0 = tanhap(a0), tr1 = tanhap(a1);
            float c0, c1; upk2(az, c0, c1);
            float z0 = fmaf(0.5f, tanhap(c0), 0.5f);
            float z1 = fmaf(0.5f, tanhap(c1), 0.5f);
            float g0, g1; upk2(an, g0, g1);              // 0.5*hn
            float x0, x1; upk2(xn, x0, x1);

            float n0 = tanhap(fmaf(tr0, g0, x0 + g0));
            float n1 = tanhap(fmaf(tr1, g1, x1 + g1));

            ha = fmaf(z0, ha - n0, n0);
            hb = fmaf(z1, hb - n1, n1);

            int t = tstart + 4 * c + k;
            if (t >= segstart) {
                int tt = dir ? (Tn - 1 - t) : t;
                hp[(size_t)(tt * Bn + row) * 2 + half] = pkh(ha, hb);
            }
        }
    }
}

// ---------------------------------------------------------------------------
// Kernel 2: segmented output GRU (H=1). Projection in half2 (HFMA2).
// S_OUT=64 for warp fill; OCK=4 + 8KB ring so smem doesn't cap residency.
#define S_OUT 64
#define W_OUT 24
#define SEGL_OUT (Tn / S_OUT)        // 32
#define OSTAGES 4
#define OCK 4
__global__ void __launch_bounds__(32, 1)
k_out(const float* __restrict__ WihO, const float* __restrict__ WhhO,
      const float* __restrict__ bihO, const float* __restrict__ bhhO,
      float* __restrict__ out) {
    __shared__ char sbuf[OSTAGES * OCK * 2 * 32 * 8];   // 8 KB
    uint32_t sbase = s2u(sbuf);

    int lane = threadIdx.x;
    int rowseg = blockIdx.x * 32 + lane;         // seg*2048 + row
    int seg = rowseg >> 11;                      // warp-uniform
    int row = rowseg & (Bn - 1);

    __half2 hwr[4], hwz[4], hwn[4];
    #pragma unroll
    for (int j = 0; j < 4; j++) {
        hwr[j] = __floats2half2_rn(0.5f * WihO[0 * 8 + 2 * j], 0.5f * WihO[0 * 8 + 2 * j + 1]);
        hwz[j] = __floats2half2_rn(0.5f * WihO[1 * 8 + 2 * j], 0.5f * WihO[1 * 8 + 2 * j + 1]);
        hwn[j] = __floats2half2_rn(WihO[2 * 8 + 2 * j],        WihO[2 * 8 + 2 * j + 1]);
    }
    __half2 hbr = __floats2half2_rn(0.5f * (bihO[0] + bhhO[0]), 0.f);
    __half2 hbz = __floats2half2_rn(0.5f * (bihO[1] + bhhO[1]), 0.f);
    __half2 hbn = __floats2half2_rn(bihO[2], 0.f);
    float wrh = 0.5f * WhhO[0], wzh = 0.5f * WhhO[1];
    float whn = 0.5f * WhhO[2], bhn = 0.5f * bhhO[2];
    float h = 0.f;

    int segstart = seg * SEGL_OUT;
    int tstart   = seg ? segstart - W_OUT : 0;
    int nsteps   = seg ? SEGL_OUT + W_OUT : SEGL_OUT;

    auto slot = [&](int st, int k, int a) -> uint32_t {
        return sbase + (uint32_t)((((st * OCK + k) * 2 + a) * 32 + lane) * 8);
    };
    auto issue = [&](int c) {
        int st = c & (OSTAGES - 1);
        #pragma unroll
        for (int k = 0; k < OCK; k++) {
            int ix = (tstart + OCK * c + k) * Bn + row;
            cpa8(slot(st, k, 0), &g_h16[0][ix]);
            cpa8(slot(st, k, 1), &g_h16[1][ix]);
        }
    };

    issue(0); cpa_commit();
    issue(1); cpa_commit();
    issue(2); cpa_commit();

    const int NC = nsteps / OCK;
    float4* outv = (float4*)out;
    for (int c = 0; c < NC; c++) {
        if (c + 3 < NC) issue(c + 3);
        cpa_commit();
        cpa_wait<3>();
        int st = c & (OSTAGES - 1);
        int t0 = tstart + OCK * c;
        float o[OCK];
        #pragma unroll
        for (int k = 0; k < OCK; k++) {
            uint2 hf = *(const uint2*)(sbuf + (slot(st, k, 0) - sbase));
            uint2 hg = *(const uint2*)(sbuf + (slot(st, k, 1) - sbase));
            __half2 i0 = u2h2(hf.x), i1 = u2h2(hf.y);
            __half2 i2 = u2h2(hg.x), i3 = u2h2(hg.y);

            __half2 acr = __hfma2(i0, hwr[0], hbr);
            acr = __hfma2(i1, hwr[1], acr);
            acr = __hfma2(i2, hwr[2], acr);
            acr = __hfma2(i3, hwr[3], acr);
            __half2 acz = __hfma2(i0, hwz[0], hbz);
            acz = __hfma2(i1, hwz[1], acz);
            acz = __hfma2(i2, hwz[2], acz);
            acz = __hfma2(i3, hwz[3], acz);
            __half2 acn = __hfma2(i0, hwn[0], hbn);
            acn = __hfma2(i1, hwn[1], acn);
            acn = __hfma2(i2, hwn[2], acn);
            acn = __hfma2(i3, hwn[3], acn);

            float sr = __half2float(__hadd(__low2half(acr), __high2half(acr)));
            float sz = __half2float(__hadd(__low2half(acz), __high2half(acz)));
            float sx = __half2float(__hadd(__low2half(acn), __high2half(acn)));

            float tr = tanhap(fmaf(wrh, h, sr));
            float z  = fmaf(0.5f, tanhap(fmaf(wzh, h, sz)), 0.5f);
            float g  = fmaf(whn, h, bhn);
            float n  = tanhap(fmaf(tr, g, sx + g));
            h = fmaf(z, h - n, n);
            o[k] = fmaf(0.5f, tanhap(0.5f * h), 0.5f);
        }
        if (t0 >= segstart) {
            outv[(size_t)row * (Tn / 4) + (t0 >> 2)] =
                make_float4(o[0], o[1], o[2], o[3]);
        }
    }
}

// ---------------------------------------------------------------------------
extern "C" void kernel_launch(void* const* d_in, const int* in_sizes, int n_in,
                              void* d_out, int out_size) {
    const void*  x    = d_in[0];
    const float* emb  = (const float*)d_in[1];
    const float* WihF = (const float*)d_in[2];
    const float* WhhF = (const float*)d_in[3];
    const float* bihF = (const float*)d_in[4];
    const float* bhhF = (const float*)d_in[5];
    const float* WihB = (const float*)d_in[6];
    const float* WhhB = (const float*)d_in[7];
    const float* bihB = (const float*)d_in[8];
    const float* bhhB = (const float*)d_in[9];
    const float* WihO = (const float*)d_in[10];
    const float* WhhO = (const float*)d_in[11];
    const float* bihO = (const float*)d_in[12];
    const float* bhhO = (const float*)d_in[13];

    k_xi<<<2048, 256>>>(x, emb);
    k_dirs<<<(2 * Bn * S_DIR) / 32, 64>>>(WhhF, bhhF, WhhB, bhhB,
                                          WihF, bihF, WihB, bihB);
    k_out<<<(Bn * S_OUT) / 32, 32>>>(WihO, WhhO, bihO, bhhO, (float*)d_out);
}